// round 1
// baseline (speedup 1.0000x reference)
#include <cuda_runtime.h>

// Problem constants
#define BB    2
#define NSEQ  2048
#define EE    768
#define HH    12
#define DD    64
#define GG    16
#define CC    128                 // chunk size
#define NCH   (NSEQ / CC)         // 16 chunks
#define BHH   (BB * HH)           // 24
#define MTOT  (BB * NSEQ)         // 4096

// ---------------- device scratch (no cudaMalloc allowed) ----------------
__device__ float g_q[MTOT * EE];
__device__ float g_k[MTOT * EE];
__device__ float g_v[MTOT * EE];
__device__ float g_gate[MTOT * EE];
__device__ float g_attn[MTOT * EE];   // intra out -> (intra+inter)*gate
__device__ float g_y[MTOT * EE];      // pre-LN (after Wo)
__device__ float g_t16[MTOT * GG];    // x @ Wg1
__device__ float g_T[BHH * NCH * DD * DD];  // per-chunk local KV sums
__device__ float g_S[BHH * NCH * DD * DD];  // scanned states (entering chunk)

// =========================================================================
// GEMM: C = act(A[M,K] @ W[K,N]), row-major. Block tile 128x64, K-step 16,
// 256 threads, per-thread 8x4 micro-tile.
// ACT: 0=none, 1=silu. ASEL: 0=param A, 1=g_attn. DSEL: 0..3 -> q,k,v,y
// =========================================================================
template <int ACT, int ASEL, int DSEL>
__global__ __launch_bounds__(256) void gemm_k(const float* __restrict__ Apar,
                                              const float* __restrict__ W,
                                              int M, int K, int N) {
    const float* A = (ASEL == 0) ? Apar : g_attn;
    float* Cmat = (DSEL == 0) ? g_q : (DSEL == 1) ? g_k : (DSEL == 2) ? g_v : g_y;

    __shared__ __align__(16) float As[128 * 20];   // [row][k], stride 20 (16B-aligned rows)
    __shared__ __align__(16) float Ws[16 * 64];    // [k][n]

    int tid = threadIdx.x;
    int bm = blockIdx.y * 128;
    int bn = blockIdx.x * 64;
    int tm = tid >> 4;          // 0..15 -> rows 8*tm .. 8*tm+7
    int tn = tid & 15;          // 0..15 -> cols 4*tn .. 4*tn+3
    int lm = tid >> 2;          // A loader: rows lm, lm+64
    int lk4 = (tid & 3) * 4;    // A loader: k offset 0/4/8/12
    int wn = tid & 63;          // W loader
    int wk = tid >> 6;          // 0..3

    float acc[8][4];
#pragma unroll
    for (int i = 0; i < 8; i++)
#pragma unroll
        for (int j = 0; j < 4; j++) acc[i][j] = 0.f;

    for (int k0 = 0; k0 < K; k0 += 16) {
        __syncthreads();
#pragma unroll
        for (int r = 0; r < 2; r++) {
            int row = lm + 64 * r;
            float4 a4 = *(const float4*)(A + (size_t)(bm + row) * K + k0 + lk4);
            *(float4*)(&As[row * 20 + lk4]) = a4;
        }
#pragma unroll
        for (int r = 0; r < 4; r++) {
            int kk = wk + 4 * r;
            Ws[kk * 64 + wn] = W[(size_t)(k0 + kk) * N + bn + wn];
        }
        __syncthreads();
#pragma unroll
        for (int kk = 0; kk < 16; kk++) {
            float4 bv = *(const float4*)(&Ws[kk * 64 + 4 * tn]);
            float a[8];
#pragma unroll
            for (int i = 0; i < 8; i++) a[i] = As[(8 * tm + i) * 20 + kk];
#pragma unroll
            for (int i = 0; i < 8; i++) {
                acc[i][0] += a[i] * bv.x;
                acc[i][1] += a[i] * bv.y;
                acc[i][2] += a[i] * bv.z;
                acc[i][3] += a[i] * bv.w;
            }
        }
    }
#pragma unroll
    for (int i = 0; i < 8; i++) {
        int row = bm + 8 * tm + i;
        float4 o;
        float* ov = (float*)&o;
#pragma unroll
        for (int j = 0; j < 4; j++) {
            float v = acc[i][j];
            if (ACT == 1) v = v / (1.f + __expf(-v));  // silu
            ov[j] = v;
        }
        *(float4*)(Cmat + (size_t)row * N + bn + 4 * tn) = o;
    }
}

// =========================================================================
// Gate stage 1: g_t16[row][g] = sum_k x[row][k] * Wg1[k][g]
// 256 threads = 16 rows x 16 g per block
// =========================================================================
__global__ __launch_bounds__(256) void gate1_k(const float* __restrict__ x,
                                               const float* __restrict__ Wg1) {
    int row = blockIdx.x * 16 + (threadIdx.x >> 4);
    int g = threadIdx.x & 15;
    const float* xr = x + (size_t)row * EE;
    float acc = 0.f;
    for (int k = 0; k < EE; k++) acc += xr[k] * Wg1[k * GG + g];
    g_t16[row * GG + g] = acc;
}

// Gate stage 2: g_gate[row][col] = sigmoid(sum_g t16[row][g]*Wg2[g][col])
__global__ __launch_bounds__(256) void gate2_k(const float* __restrict__ Wg2) {
    __shared__ float ts[GG];
    int row = blockIdx.y;
    int col = blockIdx.x * 256 + threadIdx.x;
    if (threadIdx.x < GG) ts[threadIdx.x] = g_t16[row * GG + threadIdx.x];
    __syncthreads();
    float acc = 0.f;
#pragma unroll
    for (int g = 0; g < GG; g++) acc += ts[g] * Wg2[g * EE + col];
    g_gate[(size_t)row * EE + col] = 1.f / (1.f + __expf(-acc));
}

// =========================================================================
// Attention pass A (per bh, per chunk):
//   A[p,j]  = (q_p . k_j) * exp(lambda*(p-j)) for p>=j (else 0)
//   O_intra = A @ V                      -> g_attn
//   T       = sum_p exp(lambda*(C-p)) k_p v_p^T  -> g_T
// 256 threads. Dynamic smem: Q,K,V [128x65], A [128x129], dtab[129]
// =========================================================================
__global__ __launch_bounds__(256) void attn_intra_k(const float* __restrict__ lam) {
    extern __shared__ __align__(16) float sm[];
    float* Qs = sm;                      // 128*65
    float* Ks = Qs + 128 * 65;
    float* Vs = Ks + 128 * 65;
    float* Asm = Vs + 128 * 65;          // 128*129
    float* dtab = Asm + 128 * 129;       // 129

    int tid = threadIdx.x;
    int chunk = blockIdx.x;
    int bh = blockIdx.y;
    int b = bh / HH, h = bh % HH;
    float lambda = lam[h];
    int n0 = chunk * CC;

    for (int i = tid; i <= CC; i += 256) dtab[i] = __expf(lambda * (float)i);

    for (int idx = tid; idx < 128 * 16; idx += 256) {
        int p = idx >> 4;
        int d4 = (idx & 15) * 4;
        size_t gb = (size_t)(b * NSEQ + n0 + p) * EE + h * DD + d4;
        float4 q4 = *(const float4*)(g_q + gb);
        float4 k4 = *(const float4*)(g_k + gb);
        float4 v4 = *(const float4*)(g_v + gb);
        int sb = p * 65 + d4;
        Qs[sb] = q4.x; Qs[sb + 1] = q4.y; Qs[sb + 2] = q4.z; Qs[sb + 3] = q4.w;
        Ks[sb] = k4.x; Ks[sb + 1] = k4.y; Ks[sb + 2] = k4.z; Ks[sb + 3] = k4.w;
        Vs[sb] = v4.x; Vs[sb + 1] = v4.y; Vs[sb + 2] = v4.z; Vs[sb + 3] = v4.w;
    }
    __syncthreads();

    int ty = tid >> 4, tx = tid & 15;

    // Phase A: scores (8x8 per thread over 128x128)
    {
        float acc[8][8];
#pragma unroll
        for (int i = 0; i < 8; i++)
#pragma unroll
            for (int j = 0; j < 8; j++) acc[i][j] = 0.f;
        for (int kk = 0; kk < 64; kk++) {
            float a[8], bb[8];
#pragma unroll
            for (int i = 0; i < 8; i++) a[i] = Qs[(ty + 16 * i) * 65 + kk];
#pragma unroll
            for (int j = 0; j < 8; j++) bb[j] = Ks[(tx + 16 * j) * 65 + kk];
#pragma unroll
            for (int i = 0; i < 8; i++)
#pragma unroll
                for (int j = 0; j < 8; j++) acc[i][j] += a[i] * bb[j];
        }
#pragma unroll
        for (int i = 0; i < 8; i++) {
            int p = ty + 16 * i;
#pragma unroll
            for (int j = 0; j < 8; j++) {
                int jj = tx + 16 * j;
                Asm[p * 129 + jj] = (p >= jj) ? acc[i][j] * dtab[p - jj] : 0.f;
            }
        }
    }
    __syncthreads();

    // Phase O: O_intra = A @ V (8 rows x 4 cols per thread)
    {
        float o[8][4];
#pragma unroll
        for (int i = 0; i < 8; i++)
#pragma unroll
            for (int j = 0; j < 4; j++) o[i][j] = 0.f;
        for (int jj = 0; jj < 128; jj++) {
            float vv[4];
#pragma unroll
            for (int j = 0; j < 4; j++) vv[j] = Vs[jj * 65 + tx + 16 * j];
#pragma unroll
            for (int i = 0; i < 8; i++) {
                float a = Asm[(ty + 16 * i) * 129 + jj];
#pragma unroll
                for (int j = 0; j < 4; j++) o[i][j] += a * vv[j];
            }
        }
#pragma unroll
        for (int i = 0; i < 8; i++) {
            int p = ty + 16 * i;
            size_t gb = (size_t)(b * NSEQ + n0 + p) * EE + h * DD;
#pragma unroll
            for (int j = 0; j < 4; j++) g_attn[gb + tx + 16 * j] = o[i][j];
        }
    }

    // Phase T: local weighted KV sum (4x4 per thread over 64x64), reads K,V only
    {
        float t[4][4];
#pragma unroll
        for (int ii = 0; ii < 4; ii++)
#pragma unroll
            for (int jj = 0; jj < 4; jj++) t[ii][jj] = 0.f;
        for (int p = 0; p < 128; p++) {
            float w = dtab[CC - p];
            float kw[4], vv[4];
#pragma unroll
            for (int ii = 0; ii < 4; ii++) kw[ii] = Ks[p * 65 + ty + 16 * ii] * w;
#pragma unroll
            for (int jj = 0; jj < 4; jj++) vv[jj] = Vs[p * 65 + tx + 16 * jj];
#pragma unroll
            for (int ii = 0; ii < 4; ii++)
#pragma unroll
                for (int jj = 0; jj < 4; jj++) t[ii][jj] += kw[ii] * vv[jj];
        }
        size_t tb = ((size_t)bh * NCH + chunk) * DD * DD;
#pragma unroll
        for (int ii = 0; ii < 4; ii++)
#pragma unroll
            for (int jj = 0; jj < 4; jj++)
                g_T[tb + (ty + 16 * ii) * DD + tx + 16 * jj] = t[ii][jj];
    }
}

// =========================================================================
// Pass B: per-bh serial scan over 16 chunks: S_0=0; S_{t+1}=gamma*S_t + T_t
// =========================================================================
__global__ __launch_bounds__(256) void scan_k(const float* __restrict__ lam) {
    int bh = blockIdx.x;
    int h = bh % HH;
    float gamma = __expf(lam[h] * (float)CC);
    size_t base = (size_t)bh * NCH * DD * DD;
    for (int e = threadIdx.x; e < DD * DD; e += blockDim.x) {
        float s = 0.f;
#pragma unroll
        for (int t = 0; t < NCH; t++) {
            g_S[base + t * DD * DD + e] = s;
            s = gamma * s + g_T[base + t * DD * DD + e];
        }
    }
}

// =========================================================================
// Pass C: O_inter[p] = exp(lambda*p) * (q_p @ S); fuse gate multiply:
//   g_attn = (g_attn + O_inter) * g_gate
// Dynamic smem: Q[128x64], S[64x64], ep[128]
// =========================================================================
__global__ __launch_bounds__(256) void attn_inter_k(const float* __restrict__ lam) {
    extern __shared__ __align__(16) float sm2[];
    float* Qs = sm2;                 // 128*64
    float* Ss = Qs + 128 * 64;       // 64*64
    float* ep = Ss + 64 * 64;        // 128

    int tid = threadIdx.x;
    int chunk = blockIdx.x;
    int bh = blockIdx.y;
    int b = bh / HH, h = bh % HH;
    float lambda = lam[h];
    int n0 = chunk * CC;

    for (int i = tid; i < 128; i += 256) ep[i] = __expf(lambda * (float)i);

    for (int idx = tid; idx < 128 * 16; idx += 256) {
        int p = idx >> 4;
        int d4 = (idx & 15) * 4;
        float4 q4 = *(const float4*)(g_q + (size_t)(b * NSEQ + n0 + p) * EE + h * DD + d4);
        *(float4*)(&Qs[p * 64 + d4]) = q4;
    }
    size_t sb = ((size_t)bh * NCH + chunk) * DD * DD;
    for (int idx = tid; idx < 64 * 16; idx += 256) {
        *(float4*)(&Ss[idx * 4]) = *(const float4*)(g_S + sb + idx * 4);
    }
    __syncthreads();

    int ty = tid >> 4, tx = tid & 15;
    float o[8][4];
#pragma unroll
    for (int i = 0; i < 8; i++)
#pragma unroll
        for (int j = 0; j < 4; j++) o[i][j] = 0.f;
    for (int kd = 0; kd < 64; kd++) {
        float sv[4];
#pragma unroll
        for (int j = 0; j < 4; j++) sv[j] = Ss[kd * 64 + tx + 16 * j];
#pragma unroll
        for (int i = 0; i < 8; i++) {
            float q = Qs[(ty + 16 * i) * 64 + kd];
#pragma unroll
            for (int j = 0; j < 4; j++) o[i][j] += q * sv[j];
        }
    }
#pragma unroll
    for (int i = 0; i < 8; i++) {
        int p = ty + 16 * i;
        float e = ep[p];
        size_t gb = (size_t)(b * NSEQ + n0 + p) * EE + h * DD;
#pragma unroll
        for (int j = 0; j < 4; j++) {
            size_t gi = gb + tx + 16 * j;
            g_attn[gi] = (g_attn[gi] + e * o[i][j]) * g_gate[gi];
        }
    }
}

// =========================================================================
// LayerNorm over last dim (768). One block (256 thr) per row; two-pass.
// =========================================================================
__global__ __launch_bounds__(256) void ln_k(const float* __restrict__ w,
                                            const float* __restrict__ bias,
                                            float* __restrict__ out) {
    int row = blockIdx.x;
    int t = threadIdx.x;
    const float* yr = g_y + (size_t)row * EE;
    float v0 = yr[t], v1 = yr[t + 256], v2 = yr[t + 512];

    __shared__ float red[32];
    float s = v0 + v1 + v2;
#pragma unroll
    for (int off = 16; off > 0; off >>= 1) s += __shfl_down_sync(0xffffffffu, s, off);
    if ((t & 31) == 0) red[t >> 5] = s;
    __syncthreads();
    if (t < 32) {
        float x = (t < 8) ? red[t] : 0.f;
#pragma unroll
        for (int off = 4; off > 0; off >>= 1) x += __shfl_down_sync(0xffffffffu, x, off);
        if (t == 0) red[0] = x;
    }
    __syncthreads();
    float mu = red[0] * (1.f / 768.f);
    __syncthreads();

    float d0 = v0 - mu, d1 = v1 - mu, d2 = v2 - mu;
    float s2 = d0 * d0 + d1 * d1 + d2 * d2;
#pragma unroll
    for (int off = 16; off > 0; off >>= 1) s2 += __shfl_down_sync(0xffffffffu, s2, off);
    if ((t & 31) == 0) red[t >> 5] = s2;
    __syncthreads();
    if (t < 32) {
        float x = (t < 8) ? red[t] : 0.f;
#pragma unroll
        for (int off = 4; off > 0; off >>= 1) x += __shfl_down_sync(0xffffffffu, x, off);
        if (t == 0) red[0] = x;
    }
    __syncthreads();
    float var = red[0] * (1.f / 768.f);
    float rs = rsqrtf(var + 1e-5f);

    size_t ob = (size_t)row * EE;
    out[ob + t]       = d0 * rs * w[t]       + bias[t];
    out[ob + t + 256] = d1 * rs * w[t + 256] + bias[t + 256];
    out[ob + t + 512] = d2 * rs * w[t + 512] + bias[t + 512];
}

// =========================================================================
extern "C" void kernel_launch(void* const* d_in, const int* in_sizes, int n_in,
                              void* d_out, int out_size) {
    (void)in_sizes; (void)n_in; (void)out_size;
    const float* x         = (const float*)d_in[0];
    const float* log_slope = (const float*)d_in[1];
    const float* Wq        = (const float*)d_in[2];
    const float* Wk        = (const float*)d_in[3];
    const float* Wv        = (const float*)d_in[4];
    const float* Wo        = (const float*)d_in[5];
    const float* Wg1       = (const float*)d_in[6];
    const float* Wg2       = (const float*)d_in[7];
    const float* ln_w      = (const float*)d_in[8];
    const float* ln_b      = (const float*)d_in[9];
    float* out = (float*)d_out;

    int smA = (3 * 128 * 65 + 128 * 129 + 129) * (int)sizeof(float);   // ~166 KB
    cudaFuncSetAttribute(attn_intra_k, cudaFuncAttributeMaxDynamicSharedMemorySize, smA);
    int smC = (128 * 64 + 64 * 64 + 128) * (int)sizeof(float);         // ~50 KB
    cudaFuncSetAttribute(attn_inter_k, cudaFuncAttributeMaxDynamicSharedMemorySize, smC);

    dim3 gGemm(EE / 64, MTOT / 128);   // (12, 32)

    gemm_k<1, 0, 0><<<gGemm, 256>>>(x, Wq, MTOT, EE, EE);   // q = silu(x@Wq)
    gemm_k<1, 0, 1><<<gGemm, 256>>>(x, Wk, MTOT, EE, EE);   // k
    gemm_k<1, 0, 2><<<gGemm, 256>>>(x, Wv, MTOT, EE, EE);   // v
    gate1_k<<<MTOT / 16, 256>>>(x, Wg1);
    gate2_k<<<dim3(EE / 256, MTOT), 256>>>(Wg2);
    attn_intra_k<<<dim3(NCH, BHH), 256, smA>>>(log_slope);
    scan_k<<<BHH, 256>>>(log_slope);
    attn_inter_k<<<dim3(NCH, BHH), 256, smC>>>(log_slope);
    gemm_k<0, 1, 3><<<gGemm, 256>>>(nullptr, Wo, MTOT, EE, EE);  // y = gated @ Wo
    ln_k<<<MTOT, 256>>>(ln_w, ln_b, out);
}

// round 3
// speedup vs baseline: 1.8284x; 1.8284x over previous
#include <cuda_runtime.h>
#include <cuda_bf16.h>
#include <cstdint>

// Problem constants
#define BB    2
#define NSEQ  2048
#define EE    768
#define HH    12
#define DD    64
#define GG    16
#define CC    128
#define NCH   (NSEQ / CC)         // 16
#define BHH   (BB * HH)           // 24
#define MTOT  (BB * NSEQ)         // 4096

// ---------------- device scratch ----------------
__device__ float g_q[MTOT * EE];
__device__ float g_k[MTOT * EE];
__device__ float g_v[MTOT * EE];
__device__ float g_attn[MTOT * EE];   // intra-chunk attention out (fp32)
__device__ float g_y[MTOT * EE];      // pre-LN (after Wo)
__device__ float g_t16[MTOT * GG];    // x @ Wg1
__device__ float g_T[BHH * NCH * DD * DD];
__device__ float g_S[BHH * NCH * DD * DD];

// bf16 split operands for tensor-core GEMMs
__device__ __nv_bfloat16 g_xhi[MTOT * EE];
__device__ __nv_bfloat16 g_xlo[MTOT * EE];
__device__ __nv_bfloat16 g_ahi[MTOT * EE];
__device__ __nv_bfloat16 g_alo[MTOT * EE];
__device__ __nv_bfloat16 g_wthi[4 * EE * EE];   // transposed [n][k], 4 weights
__device__ __nv_bfloat16 g_wtlo[4 * EE * EE];

// ======================= helpers ==========================
__device__ __forceinline__ uint32_t smem_u32(const void* p) {
    uint32_t a;
    asm("{ .reg .u64 t; cvta.to.shared.u64 t, %1; cvt.u32.u64 %0, t; }"
        : "=r"(a) : "l"(p));
    return a;
}
__device__ __forceinline__ void cp_async16(uint32_t s, const void* g) {
    asm volatile("cp.async.cg.shared.global [%0], [%1], 16;" :: "r"(s), "l"(g));
}
__device__ __forceinline__ void cp_commit() {
    asm volatile("cp.async.commit_group;");
}
template <int N>
__device__ __forceinline__ void cp_wait() {
    asm volatile("cp.async.wait_group %0;" :: "n"(N));
}
__device__ __forceinline__ void ldsm4(uint32_t& r0, uint32_t& r1, uint32_t& r2,
                                      uint32_t& r3, uint32_t a) {
    asm volatile("ldmatrix.sync.aligned.m8n8.x4.shared.b16 {%0,%1,%2,%3}, [%4];"
                 : "=r"(r0), "=r"(r1), "=r"(r2), "=r"(r3) : "r"(a));
}
__device__ __forceinline__ void ldsm2(uint32_t& r0, uint32_t& r1, uint32_t a) {
    asm volatile("ldmatrix.sync.aligned.m8n8.x2.shared.b16 {%0,%1}, [%2];"
                 : "=r"(r0), "=r"(r1) : "r"(a));
}
__device__ __forceinline__ void mma_bf16(float* c, const uint32_t* a,
                                         const uint32_t* b) {
    asm volatile(
        "mma.sync.aligned.m16n8k16.row.col.f32.bf16.bf16.f32 "
        "{%0,%1,%2,%3}, {%4,%5,%6,%7}, {%8,%9}, {%0,%1,%2,%3};"
        : "+f"(c[0]), "+f"(c[1]), "+f"(c[2]), "+f"(c[3])
        : "r"(a[0]), "r"(a[1]), "r"(a[2]), "r"(a[3]), "r"(b[0]), "r"(b[1]));
}
__device__ __forceinline__ void split_bf16(float v, __nv_bfloat16& h, __nv_bfloat16& l) {
    h = __float2bfloat16(v);
    l = __float2bfloat16(v - __bfloat162float(h));
}

// ======================= conversion kernels ==============================
__global__ __launch_bounds__(256) void conv_x_k(const float* __restrict__ x) {
    size_t i = ((size_t)blockIdx.x * 256 + threadIdx.x) * 4;
    float4 v = *(const float4*)(x + i);
    __align__(8) __nv_bfloat16 hi[4], lo[4];
    split_bf16(v.x, hi[0], lo[0]);
    split_bf16(v.y, hi[1], lo[1]);
    split_bf16(v.z, hi[2], lo[2]);
    split_bf16(v.w, hi[3], lo[3]);
    *(uint2*)(g_xhi + i) = *(uint2*)hi;
    *(uint2*)(g_xlo + i) = *(uint2*)lo;
}

// transpose + split weights: out[n][k] = split(W[k][n]); z selects weight
__global__ __launch_bounds__(256) void conv_w_k(const float* __restrict__ Wq,
                                                const float* __restrict__ Wk,
                                                const float* __restrict__ Wv,
                                                const float* __restrict__ Wo) {
    const float* W = (blockIdx.z == 0) ? Wq : (blockIdx.z == 1) ? Wk
                   : (blockIdx.z == 2) ? Wv : Wo;
    __shared__ float t[32][33];
    int tx = threadIdx.x & 31, ty0 = threadIdx.x >> 5;
    int bn = blockIdx.x * 32, bk = blockIdx.y * 32;
#pragma unroll
    for (int r = 0; r < 4; r++) {
        int ty = ty0 + r * 8;
        t[ty][tx] = W[(size_t)(bk + ty) * EE + bn + tx];
    }
    __syncthreads();
    size_t base = (size_t)blockIdx.z * EE * EE;
#pragma unroll
    for (int r = 0; r < 4; r++) {
        int ty = ty0 + r * 8;
        float v = t[tx][ty];   // = W[bk+tx][bn+ty] -> (n=bn+ty, k=bk+tx)
        __nv_bfloat16 h, l;
        split_bf16(v, h, l);
        size_t o = base + (size_t)(bn + ty) * EE + bk + tx;
        g_wthi[o] = h;
        g_wtlo[o] = l;
    }
}

// ======================= bf16x3 mma.sync GEMM ============================
// C[M,768] = act(A @ W). Block 128x128x32, 8 warps (2M x 4N), warp 64x32.
// A split (hi,lo) row-major [m][k]; W split transposed [n][k] (col-major B).
// MODE 0: QKV (silu, z selects); MODE 1: Wo (no act).
#define RSTRIDE 40            // bf16 elems per smem row (80B, conflict-free)
#define SA_H 0
#define SA_L 10240
#define SB_H 20480
#define SB_L 30720
#define STAGE 40960

template <int MODE>
__global__ __launch_bounds__(256, 1) void mm_tc() {
    extern __shared__ char smem[];
    uint32_t sb = smem_u32(smem);

    int tid = threadIdx.x;
    int wid = tid >> 5, lane = tid & 31;
    int wm = wid & 1, wn = wid >> 1;          // warp grid 2(M) x 4(N)

    int z = blockIdx.z;
    const __nv_bfloat16 *Ahi, *Alo, *Whi, *Wlo;
    float* Cm;
    if (MODE == 0) {
        Ahi = g_xhi; Alo = g_xlo;
        Whi = g_wthi + (size_t)z * EE * EE;
        Wlo = g_wtlo + (size_t)z * EE * EE;
        Cm = (z == 0) ? g_q : (z == 1) ? g_k : g_v;
    } else {
        Ahi = g_ahi; Alo = g_alo;
        Whi = g_wthi + (size_t)3 * EE * EE;
        Wlo = g_wtlo + (size_t)3 * EE * EE;
        Cm = g_y;
    }
    int bm = blockIdx.y * 128, bn = blockIdx.x * 128;

    float acc[4][4][4];
#pragma unroll
    for (int i = 0; i < 4; i++)
#pragma unroll
        for (int j = 0; j < 4; j++)
#pragma unroll
            for (int e = 0; e < 4; e++) acc[i][j][e] = 0.f;

    // loader indices: per array, 512 16B-chunks; each thread does 2 per array
    int lr0 = tid >> 2;            // rows tid/4 and tid/4+64
    int lc = (tid & 3) * 8;        // bf16 col offset (8 bf16 = 16B)

    auto issue = [&](int kt, int buf) {
        int k0 = kt * 32;
        uint32_t st = sb + (uint32_t)buf * STAGE;
#pragma unroll
        for (int rr = 0; rr < 2; rr++) {
            int r = lr0 + rr * 64;
            uint32_t so = (uint32_t)(r * RSTRIDE + lc) * 2;
            size_t ga = (size_t)(bm + r) * EE + k0 + lc;
            size_t gb = (size_t)(bn + r) * EE + k0 + lc;
            cp_async16(st + SA_H + so, Ahi + ga);
            cp_async16(st + SA_L + so, Alo + ga);
            cp_async16(st + SB_H + so, Whi + gb);
            cp_async16(st + SB_L + so, Wlo + gb);
        }
        cp_commit();
    };

    // ldmatrix lane addressing (element offsets within tile, bf16 units)
    int a_r = lane & 15;                 // A: row within 16
    int a_k = (lane >> 4) << 3;          // A: +8 k for upper half
    int b_r = lane & 7;                  // B: n within 8
    int b_k = ((lane >> 3) & 1) << 3;    // B: +8 k for second matrix

    issue(0, 0);
    for (int kt = 0; kt < 24; kt++) {
        int buf = kt & 1;
        if (kt < 23) issue(kt + 1, buf ^ 1);
        if (kt < 23) cp_wait<1>(); else cp_wait<0>();
        __syncthreads();

        uint32_t st = sb + (uint32_t)buf * STAGE;
#pragma unroll
        for (int ks = 0; ks < 2; ks++) {
            int kk = ks * 16;
            uint32_t ah[4][4], al[4][4];
#pragma unroll
            for (int im = 0; im < 4; im++) {
                int row = wm * 64 + im * 16 + a_r;
                uint32_t off = (uint32_t)(row * RSTRIDE + kk + a_k) * 2;
                ldsm4(ah[im][0], ah[im][1], ah[im][2], ah[im][3], st + SA_H + off);
                ldsm4(al[im][0], al[im][1], al[im][2], al[im][3], st + SA_L + off);
            }
            uint32_t bh[4][2], bl[4][2];
#pragma unroll
            for (int jn = 0; jn < 4; jn++) {
                int nrow = wn * 32 + jn * 8 + b_r;
                uint32_t off = (uint32_t)(nrow * RSTRIDE + kk + b_k) * 2;
                ldsm2(bh[jn][0], bh[jn][1], st + SB_H + off);
                ldsm2(bl[jn][0], bl[jn][1], st + SB_L + off);
            }
#pragma unroll
            for (int im = 0; im < 4; im++)
#pragma unroll
                for (int jn = 0; jn < 4; jn++) {
                    mma_bf16(acc[im][jn], ah[im], bh[jn]);
                    mma_bf16(acc[im][jn], ah[im], bl[jn]);
                    mma_bf16(acc[im][jn], al[im], bh[jn]);
                }
        }
        __syncthreads();
    }

    // epilogue: c0,c1 -> (r, c..c+1); c2,c3 -> (r+8, c..c+1)
    int er = lane >> 2, ec = (lane & 3) * 2;
#pragma unroll
    for (int im = 0; im < 4; im++) {
#pragma unroll
        for (int jn = 0; jn < 4; jn++) {
            int row = bm + wm * 64 + im * 16 + er;
            int col = bn + wn * 32 + jn * 8 + ec;
            float v0 = acc[im][jn][0], v1 = acc[im][jn][1];
            float v2 = acc[im][jn][2], v3 = acc[im][jn][3];
            if (MODE == 0) {
                v0 = v0 / (1.f + __expf(-v0));
                v1 = v1 / (1.f + __expf(-v1));
                v2 = v2 / (1.f + __expf(-v2));
                v3 = v3 / (1.f + __expf(-v3));
            }
            *(float2*)(Cm + (size_t)row * EE + col) = make_float2(v0, v1);
            *(float2*)(Cm + (size_t)(row + 8) * EE + col) = make_float2(v2, v3);
        }
    }
}

// ======================= gate stage 1 ====================================
__global__ __launch_bounds__(128) void gate1_k(const float* __restrict__ x,
                                               const float* __restrict__ Wg1) {
    __shared__ float xs[8 * EE];
    int row0 = blockIdx.x * 8;
    for (int i = threadIdx.x; i < 8 * (EE / 4); i += 128)
        *(float4*)(xs + i * 4) = *(const float4*)(x + (size_t)row0 * EE + i * 4);
    __syncthreads();
    int r = threadIdx.x >> 4, g = threadIdx.x & 15;
    const float* xr = xs + r * EE;
    float acc = 0.f;
#pragma unroll 16
    for (int k = 0; k < EE; k++) acc += xr[k] * Wg1[k * GG + g];
    g_t16[(size_t)(row0 + r) * GG + g] = acc;
}

// ======================= attention pass A (intra-chunk) ==================
__global__ __launch_bounds__(256) void attn_intra_k(const float* __restrict__ lam) {
    extern __shared__ __align__(16) float sm[];
    float* Qs = sm;                      // 128*65
    float* Ks = Qs + 128 * 65;
    float* Vs = Ks + 128 * 65;
    float* Asm = Vs + 128 * 65;          // 128*129
    float* dtab = Asm + 128 * 129;       // 129

    int tid = threadIdx.x;
    int chunk = blockIdx.x;
    int bh = blockIdx.y;
    int b = bh / HH, h = bh % HH;
    float lambda = lam[h];
    int n0 = chunk * CC;

    for (int i = tid; i <= CC; i += 256) dtab[i] = __expf(lambda * (float)i);

    for (int idx = tid; idx < 128 * 16; idx += 256) {
        int p = idx >> 4;
        int d4 = (idx & 15) * 4;
        size_t gb = (size_t)(b * NSEQ + n0 + p) * EE + h * DD + d4;
        float4 q4 = *(const float4*)(g_q + gb);
        float4 k4 = *(const float4*)(g_k + gb);
        float4 v4 = *(const float4*)(g_v + gb);
        int sb = p * 65 + d4;
        Qs[sb] = q4.x; Qs[sb + 1] = q4.y; Qs[sb + 2] = q4.z; Qs[sb + 3] = q4.w;
        Ks[sb] = k4.x; Ks[sb + 1] = k4.y; Ks[sb + 2] = k4.z; Ks[sb + 3] = k4.w;
        Vs[sb] = v4.x; Vs[sb + 1] = v4.y; Vs[sb + 2] = v4.z; Vs[sb + 3] = v4.w;
    }
    __syncthreads();

    int ty = tid >> 4, tx = tid & 15;

    {   // scores
        float acc[8][8];
#pragma unroll
        for (int i = 0; i < 8; i++)
#pragma unroll
            for (int j = 0; j < 8; j++) acc[i][j] = 0.f;
        for (int kk = 0; kk < 64; kk++) {
            float a[8], bb[8];
#pragma unroll
            for (int i = 0; i < 8; i++) a[i] = Qs[(ty + 16 * i) * 65 + kk];
#pragma unroll
            for (int j = 0; j < 8; j++) bb[j] = Ks[(tx + 16 * j) * 65 + kk];
#pragma unroll
            for (int i = 0; i < 8; i++)
#pragma unroll
                for (int j = 0; j < 8; j++) acc[i][j] += a[i] * bb[j];
        }
#pragma unroll
        for (int i = 0; i < 8; i++) {
            int p = ty + 16 * i;
#pragma unroll
            for (int j = 0; j < 8; j++) {
                int jj = tx + 16 * j;
                Asm[p * 129 + jj] = (p >= jj) ? acc[i][j] * dtab[p - jj] : 0.f;
            }
        }
    }
    __syncthreads();

    {   // O_intra = A @ V
        float o[8][4];
#pragma unroll
        for (int i = 0; i < 8; i++)
#pragma unroll
            for (int j = 0; j < 4; j++) o[i][j] = 0.f;
        for (int jj = 0; jj < 128; jj++) {
            float vv[4];
#pragma unroll
            for (int j = 0; j < 4; j++) vv[j] = Vs[jj * 65 + tx + 16 * j];
#pragma unroll
            for (int i = 0; i < 8; i++) {
                float a = Asm[(ty + 16 * i) * 129 + jj];
#pragma unroll
                for (int j = 0; j < 4; j++) o[i][j] += a * vv[j];
            }
        }
#pragma unroll
        for (int i = 0; i < 8; i++) {
            int p = ty + 16 * i;
            size_t gb = (size_t)(b * NSEQ + n0 + p) * EE + h * DD;
#pragma unroll
            for (int j = 0; j < 4; j++) g_attn[gb + tx + 16 * j] = o[i][j];
        }
    }

    {   // local weighted KV sum
        float t[4][4];
#pragma unroll
        for (int ii = 0; ii < 4; ii++)
#pragma unroll
            for (int jj = 0; jj < 4; jj++) t[ii][jj] = 0.f;
        for (int p = 0; p < 128; p++) {
            float w = dtab[CC - p];
            float kw[4], vv[4];
#pragma unroll
            for (int ii = 0; ii < 4; ii++) kw[ii] = Ks[p * 65 + ty + 16 * ii] * w;
#pragma unroll
            for (int jj = 0; jj < 4; jj++) vv[jj] = Vs[p * 65 + tx + 16 * jj];
#pragma unroll
            for (int ii = 0; ii < 4; ii++)
#pragma unroll
                for (int jj = 0; jj < 4; jj++) t[ii][jj] += kw[ii] * vv[jj];
        }
        size_t tb = ((size_t)bh * NCH + chunk) * DD * DD;
#pragma unroll
        for (int ii = 0; ii < 4; ii++)
#pragma unroll
            for (int jj = 0; jj < 4; jj++)
                g_T[tb + (ty + 16 * ii) * DD + tx + 16 * jj] = t[ii][jj];
    }
}

// ======================= pass B: chunk-state scan ========================
__global__ __launch_bounds__(256) void scan_k(const float* __restrict__ lam) {
    int bh = blockIdx.x;
    int h = bh % HH;
    float gamma = __expf(lam[h] * (float)CC);
    size_t base = (size_t)bh * NCH * DD * DD;
    for (int e = threadIdx.x; e < DD * DD; e += blockDim.x) {
        float s = 0.f;
#pragma unroll
        for (int t = 0; t < NCH; t++) {
            g_S[base + t * DD * DD + e] = s;
            s = gamma * s + g_T[base + t * DD * DD + e];
        }
    }
}

// ======================= pass C: inter-chunk + gate fuse + bf16 out ======
__global__ __launch_bounds__(256) void attn_inter_k(const float* __restrict__ lam,
                                                    const float* __restrict__ Wg2) {
    extern __shared__ __align__(16) float sm2[];
    float* Qs = sm2;                  // 128*64
    float* Ss = Qs + 128 * 64;        // 64*64
    float* ep = Ss + 64 * 64;         // 128
    float* t16s = ep + 128;           // 128*16
    float* wg2s = t16s + 128 * 16;    // 16*64

    int tid = threadIdx.x;
    int chunk = blockIdx.x;
    int bh = blockIdx.y;
    int b = bh / HH, h = bh % HH;
    float lambda = lam[h];
    int n0 = chunk * CC;

    for (int i = tid; i < 128; i += 256) ep[i] = __expf(lambda * (float)i);

    for (int idx = tid; idx < 128 * 16; idx += 256) {
        int p = idx >> 4;
        int d4 = (idx & 15) * 4;
        float4 q4 = *(const float4*)(g_q + (size_t)(b * NSEQ + n0 + p) * EE + h * DD + d4);
        *(float4*)(&Qs[p * 64 + d4]) = q4;
    }
    size_t sbo = ((size_t)bh * NCH + chunk) * DD * DD;
    for (int idx = tid; idx < 64 * 16; idx += 256)
        *(float4*)(&Ss[idx * 4]) = *(const float4*)(g_S + sbo + idx * 4);
    for (int i = tid; i < 512; i += 256)
        *(float4*)(t16s + i * 4) =
            *(const float4*)(g_t16 + (size_t)(b * NSEQ + n0) * GG + i * 4);
    for (int i = tid; i < 256; i += 256) {
        int g = i >> 4, c4 = (i & 15) * 4;
        *(float4*)(wg2s + g * 64 + c4) = *(const float4*)(Wg2 + g * EE + h * DD + c4);
    }
    __syncthreads();

    int ty = tid >> 4, tx = tid & 15;
    float o[8][4];
#pragma unroll
    for (int i = 0; i < 8; i++)
#pragma unroll
        for (int j = 0; j < 4; j++) o[i][j] = 0.f;
    for (int kd = 0; kd < 64; kd++) {
        float sv[4];
#pragma unroll
        for (int j = 0; j < 4; j++) sv[j] = Ss[kd * 64 + tx + 16 * j];
#pragma unroll
        for (int i = 0; i < 8; i++) {
            float q = Qs[(ty + 16 * i) * 64 + kd];
#pragma unroll
            for (int j = 0; j < 4; j++) o[i][j] += q * sv[j];
        }
    }
#pragma unroll
    for (int i = 0; i < 8; i++) {
        int p = ty + 16 * i;
        float e = ep[p];
        size_t gb = (size_t)(b * NSEQ + n0 + p) * EE + h * DD;
#pragma unroll
        for (int j = 0; j < 4; j++) {
            int c = tx + 16 * j;
            float s = 0.f;
#pragma unroll
            for (int g = 0; g < 16; g++) s += t16s[p * 16 + g] * wg2s[g * 64 + c];
            float gate = 1.f / (1.f + __expf(-s));
            size_t gi = gb + c;
            float val = (g_attn[gi] + e * o[i][j]) * gate;
            __nv_bfloat16 hv, lv;
            split_bf16(val, hv, lv);
            g_ahi[gi] = hv;
            g_alo[gi] = lv;
        }
    }
}

// ======================= LayerNorm =======================================
__global__ __launch_bounds__(256) void ln_k(const float* __restrict__ w,
                                            const float* __restrict__ bias,
                                            float* __restrict__ out) {
    int row = blockIdx.x;
    int t = threadIdx.x;
    const float* yr = g_y + (size_t)row * EE;
    float v0 = yr[t], v1 = yr[t + 256], v2 = yr[t + 512];

    __shared__ float red[32];
    float s = v0 + v1 + v2;
#pragma unroll
    for (int off = 16; off > 0; off >>= 1) s += __shfl_down_sync(0xffffffffu, s, off);
    if ((t & 31) == 0) red[t >> 5] = s;
    __syncthreads();
    if (t < 32) {
        float x = (t < 8) ? red[t] : 0.f;
#pragma unroll
        for (int off = 4; off > 0; off >>= 1) x += __shfl_down_sync(0xffffffffu, x, off);
        if (t == 0) red[0] = x;
    }
    __syncthreads();
    float mu = red[0] * (1.f / 768.f);
    __syncthreads();

    float d0 = v0 - mu, d1 = v1 - mu, d2 = v2 - mu;
    float s2 = d0 * d0 + d1 * d1 + d2 * d2;
#pragma unroll
    for (int off = 16; off > 0; off >>= 1) s2 += __shfl_down_sync(0xffffffffu, s2, off);
    if ((t & 31) == 0) red[t >> 5] = s2;
    __syncthreads();
    if (t < 32) {
        float x = (t < 8) ? red[t] : 0.f;
#pragma unroll
        for (int off = 4; off > 0; off >>= 1) x += __shfl_down_sync(0xffffffffu, x, off);
        if (t == 0) red[0] = x;
    }
    __syncthreads();
    float var = red[0] * (1.f / 768.f);
    float rs = rsqrtf(var + 1e-5f);

    size_t ob = (size_t)row * EE;
    out[ob + t]       = d0 * rs * w[t]       + bias[t];
    out[ob + t + 256] = d1 * rs * w[t + 256] + bias[t + 256];
    out[ob + t + 512] = d2 * rs * w[t + 512] + bias[t + 512];
}

// =========================================================================
extern "C" void kernel_launch(void* const* d_in, const int* in_sizes, int n_in,
                              void* d_out, int out_size) {
    (void)in_sizes; (void)n_in; (void)out_size;
    const float* x         = (const float*)d_in[0];
    const float* log_slope = (const float*)d_in[1];
    const float* Wq        = (const float*)d_in[2];
    const float* Wk        = (const float*)d_in[3];
    const float* Wv        = (const float*)d_in[4];
    const float* Wo        = (const float*)d_in[5];
    const float* Wg1       = (const float*)d_in[6];
    const float* Wg2       = (const float*)d_in[7];
    const float* ln_w      = (const float*)d_in[8];
    const float* ln_b      = (const float*)d_in[9];
    float* out = (float*)d_out;

    int smMM = 2 * STAGE;   // 80 KB
    cudaFuncSetAttribute(mm_tc<0>, cudaFuncAttributeMaxDynamicSharedMemorySize, smMM);
    cudaFuncSetAttribute(mm_tc<1>, cudaFuncAttributeMaxDynamicSharedMemorySize, smMM);
    int smA = (3 * 128 * 65 + 128 * 129 + 129) * (int)sizeof(float);
    cudaFuncSetAttribute(attn_intra_k, cudaFuncAttributeMaxDynamicSharedMemorySize, smA);
    int smC = (128 * 64 + 64 * 64 + 128 + 128 * 16 + 16 * 64) * (int)sizeof(float);
    cudaFuncSetAttribute(attn_inter_k, cudaFuncAttributeMaxDynamicSharedMemorySize, smC);

    conv_x_k<<<MTOT * EE / 1024, 256>>>(x);
    conv_w_k<<<dim3(EE / 32, EE / 32, 4), 256>>>(Wq, Wk, Wv, Wo);
    mm_tc<0><<<dim3(EE / 128, MTOT / 128, 3), 256, smMM>>>();   // q,k,v = silu(x@W)
    gate1_k<<<MTOT / 8, 128>>>(x, Wg1);
    attn_intra_k<<<dim3(NCH, BHH), 256, smA>>>(log_slope);
    scan_k<<<BHH, 256>>>(log_slope);
    attn_inter_k<<<dim3(NCH, BHH), 256, smC>>>(log_slope, Wg2);
    mm_tc<1><<<dim3(EE / 128, MTOT / 128, 1), 256, smMM>>>();   // y = gated @ Wo
    ln_k<<<MTOT, 256>>>(ln_w, ln_b, out);
}

// round 4
// speedup vs baseline: 1.9645x; 1.0745x over previous
#include <cuda_runtime.h>
#include <cuda_bf16.h>
#include <cstdint>

// Problem constants
#define BB    2
#define NSEQ  2048
#define EE    768
#define HH    12
#define DD    64
#define GG    16
#define CC    128
#define NCH   (NSEQ / CC)         // 16
#define BHH   (BB * HH)           // 24
#define MTOT  (BB * NSEQ)         // 4096

// ---------------- device scratch ----------------
__device__ float g_attn[MTOT * EE];   // intra-chunk attention out (fp32)
__device__ float g_y[MTOT * EE];      // pre-LN (after Wo)
__device__ float g_t16[MTOT * GG];    // x @ Wg1
__device__ float g_T[BHH * NCH * DD * DD];
__device__ float g_S[BHH * NCH * DD * DD];

// bf16 split operands
__device__ __nv_bfloat16 g_xhi[MTOT * EE];
__device__ __nv_bfloat16 g_xlo[MTOT * EE];
__device__ __nv_bfloat16 g_ahi[MTOT * EE];
__device__ __nv_bfloat16 g_alo[MTOT * EE];
__device__ __nv_bfloat16 g_qhi[MTOT * EE];
__device__ __nv_bfloat16 g_qlo[MTOT * EE];
__device__ __nv_bfloat16 g_khi[MTOT * EE];
__device__ __nv_bfloat16 g_klo[MTOT * EE];
__device__ __nv_bfloat16 g_vhi[MTOT * EE];
__device__ __nv_bfloat16 g_vlo[MTOT * EE];
__device__ __nv_bfloat16 g_wthi[4 * EE * EE];   // transposed [n][k]
__device__ __nv_bfloat16 g_wtlo[4 * EE * EE];
__device__ __nv_bfloat16 g_g1thi[GG * EE];      // Wg1 transposed [g][k]
__device__ __nv_bfloat16 g_g1tlo[GG * EE];

// ======================= helpers ==========================
__device__ __forceinline__ uint32_t smem_u32(const void* p) {
    uint32_t a;
    asm("{ .reg .u64 t; cvta.to.shared.u64 t, %1; cvt.u32.u64 %0, t; }"
        : "=r"(a) : "l"(p));
    return a;
}
__device__ __forceinline__ void cp_async16(uint32_t s, const void* g) {
    asm volatile("cp.async.cg.shared.global [%0], [%1], 16;" :: "r"(s), "l"(g));
}
__device__ __forceinline__ void cp_commit() {
    asm volatile("cp.async.commit_group;");
}
template <int N>
__device__ __forceinline__ void cp_wait() {
    asm volatile("cp.async.wait_group %0;" :: "n"(N));
}
__device__ __forceinline__ void ldsm4(uint32_t& r0, uint32_t& r1, uint32_t& r2,
                                      uint32_t& r3, uint32_t a) {
    asm volatile("ldmatrix.sync.aligned.m8n8.x4.shared.b16 {%0,%1,%2,%3}, [%4];"
                 : "=r"(r0), "=r"(r1), "=r"(r2), "=r"(r3) : "r"(a));
}
__device__ __forceinline__ void ldsm2(uint32_t& r0, uint32_t& r1, uint32_t a) {
    asm volatile("ldmatrix.sync.aligned.m8n8.x2.shared.b16 {%0,%1}, [%2];"
                 : "=r"(r0), "=r"(r1) : "r"(a));
}
__device__ __forceinline__ void mma_bf16(float* c, const uint32_t* a,
                                         const uint32_t* b) {
    asm volatile(
        "mma.sync.aligned.m16n8k16.row.col.f32.bf16.bf16.f32 "
        "{%0,%1,%2,%3}, {%4,%5,%6,%7}, {%8,%9}, {%0,%1,%2,%3};"
        : "+f"(c[0]), "+f"(c[1]), "+f"(c[2]), "+f"(c[3])
        : "r"(a[0]), "r"(a[1]), "r"(a[2]), "r"(a[3]), "r"(b[0]), "r"(b[1]));
}
__device__ __forceinline__ void split_bf16(float v, __nv_bfloat16& h, __nv_bfloat16& l) {
    h = __float2bfloat16(v);
    l = __float2bfloat16(v - __bfloat162float(h));
}
// pack two floats into hi-word / lo-word bf16 pairs
__device__ __forceinline__ void split2(float a, float b, uint32_t& hi, uint32_t& lo) {
    __nv_bfloat16 ha = __float2bfloat16(a), hb = __float2bfloat16(b);
    hi = (uint32_t)*(uint16_t*)&ha | ((uint32_t)*(uint16_t*)&hb << 16);
    float la = a - __bfloat162float(ha), lb = b - __bfloat162float(hb);
    __nv_bfloat16 hla = __float2bfloat16(la), hlb = __float2bfloat16(lb);
    lo = (uint32_t)*(uint16_t*)&hla | ((uint32_t)*(uint16_t*)&hlb << 16);
}

// ======================= conversion kernels ==============================
__global__ __launch_bounds__(256) void conv_x_k(const float* __restrict__ x) {
    size_t i = ((size_t)blockIdx.x * 256 + threadIdx.x) * 4;
    float4 v = *(const float4*)(x + i);
    __align__(8) __nv_bfloat16 hi[4], lo[4];
    split_bf16(v.x, hi[0], lo[0]);
    split_bf16(v.y, hi[1], lo[1]);
    split_bf16(v.z, hi[2], lo[2]);
    split_bf16(v.w, hi[3], lo[3]);
    *(uint2*)(g_xhi + i) = *(uint2*)hi;
    *(uint2*)(g_xlo + i) = *(uint2*)lo;
}

__global__ __launch_bounds__(256) void conv_w_k(const float* __restrict__ Wq,
                                                const float* __restrict__ Wk,
                                                const float* __restrict__ Wv,
                                                const float* __restrict__ Wo) {
    const float* W = (blockIdx.z == 0) ? Wq : (blockIdx.z == 1) ? Wk
                   : (blockIdx.z == 2) ? Wv : Wo;
    __shared__ float t[32][33];
    int tx = threadIdx.x & 31, ty0 = threadIdx.x >> 5;
    int bn = blockIdx.x * 32, bk = blockIdx.y * 32;
#pragma unroll
    for (int r = 0; r < 4; r++) {
        int ty = ty0 + r * 8;
        t[ty][tx] = W[(size_t)(bk + ty) * EE + bn + tx];
    }
    __syncthreads();
    size_t base = (size_t)blockIdx.z * EE * EE;
#pragma unroll
    for (int r = 0; r < 4; r++) {
        int ty = ty0 + r * 8;
        float v = t[tx][ty];
        __nv_bfloat16 h, l;
        split_bf16(v, h, l);
        size_t o = base + (size_t)(bn + ty) * EE + bk + tx;
        g_wthi[o] = h;
        g_wtlo[o] = l;
    }
}

// Wg1 [768][16] -> transposed split [16][768]
__global__ __launch_bounds__(256) void convg1_k(const float* __restrict__ Wg1) {
    int i = blockIdx.x * 256 + threadIdx.x;   // < 12288
    int n = i / EE, k = i % EE;
    __nv_bfloat16 h, l;
    split_bf16(Wg1[k * GG + n], h, l);
    g_g1thi[i] = h;
    g_g1tlo[i] = l;
}

// ======================= bf16x3 mma.sync GEMM ============================
#define RSTRIDE 40
#define SA_H 0
#define SA_L 10240
#define SB_H 20480
#define SB_L 30720
#define STAGE 40960

template <int MODE>
__global__ __launch_bounds__(256, 1) void mm_tc() {
    extern __shared__ char smem[];
    uint32_t sb = smem_u32(smem);

    int tid = threadIdx.x;
    int wid = tid >> 5, lane = tid & 31;
    int wm = wid & 1, wn = wid >> 1;

    int z = blockIdx.z;
    const __nv_bfloat16 *Ahi, *Alo, *Whi, *Wlo;
    float* Cm = nullptr;
    __nv_bfloat16 *Chi = nullptr, *Clo = nullptr;
    if (MODE == 0) {
        Ahi = g_xhi; Alo = g_xlo;
        Whi = g_wthi + (size_t)z * EE * EE;
        Wlo = g_wtlo + (size_t)z * EE * EE;
        Chi = (z == 0) ? g_qhi : (z == 1) ? g_khi : g_vhi;
        Clo = (z == 0) ? g_qlo : (z == 1) ? g_klo : g_vlo;
    } else {
        Ahi = g_ahi; Alo = g_alo;
        Whi = g_wthi + (size_t)3 * EE * EE;
        Wlo = g_wtlo + (size_t)3 * EE * EE;
        Cm = g_y;
    }
    int bm = blockIdx.y * 128, bn = blockIdx.x * 128;

    float acc[4][4][4];
#pragma unroll
    for (int i = 0; i < 4; i++)
#pragma unroll
        for (int j = 0; j < 4; j++)
#pragma unroll
            for (int e = 0; e < 4; e++) acc[i][j][e] = 0.f;

    int lr0 = tid >> 2;
    int lc = (tid & 3) * 8;

    auto issue = [&](int kt, int buf) {
        int k0 = kt * 32;
        uint32_t st = sb + (uint32_t)buf * STAGE;
#pragma unroll
        for (int rr = 0; rr < 2; rr++) {
            int r = lr0 + rr * 64;
            uint32_t so = (uint32_t)(r * RSTRIDE + lc) * 2;
            size_t ga = (size_t)(bm + r) * EE + k0 + lc;
            size_t gb = (size_t)(bn + r) * EE + k0 + lc;
            cp_async16(st + SA_H + so, Ahi + ga);
            cp_async16(st + SA_L + so, Alo + ga);
            cp_async16(st + SB_H + so, Whi + gb);
            cp_async16(st + SB_L + so, Wlo + gb);
        }
        cp_commit();
    };

    int a_r = lane & 15;
    int a_k = (lane >> 4) << 3;
    int b_r = lane & 7;
    int b_k = ((lane >> 3) & 1) << 3;

    issue(0, 0);
    for (int kt = 0; kt < 24; kt++) {
        int buf = kt & 1;
        if (kt < 23) issue(kt + 1, buf ^ 1);
        if (kt < 23) cp_wait<1>(); else cp_wait<0>();
        __syncthreads();

        uint32_t st = sb + (uint32_t)buf * STAGE;
#pragma unroll
        for (int ks = 0; ks < 2; ks++) {
            int kk = ks * 16;
            uint32_t ah[4][4], al[4][4];
#pragma unroll
            for (int im = 0; im < 4; im++) {
                int row = wm * 64 + im * 16 + a_r;
                uint32_t off = (uint32_t)(row * RSTRIDE + kk + a_k) * 2;
                ldsm4(ah[im][0], ah[im][1], ah[im][2], ah[im][3], st + SA_H + off);
                ldsm4(al[im][0], al[im][1], al[im][2], al[im][3], st + SA_L + off);
            }
            uint32_t bh[4][2], bl[4][2];
#pragma unroll
            for (int jn = 0; jn < 4; jn++) {
                int nrow = wn * 32 + jn * 8 + b_r;
                uint32_t off = (uint32_t)(nrow * RSTRIDE + kk + b_k) * 2;
                ldsm2(bh[jn][0], bh[jn][1], st + SB_H + off);
                ldsm2(bl[jn][0], bl[jn][1], st + SB_L + off);
            }
#pragma unroll
            for (int im = 0; im < 4; im++)
#pragma unroll
                for (int jn = 0; jn < 4; jn++) {
                    mma_bf16(acc[im][jn], ah[im], bh[jn]);
                    mma_bf16(acc[im][jn], ah[im], bl[jn]);
                    mma_bf16(acc[im][jn], al[im], bh[jn]);
                }
        }
        __syncthreads();
    }

    int er = lane >> 2, ec = (lane & 3) * 2;
#pragma unroll
    for (int im = 0; im < 4; im++) {
#pragma unroll
        for (int jn = 0; jn < 4; jn++) {
            int row = bm + wm * 64 + im * 16 + er;
            int col = bn + wn * 32 + jn * 8 + ec;
            float v0 = acc[im][jn][0], v1 = acc[im][jn][1];
            float v2 = acc[im][jn][2], v3 = acc[im][jn][3];
            if (MODE == 0) {
                v0 = v0 / (1.f + __expf(-v0));
                v1 = v1 / (1.f + __expf(-v1));
                v2 = v2 / (1.f + __expf(-v2));
                v3 = v3 / (1.f + __expf(-v3));
                uint32_t h01, l01, h23, l23;
                split2(v0, v1, h01, l01);
                split2(v2, v3, h23, l23);
                *(uint32_t*)(Chi + (size_t)row * EE + col) = h01;
                *(uint32_t*)(Clo + (size_t)row * EE + col) = l01;
                *(uint32_t*)(Chi + (size_t)(row + 8) * EE + col) = h23;
                *(uint32_t*)(Clo + (size_t)(row + 8) * EE + col) = l23;
            } else {
                *(float2*)(Cm + (size_t)row * EE + col) = make_float2(v0, v1);
                *(float2*)(Cm + (size_t)(row + 8) * EE + col) = make_float2(v2, v3);
            }
        }
    }
}

// ======================= mm_g1: t16 = x @ Wg1 (tensor core) ==============
#define G1RB 776
// smem (bf16 elems): Bh 0, Bl 12416, Ah 24832, Al 34048, end 43264
__global__ __launch_bounds__(256) void mm_g1() {
    extern __shared__ __nv_bfloat16 sg[];
    __nv_bfloat16* Bh = sg;
    __nv_bfloat16* Bl = sg + 12416;
    __nv_bfloat16* Ah = sg + 24832;
    __nv_bfloat16* Al = sg + 34048;
    uint32_t sbase = smem_u32(sg);

    int tid = threadIdx.x, wid = tid >> 5, lane = tid & 31;
    int bm = blockIdx.x * 128;

    for (int i = tid; i < 16 * 96; i += 256) {
        int r = i / 96, c8 = (i % 96) * 8;
        *(uint4*)(Bh + r * G1RB + c8) = *(const uint4*)(g_g1thi + r * EE + c8);
        *(uint4*)(Bl + r * G1RB + c8) = *(const uint4*)(g_g1tlo + r * EE + c8);
    }

    float acc[2][4];
#pragma unroll
    for (int j = 0; j < 2; j++)
#pragma unroll
        for (int e = 0; e < 4; e++) acc[j][e] = 0.f;

    int a_r = lane & 15, a_k = (lane >> 4) << 3;
    int b_r = lane & 7, b_k = ((lane >> 3) & 1) << 3;

    for (int kt = 0; kt < 12; kt++) {
        __syncthreads();
        for (int i = tid; i < 1024; i += 256) {
            int p = i >> 3, c = i & 7;
            size_t go = (size_t)(bm + p) * EE + kt * 64 + c * 8;
            *(uint4*)(Ah + p * 72 + c * 8) = *(const uint4*)(g_xhi + go);
            *(uint4*)(Al + p * 72 + c * 8) = *(const uint4*)(g_xlo + go);
        }
        __syncthreads();
#pragma unroll
        for (int ks = 0; ks < 4; ks++) {
            int kk = ks * 16;
            uint32_t ah[4], al[4];
            int row = wid * 16 + a_r;
            uint32_t offa = (uint32_t)(24832 + row * 72 + kk + a_k) * 2;
            ldsm4(ah[0], ah[1], ah[2], ah[3], sbase + offa);
            ldsm4(al[0], al[1], al[2], al[3], sbase + offa + 9216 * 2);
#pragma unroll
            for (int jn = 0; jn < 2; jn++) {
                int nrow = jn * 8 + b_r;
                uint32_t offb = (uint32_t)(nrow * G1RB + kt * 64 + kk + b_k) * 2;
                uint32_t bh[2], bl[2];
                ldsm2(bh[0], bh[1], sbase + offb);
                ldsm2(bl[0], bl[1], sbase + offb + 12416 * 2);
                mma_bf16(acc[jn], ah, bh);
                mma_bf16(acc[jn], ah, bl);
                mma_bf16(acc[jn], al, bh);
            }
        }
    }
    int er = lane >> 2, ec = (lane & 3) * 2;
#pragma unroll
    for (int jn = 0; jn < 2; jn++) {
        int row = bm + wid * 16 + er;
        int col = jn * 8 + ec;
        *(float2*)(g_t16 + (size_t)row * GG + col) = make_float2(acc[jn][0], acc[jn][1]);
        *(float2*)(g_t16 + (size_t)(row + 8) * GG + col) = make_float2(acc[jn][2], acc[jn][3]);
    }
}

// ======================= attention pass A (intra-chunk, mma) =============
// smem layout (bf16 elems):
//  QH 0, QL 9216, KH 18432, KL 27648            (stride 72, [128][64])
//  VTH 36864, VTL 45568, KWH 54272, KWL 62976   (stride 136, [64][128])
//  AH 71680, AL 89088                           (stride 136, [128][128])
//  dtab (float) at elem 106496
#define O_QH 0
#define O_QL 9216
#define O_KH 18432
#define O_KL 27648
#define O_VTH 36864
#define O_VTL 45568
#define O_KWH 54272
#define O_KWL 62976
#define O_AH 71680
#define O_AL 89088
#define O_END 106496
#define RQ 72
#define RT 136

__global__ __launch_bounds__(256) void attn_intra_k(const float* __restrict__ lam) {
    extern __shared__ __align__(16) __nv_bfloat16 sb16[];
    float* dtab = (float*)(sb16 + O_END);
    uint32_t sbase = smem_u32(sb16);

    int tid = threadIdx.x, wid = tid >> 5, lane = tid & 31;
    int wm = wid & 1, wn = wid >> 1;
    int chunk = blockIdx.x, bh = blockIdx.y;
    int b = bh / HH, h = bh % HH;
    float lambda = lam[h];
    int n0 = chunk * CC;

    for (int i = tid; i <= CC; i += 256) dtab[i] = __expf(lambda * (float)i);

    // load Q, K (natural layout)
    for (int i = tid; i < 2048; i += 256) {
        int p = i >> 4, d4 = (i & 15) * 4;
        size_t gb = (size_t)(b * NSEQ + n0 + p) * EE + h * DD + d4;
        *(uint2*)(sb16 + O_QH + p * RQ + d4) = *(const uint2*)(g_qhi + gb);
        *(uint2*)(sb16 + O_QL + p * RQ + d4) = *(const uint2*)(g_qlo + gb);
        *(uint2*)(sb16 + O_KH + p * RQ + d4) = *(const uint2*)(g_khi + gb);
        *(uint2*)(sb16 + O_KL + p * RQ + d4) = *(const uint2*)(g_klo + gb);
    }
    // V transposed + weighted-K transposed
    for (int i = tid; i < 8192; i += 256) {
        int d = i & 63, p = i >> 6;
        size_t gb = (size_t)(b * NSEQ + n0 + p) * EE + h * DD + d;
        sb16[O_VTH + d * RT + p] = g_vhi[gb];
        sb16[O_VTL + d * RT + p] = g_vlo[gb];
        float kv = __bfloat162float(g_khi[gb]) + __bfloat162float(g_klo[gb]);
        float w = __expf(lambda * (float)(CC - p));
        __nv_bfloat16 hk, lk;
        split_bf16(kv * w, hk, lk);
        sb16[O_KWH + d * RT + p] = hk;
        sb16[O_KWL + d * RT + p] = lk;
    }
    __syncthreads();

    int a_r = lane & 15, a_k = (lane >> 4) << 3;
    int b_r = lane & 7, b_k = ((lane >> 3) & 1) << 3;
    int er = lane >> 2, ec = (lane & 3) * 2;

    // ---- phase 1: S = Q @ K^T (128x128, k=64) ----
    {
        float accS[4][4][4];
#pragma unroll
        for (int i = 0; i < 4; i++)
#pragma unroll
            for (int j = 0; j < 4; j++)
#pragma unroll
                for (int e = 0; e < 4; e++) accS[i][j][e] = 0.f;

#pragma unroll
        for (int ks = 0; ks < 4; ks++) {
            int kk = ks * 16;
            uint32_t qh[4][4], ql[4][4];
#pragma unroll
            for (int im = 0; im < 4; im++) {
                int row = wm * 64 + im * 16 + a_r;
                uint32_t off = (uint32_t)(row * RQ + kk + a_k) * 2;
                ldsm4(qh[im][0], qh[im][1], qh[im][2], qh[im][3],
                      sbase + O_QH * 2 + off);
                ldsm4(ql[im][0], ql[im][1], ql[im][2], ql[im][3],
                      sbase + O_QL * 2 + off);
            }
            uint32_t kh[4][2], kl[4][2];
#pragma unroll
            for (int jn = 0; jn < 4; jn++) {
                int nrow = wn * 32 + jn * 8 + b_r;
                uint32_t off = (uint32_t)(nrow * RQ + kk + b_k) * 2;
                ldsm2(kh[jn][0], kh[jn][1], sbase + O_KH * 2 + off);
                ldsm2(kl[jn][0], kl[jn][1], sbase + O_KL * 2 + off);
            }
#pragma unroll
            for (int im = 0; im < 4; im++)
#pragma unroll
                for (int jn = 0; jn < 4; jn++) {
                    mma_bf16(accS[im][jn], qh[im], kh[jn]);
                    mma_bf16(accS[im][jn], qh[im], kl[jn]);
                    mma_bf16(accS[im][jn], ql[im], kh[jn]);
                }
        }
        // decay + split + store to A
#pragma unroll
        for (int im = 0; im < 4; im++)
#pragma unroll
            for (int jn = 0; jn < 4; jn++) {
                int p0 = wm * 64 + im * 16 + er;
                int j0 = wn * 32 + jn * 8 + ec;
                int dj = p0 - j0;
                float v0 = (dj >= 0)     ? accS[im][jn][0] * dtab[dj] : 0.f;
                float v1 = (dj - 1 >= 0) ? accS[im][jn][1] * dtab[dj - 1] : 0.f;
                float v2 = (dj + 8 >= 0) ? accS[im][jn][2] * dtab[dj + 8] : 0.f;
                float v3 = (dj + 7 >= 0) ? accS[im][jn][3] * dtab[dj + 7] : 0.f;
                uint32_t h01, l01, h23, l23;
                split2(v0, v1, h01, l01);
                split2(v2, v3, h23, l23);
                *(uint32_t*)(sb16 + O_AH + p0 * RT + j0) = h01;
                *(uint32_t*)(sb16 + O_AL + p0 * RT + j0) = l01;
                *(uint32_t*)(sb16 + O_AH + (p0 + 8) * RT + j0) = h23;
                *(uint32_t*)(sb16 + O_AL + (p0 + 8) * RT + j0) = l23;
            }
    }
    __syncthreads();

    // ---- phase 2: O = A @ V (128x64, k=128) ----
    {
        float accO[4][2][4];
#pragma unroll
        for (int i = 0; i < 4; i++)
#pragma unroll
            for (int j = 0; j < 2; j++)
#pragma unroll
                for (int e = 0; e < 4; e++) accO[i][j][e] = 0.f;

#pragma unroll
        for (int ks = 0; ks < 8; ks++) {
            int kk = ks * 16;
            uint32_t ah[4][4], al4[4][4];
#pragma unroll
            for (int im = 0; im < 4; im++) {
                int row = wm * 64 + im * 16 + a_r;
                uint32_t off = (uint32_t)(row * RT + kk + a_k) * 2;
                ldsm4(ah[im][0], ah[im][1], ah[im][2], ah[im][3],
                      sbase + O_AH * 2 + off);
                ldsm4(al4[im][0], al4[im][1], al4[im][2], al4[im][3],
                      sbase + O_AL * 2 + off);
            }
            uint32_t vh[2][2], vl[2][2];
#pragma unroll
            for (int jn = 0; jn < 2; jn++) {
                int nrow = wn * 16 + jn * 8 + b_r;
                uint32_t off = (uint32_t)(nrow * RT + kk + b_k) * 2;
                ldsm2(vh[jn][0], vh[jn][1], sbase + O_VTH * 2 + off);
                ldsm2(vl[jn][0], vl[jn][1], sbase + O_VTL * 2 + off);
            }
#pragma unroll
            for (int im = 0; im < 4; im++)
#pragma unroll
                for (int jn = 0; jn < 2; jn++) {
                    mma_bf16(accO[im][jn], ah[im], vh[jn]);
                    mma_bf16(accO[im][jn], ah[im], vl[jn]);
                    mma_bf16(accO[im][jn], al4[im], vh[jn]);
                }
        }
#pragma unroll
        for (int im = 0; im < 4; im++)
#pragma unroll
            for (int jn = 0; jn < 2; jn++) {
                int p0 = wm * 64 + im * 16 + er;
                int col = wn * 16 + jn * 8 + ec;
                size_t gb = (size_t)(b * NSEQ + n0 + p0) * EE + h * DD + col;
                *(float2*)(g_attn + gb) = make_float2(accO[im][jn][0], accO[im][jn][1]);
                *(float2*)(g_attn + gb + (size_t)8 * EE) =
                    make_float2(accO[im][jn][2], accO[im][jn][3]);
            }
    }

    // ---- phase 3: T = Kw^T @ V (64x64, k=128) ----
    {
        float accT[2][2][4];
#pragma unroll
        for (int i = 0; i < 2; i++)
#pragma unroll
            for (int j = 0; j < 2; j++)
#pragma unroll
                for (int e = 0; e < 4; e++) accT[i][j][e] = 0.f;

#pragma unroll
        for (int ks = 0; ks < 8; ks++) {
            int kk = ks * 16;
            uint32_t kwh[2][4], kwl[2][4];
#pragma unroll
            for (int im = 0; im < 2; im++) {
                int row = wm * 32 + im * 16 + a_r;
                uint32_t off = (uint32_t)(row * RT + kk + a_k) * 2;
                ldsm4(kwh[im][0], kwh[im][1], kwh[im][2], kwh[im][3],
                      sbase + O_KWH * 2 + off);
                ldsm4(kwl[im][0], kwl[im][1], kwl[im][2], kwl[im][3],
                      sbase + O_KWL * 2 + off);
            }
            uint32_t vh[2][2], vl[2][2];
#pragma unroll
            for (int jn = 0; jn < 2; jn++) {
                int nrow = wn * 16 + jn * 8 + b_r;
                uint32_t off = (uint32_t)(nrow * RT + kk + b_k) * 2;
                ldsm2(vh[jn][0], vh[jn][1], sbase + O_VTH * 2 + off);
                ldsm2(vl[jn][0], vl[jn][1], sbase + O_VTL * 2 + off);
            }
#pragma unroll
            for (int im = 0; im < 2; im++)
#pragma unroll
                for (int jn = 0; jn < 2; jn++) {
                    mma_bf16(accT[im][jn], kwh[im], vh[jn]);
                    mma_bf16(accT[im][jn], kwh[im], vl[jn]);
                    mma_bf16(accT[im][jn], kwl[im], vh[jn]);
                }
        }
        size_t tb = ((size_t)bh * NCH + chunk) * DD * DD;
#pragma unroll
        for (int im = 0; im < 2; im++)
#pragma unroll
            for (int jn = 0; jn < 2; jn++) {
                int dk = wm * 32 + im * 16 + er;
                int dv = wn * 16 + jn * 8 + ec;
                *(float2*)(g_T + tb + dk * DD + dv) =
                    make_float2(accT[im][jn][0], accT[im][jn][1]);
                *(float2*)(g_T + tb + (dk + 8) * DD + dv) =
                    make_float2(accT[im][jn][2], accT[im][jn][3]);
            }
    }
}

// ======================= pass B: chunk-state scan ========================
__global__ __launch_bounds__(256) void scan_k(const float* __restrict__ lam) {
    int bh = blockIdx.x;
    int h = bh % HH;
    float gamma = __expf(lam[h] * (float)CC);
    size_t base = (size_t)bh * NCH * DD * DD;
    for (int e = threadIdx.x; e < DD * DD; e += blockDim.x) {
        float s = 0.f;
#pragma unroll
        for (int t = 0; t < NCH; t++) {
            g_S[base + t * DD * DD + e] = s;
            s = gamma * s + g_T[base + t * DD * DD + e];
        }
    }
}

// ======================= pass C: inter-chunk + gate fuse + bf16 out ======
__global__ __launch_bounds__(256) void attn_inter_k(const float* __restrict__ lam,
                                                    const float* __restrict__ Wg2) {
    extern __shared__ __align__(16) float sm2[];
    float* Qs = sm2;                  // 128*64
    float* Ss = Qs + 128 * 64;        // 64*64
    float* ep = Ss + 64 * 64;         // 128
    float* t16s = ep + 128;           // 128*16
    float* wg2s = t16s + 128 * 16;    // 16*64

    int tid = threadIdx.x;
    int chunk = blockIdx.x;
    int bh = blockIdx.y;
    int b = bh / HH, h = bh % HH;
    float lambda = lam[h];
    int n0 = chunk * CC;

    for (int i = tid; i < 128; i += 256) ep[i] = __expf(lambda * (float)i);

    for (int idx = tid; idx < 128 * 16; idx += 256) {
        int p = idx >> 4;
        int d4 = (idx & 15) * 4;
        size_t gb = (size_t)(b * NSEQ + n0 + p) * EE + h * DD + d4;
        uint2 hh = *(const uint2*)(g_qhi + gb);
        uint2 ll = *(const uint2*)(g_qlo + gb);
        __nv_bfloat16* hp = (__nv_bfloat16*)&hh;
        __nv_bfloat16* lp = (__nv_bfloat16*)&ll;
#pragma unroll
        for (int e = 0; e < 4; e++)
            Qs[p * 64 + d4 + e] = __bfloat162float(hp[e]) + __bfloat162float(lp[e]);
    }
    size_t sbo = ((size_t)bh * NCH + chunk) * DD * DD;
    for (int idx = tid; idx < 64 * 16; idx += 256)
        *(float4*)(&Ss[idx * 4]) = *(const float4*)(g_S + sbo + idx * 4);
    for (int i = tid; i < 512; i += 256)
        *(float4*)(t16s + i * 4) =
            *(const float4*)(g_t16 + (size_t)(b * NSEQ + n0) * GG + i * 4);
    for (int i = tid; i < 256; i += 256) {
        int g = i >> 4, c4 = (i & 15) * 4;
        *(float4*)(wg2s + g * 64 + c4) = *(const float4*)(Wg2 + g * EE + h * DD + c4);
    }
    __syncthreads();

    int ty = tid >> 4, tx = tid & 15;
    float o[8][4];
#pragma unroll
    for (int i = 0; i < 8; i++)
#pragma unroll
        for (int j = 0; j < 4; j++) o[i][j] = 0.f;
    for (int kd = 0; kd < 64; kd++) {
        float sv[4];
#pragma unroll
        for (int j = 0; j < 4; j++) sv[j] = Ss[kd * 64 + tx + 16 * j];
#pragma unroll
        for (int i = 0; i < 8; i++) {
            float q = Qs[(ty + 16 * i) * 64 + kd];
#pragma unroll
            for (int j = 0; j < 4; j++) o[i][j] += q * sv[j];
        }
    }
#pragma unroll
    for (int i = 0; i < 8; i++) {
        int p = ty + 16 * i;
        float e = ep[p];
        size_t gb = (size_t)(b * NSEQ + n0 + p) * EE + h * DD;
#pragma unroll
        for (int j = 0; j < 4; j++) {
            int c = tx + 16 * j;
            float s = 0.f;
#pragma unroll
            for (int g = 0; g < 16; g++) s += t16s[p * 16 + g] * wg2s[g * 64 + c];
            float gate = 1.f / (1.f + __expf(-s));
            size_t gi = gb + c;
            float val = (g_attn[gi] + e * o[i][j]) * gate;
            __nv_bfloat16 hv, lv;
            split_bf16(val, hv, lv);
            g_ahi[gi] = hv;
            g_alo[gi] = lv;
        }
    }
}

// ======================= LayerNorm =======================================
__global__ __launch_bounds__(256) void ln_k(const float* __restrict__ w,
                                            const float* __restrict__ bias,
                                            float* __restrict__ out) {
    int row = blockIdx.x;
    int t = threadIdx.x;
    const float* yr = g_y + (size_t)row * EE;
    float v0 = yr[t], v1 = yr[t + 256], v2 = yr[t + 512];

    __shared__ float red[32];
    float s = v0 + v1 + v2;
#pragma unroll
    for (int off = 16; off > 0; off >>= 1) s += __shfl_down_sync(0xffffffffu, s, off);
    if ((t & 31) == 0) red[t >> 5] = s;
    __syncthreads();
    if (t < 32) {
        float x = (t < 8) ? red[t] : 0.f;
#pragma unroll
        for (int off = 4; off > 0; off >>= 1) x += __shfl_down_sync(0xffffffffu, x, off);
        if (t == 0) red[0] = x;
    }
    __syncthreads();
    float mu = red[0] * (1.f / 768.f);
    __syncthreads();

    float d0 = v0 - mu, d1 = v1 - mu, d2 = v2 - mu;
    float s2 = d0 * d0 + d1 * d1 + d2 * d2;
#pragma unroll
    for (int off = 16; off > 0; off >>= 1) s2 += __shfl_down_sync(0xffffffffu, s2, off);
    if ((t & 31) == 0) red[t >> 5] = s2;
    __syncthreads();
    if (t < 32) {
        float x = (t < 8) ? red[t] : 0.f;
#pragma unroll
        for (int off = 4; off > 0; off >>= 1) x += __shfl_down_sync(0xffffffffu, x, off);
        if (t == 0) red[0] = x;
    }
    __syncthreads();
    float var = red[0] * (1.f / 768.f);
    float rs = rsqrtf(var + 1e-5f);

    size_t ob = (size_t)row * EE;
    out[ob + t]       = d0 * rs * w[t]       + bias[t];
    out[ob + t + 256] = d1 * rs * w[t + 256] + bias[t + 256];
    out[ob + t + 512] = d2 * rs * w[t + 512] + bias[t + 512];
}

// =========================================================================
extern "C" void kernel_launch(void* const* d_in, const int* in_sizes, int n_in,
                              void* d_out, int out_size) {
    (void)in_sizes; (void)n_in; (void)out_size;
    const float* x         = (const float*)d_in[0];
    const float* log_slope = (const float*)d_in[1];
    const float* Wq        = (const float*)d_in[2];
    const float* Wk        = (const float*)d_in[3];
    const float* Wv        = (const float*)d_in[4];
    const float* Wo        = (const float*)d_in[5];
    const float* Wg1       = (const float*)d_in[6];
    const float* Wg2       = (const float*)d_in[7];
    const float* ln_w      = (const float*)d_in[8];
    const float* ln_b      = (const float*)d_in[9];
    float* out = (float*)d_out;

    int smMM = 2 * STAGE;   // 80 KB
    cudaFuncSetAttribute(mm_tc<0>, cudaFuncAttributeMaxDynamicSharedMemorySize, smMM);
    cudaFuncSetAttribute(mm_tc<1>, cudaFuncAttributeMaxDynamicSharedMemorySize, smMM);
    int smA = O_END * 2 + 132 * 4;   // ~213.5 KB
    cudaFuncSetAttribute(attn_intra_k, cudaFuncAttributeMaxDynamicSharedMemorySize, smA);
    int smG1 = 43264 * 2;            // ~86.5 KB
    cudaFuncSetAttribute(mm_g1, cudaFuncAttributeMaxDynamicSharedMemorySize, smG1);
    int smC = (128 * 64 + 64 * 64 + 128 + 128 * 16 + 16 * 64) * (int)sizeof(float);
    cudaFuncSetAttribute(attn_inter_k, cudaFuncAttributeMaxDynamicSharedMemorySize, smC);

    conv_x_k<<<MTOT * EE / 1024, 256>>>(x);
    conv_w_k<<<dim3(EE / 32, EE / 32, 4), 256>>>(Wq, Wk, Wv, Wo);
    convg1_k<<<GG * EE / 256, 256>>>(Wg1);
    mm_tc<0><<<dim3(EE / 128, MTOT / 128, 3), 256, smMM>>>();   // q,k,v (bf16 split out)
    mm_g1<<<MTOT / 128, 256, smG1>>>();
    attn_intra_k<<<dim3(NCH, BHH), 256, smA>>>(log_slope);
    scan_k<<<BHH, 256>>>(log_slope);
    attn_inter_k<<<dim3(NCH, BHH), 256, smC>>>(log_slope, Wg2);
    mm_tc<1><<<dim3(EE / 128, MTOT / 128, 1), 256, smMM>>>();   // y = gated @ Wo
    ln_k<<<MTOT, 256>>>(ln_w, ln_b, out);
}

// round 5
// speedup vs baseline: 2.1229x; 1.0806x over previous
#include <cuda_runtime.h>
#include <cuda_bf16.h>
#include <cstdint>

// Problem constants
#define BB    2
#define NSEQ  2048
#define EE    768
#define HH    12
#define DD    64
#define GG    16
#define CC    128
#define NCH   (NSEQ / CC)         // 16
#define BHH   (BB * HH)           // 24
#define MTOT  (BB * NSEQ)         // 4096

// ---------------- device scratch ----------------
__device__ float g_attn[MTOT * EE];
__device__ float g_y[MTOT * EE];
__device__ float g_t16[MTOT * GG];
__device__ float g_T[BHH * NCH * DD * DD];
__device__ float g_S[BHH * NCH * DD * DD];

__device__ __nv_bfloat16 g_xhi[MTOT * EE];
__device__ __nv_bfloat16 g_xlo[MTOT * EE];
__device__ __nv_bfloat16 g_ahi[MTOT * EE];
__device__ __nv_bfloat16 g_alo[MTOT * EE];
__device__ __nv_bfloat16 g_qhi[MTOT * EE];
__device__ __nv_bfloat16 g_qlo[MTOT * EE];
__device__ __nv_bfloat16 g_khi[MTOT * EE];
__device__ __nv_bfloat16 g_klo[MTOT * EE];
__device__ __nv_bfloat16 g_vhi[MTOT * EE];
__device__ __nv_bfloat16 g_vlo[MTOT * EE];
__device__ __nv_bfloat16 g_wthi[4 * EE * EE];
__device__ __nv_bfloat16 g_wtlo[4 * EE * EE];
__device__ __nv_bfloat16 g_g1thi[GG * EE];
__device__ __nv_bfloat16 g_g1tlo[GG * EE];

// ======================= helpers ==========================
__device__ __forceinline__ uint32_t smem_u32(const void* p) {
    uint32_t a;
    asm("{ .reg .u64 t; cvta.to.shared.u64 t, %1; cvt.u32.u64 %0, t; }"
        : "=r"(a) : "l"(p));
    return a;
}
__device__ __forceinline__ void cp_async16(uint32_t s, const void* g) {
    asm volatile("cp.async.cg.shared.global [%0], [%1], 16;" :: "r"(s), "l"(g));
}
__device__ __forceinline__ void cp_commit() {
    asm volatile("cp.async.commit_group;");
}
template <int N>
__device__ __forceinline__ void cp_wait() {
    asm volatile("cp.async.wait_group %0;" :: "n"(N));
}
__device__ __forceinline__ void ldsm4(uint32_t& r0, uint32_t& r1, uint32_t& r2,
                                      uint32_t& r3, uint32_t a) {
    asm volatile("ldmatrix.sync.aligned.m8n8.x4.shared.b16 {%0,%1,%2,%3}, [%4];"
                 : "=r"(r0), "=r"(r1), "=r"(r2), "=r"(r3) : "r"(a));
}
__device__ __forceinline__ void ldsm2(uint32_t& r0, uint32_t& r1, uint32_t a) {
    asm volatile("ldmatrix.sync.aligned.m8n8.x2.shared.b16 {%0,%1}, [%2];"
                 : "=r"(r0), "=r"(r1) : "r"(a));
}
__device__ __forceinline__ void mma_bf16(float* c, const uint32_t* a,
                                         const uint32_t* b) {
    asm volatile(
        "mma.sync.aligned.m16n8k16.row.col.f32.bf16.bf16.f32 "
        "{%0,%1,%2,%3}, {%4,%5,%6,%7}, {%8,%9}, {%0,%1,%2,%3};"
        : "+f"(c[0]), "+f"(c[1]), "+f"(c[2]), "+f"(c[3])
        : "r"(a[0]), "r"(a[1]), "r"(a[2]), "r"(a[3]), "r"(b[0]), "r"(b[1]));
}
__device__ __forceinline__ void split_bf16(float v, __nv_bfloat16& h, __nv_bfloat16& l) {
    h = __float2bfloat16(v);
    l = __float2bfloat16(v - __bfloat162float(h));
}
__device__ __forceinline__ void split2(float a, float b, uint32_t& hi, uint32_t& lo) {
    __nv_bfloat16 ha = __float2bfloat16(a), hb = __float2bfloat16(b);
    hi = (uint32_t)*(uint16_t*)&ha | ((uint32_t)*(uint16_t*)&hb << 16);
    float la = a - __bfloat162float(ha), lb = b - __bfloat162float(hb);
    __nv_bfloat16 hla = __float2bfloat16(la), hlb = __float2bfloat16(lb);
    lo = (uint32_t)*(uint16_t*)&hla | ((uint32_t)*(uint16_t*)&hlb << 16);
}

// ======================= conversion kernels ==============================
__global__ __launch_bounds__(256) void conv_x_k(const float* __restrict__ x) {
    size_t i = ((size_t)blockIdx.x * 256 + threadIdx.x) * 4;
    float4 v = *(const float4*)(x + i);
    __align__(8) __nv_bfloat16 hi[4], lo[4];
    split_bf16(v.x, hi[0], lo[0]);
    split_bf16(v.y, hi[1], lo[1]);
    split_bf16(v.z, hi[2], lo[2]);
    split_bf16(v.w, hi[3], lo[3]);
    *(uint2*)(g_xhi + i) = *(uint2*)hi;
    *(uint2*)(g_xlo + i) = *(uint2*)lo;
}

__global__ __launch_bounds__(256) void conv_w_k(const float* __restrict__ Wq,
                                                const float* __restrict__ Wk,
                                                const float* __restrict__ Wv,
                                                const float* __restrict__ Wo) {
    const float* W = (blockIdx.z == 0) ? Wq : (blockIdx.z == 1) ? Wk
                   : (blockIdx.z == 2) ? Wv : Wo;
    __shared__ float t[32][33];
    int tx = threadIdx.x & 31, ty0 = threadIdx.x >> 5;
    int bn = blockIdx.x * 32, bk = blockIdx.y * 32;
#pragma unroll
    for (int r = 0; r < 4; r++) {
        int ty = ty0 + r * 8;
        t[ty][tx] = W[(size_t)(bk + ty) * EE + bn + tx];
    }
    __syncthreads();
    size_t base = (size_t)blockIdx.z * EE * EE;
#pragma unroll
    for (int r = 0; r < 4; r++) {
        int ty = ty0 + r * 8;
        float v = t[tx][ty];
        __nv_bfloat16 h, l;
        split_bf16(v, h, l);
        size_t o = base + (size_t)(bn + ty) * EE + bk + tx;
        g_wthi[o] = h;
        g_wtlo[o] = l;
    }
}

__global__ __launch_bounds__(256) void convg1_k(const float* __restrict__ Wg1) {
    int i = blockIdx.x * 256 + threadIdx.x;
    int n = i / EE, k = i % EE;
    __nv_bfloat16 h, l;
    split_bf16(Wg1[k * GG + n], h, l);
    g_g1thi[i] = h;
    g_g1tlo[i] = l;
}

// ======================= bf16x3 mma.sync GEMM ============================
#define RSTRIDE 40
#define SA_H 0
#define SA_L 10240
#define SB_H 20480
#define SB_L 30720
#define STAGE 40960

template <int MODE>
__global__ __launch_bounds__(256, 2) void mm_tc() {
    extern __shared__ char smem[];
    uint32_t sb = smem_u32(smem);

    int tid = threadIdx.x;
    int wid = tid >> 5, lane = tid & 31;
    int wm = wid & 1, wn = wid >> 1;

    int z = blockIdx.z;
    const __nv_bfloat16 *Ahi, *Alo, *Whi, *Wlo;
    float* Cm = nullptr;
    __nv_bfloat16 *Chi = nullptr, *Clo = nullptr;
    if (MODE == 0) {
        Ahi = g_xhi; Alo = g_xlo;
        Whi = g_wthi + (size_t)z * EE * EE;
        Wlo = g_wtlo + (size_t)z * EE * EE;
        Chi = (z == 0) ? g_qhi : (z == 1) ? g_khi : g_vhi;
        Clo = (z == 0) ? g_qlo : (z == 1) ? g_klo : g_vlo;
    } else {
        Ahi = g_ahi; Alo = g_alo;
        Whi = g_wthi + (size_t)3 * EE * EE;
        Wlo = g_wtlo + (size_t)3 * EE * EE;
        Cm = g_y;
    }
    int bm = blockIdx.y * 128, bn = blockIdx.x * 128;

    float acc[4][4][4];
#pragma unroll
    for (int i = 0; i < 4; i++)
#pragma unroll
        for (int j = 0; j < 4; j++)
#pragma unroll
            for (int e = 0; e < 4; e++) acc[i][j][e] = 0.f;

    int lr0 = tid >> 2;
    int lc = (tid & 3) * 8;

    auto issue = [&](int kt, int buf) {
        int k0 = kt * 32;
        uint32_t st = sb + (uint32_t)buf * STAGE;
#pragma unroll
        for (int rr = 0; rr < 2; rr++) {
            int r = lr0 + rr * 64;
            uint32_t so = (uint32_t)(r * RSTRIDE + lc) * 2;
            size_t ga = (size_t)(bm + r) * EE + k0 + lc;
            size_t gb = (size_t)(bn + r) * EE + k0 + lc;
            cp_async16(st + SA_H + so, Ahi + ga);
            cp_async16(st + SA_L + so, Alo + ga);
            cp_async16(st + SB_H + so, Whi + gb);
            cp_async16(st + SB_L + so, Wlo + gb);
        }
        cp_commit();
    };

    int a_r = lane & 15;
    int a_k = (lane >> 4) << 3;
    int b_r = lane & 7;
    int b_k = ((lane >> 3) & 1) << 3;

    issue(0, 0);
    for (int kt = 0; kt < 24; kt++) {
        int buf = kt & 1;
        if (kt < 23) issue(kt + 1, buf ^ 1);
        if (kt < 23) cp_wait<1>(); else cp_wait<0>();
        __syncthreads();

        uint32_t st = sb + (uint32_t)buf * STAGE;
#pragma unroll
        for (int ks = 0; ks < 2; ks++) {
            int kk = ks * 16;
            // B fragments once per k-slice (16 regs live)
            uint32_t bh[4][2], bl[4][2];
#pragma unroll
            for (int jn = 0; jn < 4; jn++) {
                int nrow = wn * 32 + jn * 8 + b_r;
                uint32_t off = (uint32_t)(nrow * RSTRIDE + kk + b_k) * 2;
                ldsm2(bh[jn][0], bh[jn][1], st + SB_H + off);
                ldsm2(bl[jn][0], bl[jn][1], st + SB_L + off);
            }
            // A fragments per im (8 regs live at a time)
#pragma unroll
            for (int im = 0; im < 4; im++) {
                int row = wm * 64 + im * 16 + a_r;
                uint32_t off = (uint32_t)(row * RSTRIDE + kk + a_k) * 2;
                uint32_t ah[4], al[4];
                ldsm4(ah[0], ah[1], ah[2], ah[3], st + SA_H + off);
                ldsm4(al[0], al[1], al[2], al[3], st + SA_L + off);
#pragma unroll
                for (int jn = 0; jn < 4; jn++) {
                    mma_bf16(acc[im][jn], ah, bh[jn]);
                    mma_bf16(acc[im][jn], ah, bl[jn]);
                    mma_bf16(acc[im][jn], al, bh[jn]);
                }
            }
        }
        __syncthreads();
    }

    int er = lane >> 2, ec = (lane & 3) * 2;
#pragma unroll
    for (int im = 0; im < 4; im++) {
#pragma unroll
        for (int jn = 0; jn < 4; jn++) {
            int row = bm + wm * 64 + im * 16 + er;
            int col = bn + wn * 32 + jn * 8 + ec;
            float v0 = acc[im][jn][0], v1 = acc[im][jn][1];
            float v2 = acc[im][jn][2], v3 = acc[im][jn][3];
            if (MODE == 0) {
                v0 = v0 / (1.f + __expf(-v0));
                v1 = v1 / (1.f + __expf(-v1));
                v2 = v2 / (1.f + __expf(-v2));
                v3 = v3 / (1.f + __expf(-v3));
                uint32_t h01, l01, h23, l23;
                split2(v0, v1, h01, l01);
                split2(v2, v3, h23, l23);
                *(uint32_t*)(Chi + (size_t)row * EE + col) = h01;
                *(uint32_t*)(Clo + (size_t)row * EE + col) = l01;
                *(uint32_t*)(Chi + (size_t)(row + 8) * EE + col) = h23;
                *(uint32_t*)(Clo + (size_t)(row + 8) * EE + col) = l23;
            } else {
                *(float2*)(Cm + (size_t)row * EE + col) = make_float2(v0, v1);
                *(float2*)(Cm + (size_t)(row + 8) * EE + col) = make_float2(v2, v3);
            }
        }
    }
}

// ======================= mm_g1: t16 = x @ Wg1 ============================
#define G1RB 776
__global__ __launch_bounds__(256) void mm_g1() {
    extern __shared__ __nv_bfloat16 sg[];
    __nv_bfloat16* Bh = sg;
    __nv_bfloat16* Bl = sg + 12416;
    __nv_bfloat16* Ah = sg + 24832;
    __nv_bfloat16* Al = sg + 34048;
    uint32_t sbase = smem_u32(sg);

    int tid = threadIdx.x, wid = tid >> 5, lane = tid & 31;
    int bm = blockIdx.x * 128;

    for (int i = tid; i < 16 * 96; i += 256) {
        int r = i / 96, c8 = (i % 96) * 8;
        *(uint4*)(Bh + r * G1RB + c8) = *(const uint4*)(g_g1thi + r * EE + c8);
        *(uint4*)(Bl + r * G1RB + c8) = *(const uint4*)(g_g1tlo + r * EE + c8);
    }

    float acc[2][4];
#pragma unroll
    for (int j = 0; j < 2; j++)
#pragma unroll
        for (int e = 0; e < 4; e++) acc[j][e] = 0.f;

    int a_r = lane & 15, a_k = (lane >> 4) << 3;
    int b_r = lane & 7, b_k = ((lane >> 3) & 1) << 3;

    for (int kt = 0; kt < 12; kt++) {
        __syncthreads();
        for (int i = tid; i < 1024; i += 256) {
            int p = i >> 3, c = i & 7;
            size_t go = (size_t)(bm + p) * EE + kt * 64 + c * 8;
            *(uint4*)(Ah + p * 72 + c * 8) = *(const uint4*)(g_xhi + go);
            *(uint4*)(Al + p * 72 + c * 8) = *(const uint4*)(g_xlo + go);
        }
        __syncthreads();
#pragma unroll
        for (int ks = 0; ks < 4; ks++) {
            int kk = ks * 16;
            uint32_t ah[4], al[4];
            int row = wid * 16 + a_r;
            uint32_t offa = (uint32_t)(24832 + row * 72 + kk + a_k) * 2;
            ldsm4(ah[0], ah[1], ah[2], ah[3], sbase + offa);
            ldsm4(al[0], al[1], al[2], al[3], sbase + offa + 9216 * 2);
#pragma unroll
            for (int jn = 0; jn < 2; jn++) {
                int nrow = jn * 8 + b_r;
                uint32_t offb = (uint32_t)(nrow * G1RB + kt * 64 + kk + b_k) * 2;
                uint32_t bh[2], bl[2];
                ldsm2(bh[0], bh[1], sbase + offb);
                ldsm2(bl[0], bl[1], sbase + offb + 12416 * 2);
                mma_bf16(acc[jn], ah, bh);
                mma_bf16(acc[jn], ah, bl);
                mma_bf16(acc[jn], al, bh);
            }
        }
    }
    int er = lane >> 2, ec = (lane & 3) * 2;
#pragma unroll
    for (int jn = 0; jn < 2; jn++) {
        int row = bm + wid * 16 + er;
        int col = jn * 8 + ec;
        *(float2*)(g_t16 + (size_t)row * GG + col) = make_float2(acc[jn][0], acc[jn][1]);
        *(float2*)(g_t16 + (size_t)(row + 8) * GG + col) = make_float2(acc[jn][2], acc[jn][3]);
    }
}

// ======================= attention pass A (intra-chunk, mma) =============
#define O_QH 0
#define O_QL 9216
#define O_KH 18432
#define O_KL 27648
#define O_VTH 36864
#define O_VTL 45568
#define O_KWH 54272
#define O_KWL 62976
#define O_AH 71680
#define O_AL 89088
#define O_END 106496
#define RQ 72
#define RT 136

__global__ __launch_bounds__(256) void attn_intra_k(const float* __restrict__ lam) {
    extern __shared__ __align__(16) __nv_bfloat16 sb16[];
    float* dtab = (float*)(sb16 + O_END);
    uint32_t sbase = smem_u32(sb16);

    int tid = threadIdx.x, wid = tid >> 5, lane = tid & 31;
    int wm = wid & 1, wn = wid >> 1;
    int chunk = blockIdx.x, bh = blockIdx.y;
    int b = bh / HH, h = bh % HH;
    float lambda = lam[h];
    int n0 = chunk * CC;

    for (int i = tid; i <= CC; i += 256) dtab[i] = __expf(lambda * (float)i);

    for (int i = tid; i < 2048; i += 256) {
        int p = i >> 4, d4 = (i & 15) * 4;
        size_t gb = (size_t)(b * NSEQ + n0 + p) * EE + h * DD + d4;
        *(uint2*)(sb16 + O_QH + p * RQ + d4) = *(const uint2*)(g_qhi + gb);
        *(uint2*)(sb16 + O_QL + p * RQ + d4) = *(const uint2*)(g_qlo + gb);
        *(uint2*)(sb16 + O_KH + p * RQ + d4) = *(const uint2*)(g_khi + gb);
        *(uint2*)(sb16 + O_KL + p * RQ + d4) = *(const uint2*)(g_klo + gb);
    }
    for (int i = tid; i < 8192; i += 256) {
        int d = i & 63, p = i >> 6;
        size_t gb = (size_t)(b * NSEQ + n0 + p) * EE + h * DD + d;
        sb16[O_VTH + d * RT + p] = g_vhi[gb];
        sb16[O_VTL + d * RT + p] = g_vlo[gb];
        float kv = __bfloat162float(g_khi[gb]) + __bfloat162float(g_klo[gb]);
        float w = __expf(lambda * (float)(CC - p));
        __nv_bfloat16 hk, lk;
        split_bf16(kv * w, hk, lk);
        sb16[O_KWH + d * RT + p] = hk;
        sb16[O_KWL + d * RT + p] = lk;
    }
    __syncthreads();

    int a_r = lane & 15, a_k = (lane >> 4) << 3;
    int b_r = lane & 7, b_k = ((lane >> 3) & 1) << 3;
    int er = lane >> 2, ec = (lane & 3) * 2;

    // ---- phase 1: S = Q @ K^T ----
    {
        float accS[4][4][4];
#pragma unroll
        for (int i = 0; i < 4; i++)
#pragma unroll
            for (int j = 0; j < 4; j++)
#pragma unroll
                for (int e = 0; e < 4; e++) accS[i][j][e] = 0.f;

#pragma unroll
        for (int ks = 0; ks < 4; ks++) {
            int kk = ks * 16;
            uint32_t kh[4][2], kl[4][2];
#pragma unroll
            for (int jn = 0; jn < 4; jn++) {
                int nrow = wn * 32 + jn * 8 + b_r;
                uint32_t off = (uint32_t)(nrow * RQ + kk + b_k) * 2;
                ldsm2(kh[jn][0], kh[jn][1], sbase + O_KH * 2 + off);
                ldsm2(kl[jn][0], kl[jn][1], sbase + O_KL * 2 + off);
            }
#pragma unroll
            for (int im = 0; im < 4; im++) {
                int row = wm * 64 + im * 16 + a_r;
                uint32_t off = (uint32_t)(row * RQ + kk + a_k) * 2;
                uint32_t qh[4], ql[4];
                ldsm4(qh[0], qh[1], qh[2], qh[3], sbase + O_QH * 2 + off);
                ldsm4(ql[0], ql[1], ql[2], ql[3], sbase + O_QL * 2 + off);
#pragma unroll
                for (int jn = 0; jn < 4; jn++) {
                    mma_bf16(accS[im][jn], qh, kh[jn]);
                    mma_bf16(accS[im][jn], qh, kl[jn]);
                    mma_bf16(accS[im][jn], ql, kh[jn]);
                }
            }
        }
#pragma unroll
        for (int im = 0; im < 4; im++)
#pragma unroll
            for (int jn = 0; jn < 4; jn++) {
                int p0 = wm * 64 + im * 16 + er;
                int j0 = wn * 32 + jn * 8 + ec;
                int dj = p0 - j0;
                float v0 = (dj >= 0)     ? accS[im][jn][0] * dtab[dj] : 0.f;
                float v1 = (dj - 1 >= 0) ? accS[im][jn][1] * dtab[dj - 1] : 0.f;
                float v2 = (dj + 8 >= 0) ? accS[im][jn][2] * dtab[dj + 8] : 0.f;
                float v3 = (dj + 7 >= 0) ? accS[im][jn][3] * dtab[dj + 7] : 0.f;
                uint32_t h01, l01, h23, l23;
                split2(v0, v1, h01, l01);
                split2(v2, v3, h23, l23);
                *(uint32_t*)(sb16 + O_AH + p0 * RT + j0) = h01;
                *(uint32_t*)(sb16 + O_AL + p0 * RT + j0) = l01;
                *(uint32_t*)(sb16 + O_AH + (p0 + 8) * RT + j0) = h23;
                *(uint32_t*)(sb16 + O_AL + (p0 + 8) * RT + j0) = l23;
            }
    }
    __syncthreads();

    // ---- phase 2: O = A @ V ----
    {
        float accO[4][2][4];
#pragma unroll
        for (int i = 0; i < 4; i++)
#pragma unroll
            for (int j = 0; j < 2; j++)
#pragma unroll
                for (int e = 0; e < 4; e++) accO[i][j][e] = 0.f;

#pragma unroll
        for (int ks = 0; ks < 8; ks++) {
            int kk = ks * 16;
            uint32_t vh[2][2], vl[2][2];
#pragma unroll
            for (int jn = 0; jn < 2; jn++) {
                int nrow = wn * 16 + jn * 8 + b_r;
                uint32_t off = (uint32_t)(nrow * RT + kk + b_k) * 2;
                ldsm2(vh[jn][0], vh[jn][1], sbase + O_VTH * 2 + off);
                ldsm2(vl[jn][0], vl[jn][1], sbase + O_VTL * 2 + off);
            }
#pragma unroll
            for (int im = 0; im < 4; im++) {
                int row = wm * 64 + im * 16 + a_r;
                uint32_t off = (uint32_t)(row * RT + kk + a_k) * 2;
                uint32_t ah[4], al4[4];
                ldsm4(ah[0], ah[1], ah[2], ah[3], sbase + O_AH * 2 + off);
                ldsm4(al4[0], al4[1], al4[2], al4[3], sbase + O_AL * 2 + off);
#pragma unroll
                for (int jn = 0; jn < 2; jn++) {
                    mma_bf16(accO[im][jn], ah, vh[jn]);
                    mma_bf16(accO[im][jn], ah, vl[jn]);
                    mma_bf16(accO[im][jn], al4, vh[jn]);
                }
            }
        }
#pragma unroll
        for (int im = 0; im < 4; im++)
#pragma unroll
            for (int jn = 0; jn < 2; jn++) {
                int p0 = wm * 64 + im * 16 + er;
                int col = wn * 16 + jn * 8 + ec;
                size_t gb = (size_t)(b * NSEQ + n0 + p0) * EE + h * DD + col;
                *(float2*)(g_attn + gb) = make_float2(accO[im][jn][0], accO[im][jn][1]);
                *(float2*)(g_attn + gb + (size_t)8 * EE) =
                    make_float2(accO[im][jn][2], accO[im][jn][3]);
            }
    }

    // ---- phase 3: T = Kw^T @ V ----
    {
        float accT[2][2][4];
#pragma unroll
        for (int i = 0; i < 2; i++)
#pragma unroll
            for (int j = 0; j < 2; j++)
#pragma unroll
                for (int e = 0; e < 4; e++) accT[i][j][e] = 0.f;

#pragma unroll
        for (int ks = 0; ks < 8; ks++) {
            int kk = ks * 16;
            uint32_t vh[2][2], vl[2][2];
#pragma unroll
            for (int jn = 0; jn < 2; jn++) {
                int nrow = wn * 16 + jn * 8 + b_r;
                uint32_t off = (uint32_t)(nrow * RT + kk + b_k) * 2;
                ldsm2(vh[jn][0], vh[jn][1], sbase + O_VTH * 2 + off);
                ldsm2(vl[jn][0], vl[jn][1], sbase + O_VTL * 2 + off);
            }
#pragma unroll
            for (int im = 0; im < 2; im++) {
                int row = wm * 32 + im * 16 + a_r;
                uint32_t off = (uint32_t)(row * RT + kk + a_k) * 2;
                uint32_t kwh[4], kwl[4];
                ldsm4(kwh[0], kwh[1], kwh[2], kwh[3], sbase + O_KWH * 2 + off);
                ldsm4(kwl[0], kwl[1], kwl[2], kwl[3], sbase + O_KWL * 2 + off);
#pragma unroll
                for (int jn = 0; jn < 2; jn++) {
                    mma_bf16(accT[im][jn], kwh, vh[jn]);
                    mma_bf16(accT[im][jn], kwh, vl[jn]);
                    mma_bf16(accT[im][jn], kwl, vh[jn]);
                }
            }
        }
        size_t tb = ((size_t)bh * NCH + chunk) * DD * DD;
#pragma unroll
        for (int im = 0; im < 2; im++)
#pragma unroll
            for (int jn = 0; jn < 2; jn++) {
                int dk = wm * 32 + im * 16 + er;
                int dv = wn * 16 + jn * 8 + ec;
                *(float2*)(g_T + tb + dk * DD + dv) =
                    make_float2(accT[im][jn][0], accT[im][jn][1]);
                *(float2*)(g_T + tb + (dk + 8) * DD + dv) =
                    make_float2(accT[im][jn][2], accT[im][jn][3]);
            }
    }
}

// ======================= pass B: chunk-state scan ========================
__global__ __launch_bounds__(256) void scan_k(const float* __restrict__ lam) {
    int bh = blockIdx.x;
    int h = bh % HH;
    float gamma = __expf(lam[h] * (float)CC);
    size_t base = (size_t)bh * NCH * DD * DD;
    for (int e = threadIdx.x; e < DD * DD; e += blockDim.x) {
        float s = 0.f;
#pragma unroll
        for (int t = 0; t < NCH; t++) {
            g_S[base + t * DD * DD + e] = s;
            s = gamma * s + g_T[base + t * DD * DD + e];
        }
    }
}

// ======================= pass C: inter-chunk + gate fuse + bf16 out ======
__global__ __launch_bounds__(256) void attn_inter_k(const float* __restrict__ lam,
                                                    const float* __restrict__ Wg2) {
    extern __shared__ __align__(16) float sm2[];
    float* Qs = sm2;
    float* Ss = Qs + 128 * 64;
    float* ep = Ss + 64 * 64;
    float* t16s = ep + 128;
    float* wg2s = t16s + 128 * 16;

    int tid = threadIdx.x;
    int chunk = blockIdx.x;
    int bh = blockIdx.y;
    int b = bh / HH, h = bh % HH;
    float lambda = lam[h];
    int n0 = chunk * CC;

    for (int i = tid; i < 128; i += 256) ep[i] = __expf(lambda * (float)i);

    for (int idx = tid; idx < 128 * 16; idx += 256) {
        int p = idx >> 4;
        int d4 = (idx & 15) * 4;
        size_t gb = (size_t)(b * NSEQ + n0 + p) * EE + h * DD + d4;
        uint2 hh = *(const uint2*)(g_qhi + gb);
        uint2 ll = *(const uint2*)(g_qlo + gb);
        __nv_bfloat16* hp = (__nv_bfloat16*)&hh;
        __nv_bfloat16* lp = (__nv_bfloat16*)&ll;
#pragma unroll
        for (int e = 0; e < 4; e++)
            Qs[p * 64 + d4 + e] = __bfloat162float(hp[e]) + __bfloat162float(lp[e]);
    }
    size_t sbo = ((size_t)bh * NCH + chunk) * DD * DD;
    for (int idx = tid; idx < 64 * 16; idx += 256)
        *(float4*)(&Ss[idx * 4]) = *(const float4*)(g_S + sbo + idx * 4);
    for (int i = tid; i < 512; i += 256)
        *(float4*)(t16s + i * 4) =
            *(const float4*)(g_t16 + (size_t)(b * NSEQ + n0) * GG + i * 4);
    for (int i = tid; i < 256; i += 256) {
        int g = i >> 4, c4 = (i & 15) * 4;
        *(float4*)(wg2s + g * 64 + c4) = *(const float4*)(Wg2 + g * EE + h * DD + c4);
    }
    __syncthreads();

    int ty = tid >> 4, tx = tid & 15;
    float o[8][4];
#pragma unroll
    for (int i = 0; i < 8; i++)
#pragma unroll
        for (int j = 0; j < 4; j++) o[i][j] = 0.f;
    for (int kd = 0; kd < 64; kd++) {
        float sv[4];
#pragma unroll
        for (int j = 0; j < 4; j++) sv[j] = Ss[kd * 64 + tx + 16 * j];
#pragma unroll
        for (int i = 0; i < 8; i++) {
            float q = Qs[(ty + 16 * i) * 64 + kd];
#pragma unroll
            for (int j = 0; j < 4; j++) o[i][j] += q * sv[j];
        }
    }
#pragma unroll
    for (int i = 0; i < 8; i++) {
        int p = ty + 16 * i;
        float e = ep[p];
        size_t gb = (size_t)(b * NSEQ + n0 + p) * EE + h * DD;
#pragma unroll
        for (int j = 0; j < 4; j++) {
            int c = tx + 16 * j;
            float s = 0.f;
#pragma unroll
            for (int g = 0; g < 16; g++) s += t16s[p * 16 + g] * wg2s[g * 64 + c];
            float gate = 1.f / (1.f + __expf(-s));
            size_t gi = gb + c;
            float val = (g_attn[gi] + e * o[i][j]) * gate;
            __nv_bfloat16 hv, lv;
            split_bf16(val, hv, lv);
            g_ahi[gi] = hv;
            g_alo[gi] = lv;
        }
    }
}

// ======================= LayerNorm =======================================
__global__ __launch_bounds__(256) void ln_k(const float* __restrict__ w,
                                            const float* __restrict__ bias,
                                            float* __restrict__ out) {
    int row = blockIdx.x;
    int t = threadIdx.x;
    const float* yr = g_y + (size_t)row * EE;
    float v0 = yr[t], v1 = yr[t + 256], v2 = yr[t + 512];

    __shared__ float red[32];
    float s = v0 + v1 + v2;
#pragma unroll
    for (int off = 16; off > 0; off >>= 1) s += __shfl_down_sync(0xffffffffu, s, off);
    if ((t & 31) == 0) red[t >> 5] = s;
    __syncthreads();
    if (t < 32) {
        float x = (t < 8) ? red[t] : 0.f;
#pragma unroll
        for (int off = 4; off > 0; off >>= 1) x += __shfl_down_sync(0xffffffffu, x, off);
        if (t == 0) red[0] = x;
    }
    __syncthreads();
    float mu = red[0] * (1.f / 768.f);
    __syncthreads();

    float d0 = v0 - mu, d1 = v1 - mu, d2 = v2 - mu;
    float s2 = d0 * d0 + d1 * d1 + d2 * d2;
#pragma unroll
    for (int off = 16; off > 0; off >>= 1) s2 += __shfl_down_sync(0xffffffffu, s2, off);
    if ((t & 31) == 0) red[t >> 5] = s2;
    __syncthreads();
    if (t < 32) {
        float x = (t < 8) ? red[t] : 0.f;
#pragma unroll
        for (int off = 4; off > 0; off >>= 1) x += __shfl_down_sync(0xffffffffu, x, off);
        if (t == 0) red[0] = x;
    }
    __syncthreads();
    float var = red[0] * (1.f / 768.f);
    float rs = rsqrtf(var + 1e-5f);

    size_t ob = (size_t)row * EE;
    out[ob + t]       = d0 * rs * w[t]       + bias[t];
    out[ob + t + 256] = d1 * rs * w[t + 256] + bias[t + 256];
    out[ob + t + 512] = d2 * rs * w[t + 512] + bias[t + 512];
}

// =========================================================================
extern "C" void kernel_launch(void* const* d_in, const int* in_sizes, int n_in,
                              void* d_out, int out_size) {
    (void)in_sizes; (void)n_in; (void)out_size;
    const float* x         = (const float*)d_in[0];
    const float* log_slope = (const float*)d_in[1];
    const float* Wq        = (const float*)d_in[2];
    const float* Wk        = (const float*)d_in[3];
    const float* Wv        = (const float*)d_in[4];
    const float* Wo        = (const float*)d_in[5];
    const float* Wg1       = (const float*)d_in[6];
    const float* Wg2       = (const float*)d_in[7];
    const float* ln_w      = (const float*)d_in[8];
    const float* ln_b      = (const float*)d_in[9];
    float* out = (float*)d_out;

    int smMM = 2 * STAGE;   // 80 KB
    cudaFuncSetAttribute(mm_tc<0>, cudaFuncAttributeMaxDynamicSharedMemorySize, smMM);
    cudaFuncSetAttribute(mm_tc<1>, cudaFuncAttributeMaxDynamicSharedMemorySize, smMM);
    int smA = O_END * 2 + 132 * 4;
    cudaFuncSetAttribute(attn_intra_k, cudaFuncAttributeMaxDynamicSharedMemorySize, smA);
    int smG1 = 43264 * 2;
    cudaFuncSetAttribute(mm_g1, cudaFuncAttributeMaxDynamicSharedMemorySize, smG1);
    int smC = (128 * 64 + 64 * 64 + 128 + 128 * 16 + 16 * 64) * (int)sizeof(float);
    cudaFuncSetAttribute(attn_inter_k, cudaFuncAttributeMaxDynamicSharedMemorySize, smC);

    conv_x_k<<<MTOT * EE / 1024, 256>>>(x);
    conv_w_k<<<dim3(EE / 32, EE / 32, 4), 256>>>(Wq, Wk, Wv, Wo);
    convg1_k<<<GG * EE / 256, 256>>>(Wg1);
    mm_tc<0><<<dim3(EE / 128, MTOT / 128, 3), 256, smMM>>>();
    mm_g1<<<MTOT / 128, 256, smG1>>>();
    attn_intra_k<<<dim3(NCH, BHH), 256, smA>>>(log_slope);
    scan_k<<<BHH, 256>>>(log_slope);
    attn_inter_k<<<dim3(NCH, BHH), 256, smC>>>(log_slope, Wg2);
    mm_tc<1><<<dim3(EE / 128, MTOT / 128, 1), 256, smMM>>>();
    ln_k<<<MTOT, 256>>>(ln_w, ln_b, out);
}

// round 6
// speedup vs baseline: 2.2833x; 1.0755x over previous
#include <cuda_runtime.h>
#include <cuda_bf16.h>
#include <cstdint>

// Problem constants
#define BB    2
#define NSEQ  2048
#define EE    768
#define HH    12
#define DD    64
#define GG    16
#define CC    128
#define NCH   (NSEQ / CC)         // 16
#define BHH   (BB * HH)           // 24
#define MTOT  (BB * NSEQ)         // 4096

// ---------------- device scratch ----------------
__device__ float g_attn[MTOT * EE];
__device__ float g_y[MTOT * EE];
__device__ float g_t16[MTOT * GG];
__device__ float g_T[BHH * NCH * DD * DD];
__device__ float g_S[BHH * NCH * DD * DD];

__device__ __nv_bfloat16 g_xhi[MTOT * EE];
__device__ __nv_bfloat16 g_xlo[MTOT * EE];
__device__ __nv_bfloat16 g_ahi[MTOT * EE];
__device__ __nv_bfloat16 g_alo[MTOT * EE];
__device__ __nv_bfloat16 g_qhi[MTOT * EE];
__device__ __nv_bfloat16 g_qlo[MTOT * EE];
__device__ __nv_bfloat16 g_khi[MTOT * EE];
__device__ __nv_bfloat16 g_klo[MTOT * EE];
__device__ __nv_bfloat16 g_vhi[MTOT * EE];
__device__ __nv_bfloat16 g_vlo[MTOT * EE];
__device__ __nv_bfloat16 g_wthi[4 * EE * EE];
__device__ __nv_bfloat16 g_wtlo[4 * EE * EE];
__device__ __nv_bfloat16 g_g1thi[GG * EE];
__device__ __nv_bfloat16 g_g1tlo[GG * EE];

// ======================= helpers ==========================
__device__ __forceinline__ uint32_t smem_u32(const void* p) {
    uint32_t a;
    asm("{ .reg .u64 t; cvta.to.shared.u64 t, %1; cvt.u32.u64 %0, t; }"
        : "=r"(a) : "l"(p));
    return a;
}
__device__ __forceinline__ void cp_async16(uint32_t s, const void* g) {
    asm volatile("cp.async.cg.shared.global [%0], [%1], 16;" :: "r"(s), "l"(g));
}
__device__ __forceinline__ void cp_commit() {
    asm volatile("cp.async.commit_group;");
}
template <int N>
__device__ __forceinline__ void cp_wait() {
    asm volatile("cp.async.wait_group %0;" :: "n"(N));
}
__device__ __forceinline__ void ldsm4(uint32_t& r0, uint32_t& r1, uint32_t& r2,
                                      uint32_t& r3, uint32_t a) {
    asm volatile("ldmatrix.sync.aligned.m8n8.x4.shared.b16 {%0,%1,%2,%3}, [%4];"
                 : "=r"(r0), "=r"(r1), "=r"(r2), "=r"(r3) : "r"(a));
}
__device__ __forceinline__ void ldsm2(uint32_t& r0, uint32_t& r1, uint32_t a) {
    asm volatile("ldmatrix.sync.aligned.m8n8.x2.shared.b16 {%0,%1}, [%2];"
                 : "=r"(r0), "=r"(r1) : "r"(a));
}
__device__ __forceinline__ void mma_bf16(float* c, const uint32_t* a,
                                         const uint32_t* b) {
    asm volatile(
        "mma.sync.aligned.m16n8k16.row.col.f32.bf16.bf16.f32 "
        "{%0,%1,%2,%3}, {%4,%5,%6,%7}, {%8,%9}, {%0,%1,%2,%3};"
        : "+f"(c[0]), "+f"(c[1]), "+f"(c[2]), "+f"(c[3])
        : "r"(a[0]), "r"(a[1]), "r"(a[2]), "r"(a[3]), "r"(b[0]), "r"(b[1]));
}
__device__ __forceinline__ void split_bf16(float v, __nv_bfloat16& h, __nv_bfloat16& l) {
    h = __float2bfloat16(v);
    l = __float2bfloat16(v - __bfloat162float(h));
}
__device__ __forceinline__ void split2(float a, float b, uint32_t& hi, uint32_t& lo) {
    __nv_bfloat16 ha = __float2bfloat16(a), hb = __float2bfloat16(b);
    hi = (uint32_t)*(uint16_t*)&ha | ((uint32_t)*(uint16_t*)&hb << 16);
    float la = a - __bfloat162float(ha), lb = b - __bfloat162float(hb);
    __nv_bfloat16 hla = __float2bfloat16(la), hlb = __float2bfloat16(lb);
    lo = (uint32_t)*(uint16_t*)&hla | ((uint32_t)*(uint16_t*)&hlb << 16);
}
// 64B-row swizzle: rows r, r+2, r+4, r+6 land on distinct 16B quads
__device__ __forceinline__ uint32_t swz64(int r, int cbyte) {
    return (uint32_t)(r * 64 + (cbyte ^ (((r >> 1) & 3) << 4)));
}

// ======================= conversion kernels ==============================
__global__ __launch_bounds__(256) void conv_x_k(const float* __restrict__ x) {
    size_t i = ((size_t)blockIdx.x * 256 + threadIdx.x) * 4;
    float4 v = *(const float4*)(x + i);
    __align__(8) __nv_bfloat16 hi[4], lo[4];
    split_bf16(v.x, hi[0], lo[0]);
    split_bf16(v.y, hi[1], lo[1]);
    split_bf16(v.z, hi[2], lo[2]);
    split_bf16(v.w, hi[3], lo[3]);
    *(uint2*)(g_xhi + i) = *(uint2*)hi;
    *(uint2*)(g_xlo + i) = *(uint2*)lo;
}

__global__ __launch_bounds__(256) void conv_w_k(const float* __restrict__ Wq,
                                                const float* __restrict__ Wk,
                                                const float* __restrict__ Wv,
                                                const float* __restrict__ Wo) {
    const float* W = (blockIdx.z == 0) ? Wq : (blockIdx.z == 1) ? Wk
                   : (blockIdx.z == 2) ? Wv : Wo;
    __shared__ float t[32][33];
    int tx = threadIdx.x & 31, ty0 = threadIdx.x >> 5;
    int bn = blockIdx.x * 32, bk = blockIdx.y * 32;
#pragma unroll
    for (int r = 0; r < 4; r++) {
        int ty = ty0 + r * 8;
        t[ty][tx] = W[(size_t)(bk + ty) * EE + bn + tx];
    }
    __syncthreads();
    size_t base = (size_t)blockIdx.z * EE * EE;
#pragma unroll
    for (int r = 0; r < 4; r++) {
        int ty = ty0 + r * 8;
        float v = t[tx][ty];
        __nv_bfloat16 h, l;
        split_bf16(v, h, l);
        size_t o = base + (size_t)(bn + ty) * EE + bk + tx;
        g_wthi[o] = h;
        g_wtlo[o] = l;
    }
}

__global__ __launch_bounds__(256) void convg1_k(const float* __restrict__ Wg1) {
    int i = blockIdx.x * 256 + threadIdx.x;
    int n = i / EE, k = i % EE;
    __nv_bfloat16 h, l;
    split_bf16(Wg1[k * GG + n], h, l);
    g_g1thi[i] = h;
    g_g1tlo[i] = l;
}

// ======================= bf16x3 mma.sync GEMM ============================
// 3-stage cp.async pipeline, single barrier per K-tile, swizzled 64B rows.
// Per-stage layout (bytes): Ah 0, Al 8192, Bh 16384, Bl 24576; stage 32768.
#define MMSTG 32768
#define MM_AH 0
#define MM_AL 8192
#define MM_BH 16384
#define MM_BL 24576

template <int MODE>
__global__ __launch_bounds__(256, 2) void mm_tc() {
    extern __shared__ char smem[];
    uint32_t sb = smem_u32(smem);

    int tid = threadIdx.x;
    int wid = tid >> 5, lane = tid & 31;
    int wm = wid & 1, wn = wid >> 1;

    int z = blockIdx.z;
    const __nv_bfloat16 *Ahi, *Alo, *Whi, *Wlo;
    float* Cm = nullptr;
    __nv_bfloat16 *Chi = nullptr, *Clo = nullptr;
    if (MODE == 0) {
        Ahi = g_xhi; Alo = g_xlo;
        Whi = g_wthi + (size_t)z * EE * EE;
        Wlo = g_wtlo + (size_t)z * EE * EE;
        Chi = (z == 0) ? g_qhi : (z == 1) ? g_khi : g_vhi;
        Clo = (z == 0) ? g_qlo : (z == 1) ? g_klo : g_vlo;
    } else {
        Ahi = g_ahi; Alo = g_alo;
        Whi = g_wthi + (size_t)3 * EE * EE;
        Wlo = g_wtlo + (size_t)3 * EE * EE;
        Cm = g_y;
    }
    int bm = blockIdx.y * 128, bn = blockIdx.x * 128;

    float acc[4][4][4];
#pragma unroll
    for (int i = 0; i < 4; i++)
#pragma unroll
        for (int j = 0; j < 4; j++)
#pragma unroll
            for (int e = 0; e < 4; e++) acc[i][j][e] = 0.f;

    int lr0 = tid >> 2;            // rows lr0, lr0+64
    int lcb = (tid & 3) * 16;      // 16B chunk within 64B row
    int lce = (tid & 3) * 8;       // element col

    auto issue = [&](int kt, int stg) {
        int k0 = kt * 32;
        uint32_t st = sb + (uint32_t)stg * MMSTG;
#pragma unroll
        for (int rr = 0; rr < 2; rr++) {
            int r = lr0 + rr * 64;
            uint32_t so = swz64(r, lcb);
            size_t ga = (size_t)(bm + r) * EE + k0 + lce;
            size_t gb = (size_t)(bn + r) * EE + k0 + lce;
            cp_async16(st + MM_AH + so, Ahi + ga);
            cp_async16(st + MM_AL + so, Alo + ga);
            cp_async16(st + MM_BH + so, Whi + gb);
            cp_async16(st + MM_BL + so, Wlo + gb);
        }
        cp_commit();
    };

    // ldmatrix lane addressing
    int a_r = lane & 15;                 // A rows 0-15
    int a_kb = ((lane >> 4) & 1) << 4;   // +16B for k upper half
    int bg = lane >> 3;                  // B x4 group 0..3
    int b_r = lane & 7;
    int b_jn = bg >> 1;                  // group -> jn offset (0/1)
    int b_kb = (bg & 1) << 4;            // group -> k offset bytes

    issue(0, 0);
    issue(1, 1);
    int stg = 0;
    for (int kt = 0; kt < 24; kt++) {
        if (kt < 23) cp_wait<1>(); else cp_wait<0>();
        __syncthreads();
        if (kt < 22) {
            int ns = stg + 2;
            if (ns >= 3) ns -= 3;
            issue(kt + 2, ns);
        }
        uint32_t st = sb + (uint32_t)stg * MMSTG;
#pragma unroll
        for (int ks = 0; ks < 2; ks++) {
            int kb = ks * 32;   // k-slice byte base
            // B fragments: 2x ldsm4 per hi/lo covers jn pairs (0,1) and (2,3)
            uint32_t bh[4][2], bl[4][2];
#pragma unroll
            for (int jp = 0; jp < 2; jp++) {
                int nrow = wn * 32 + (jp * 2 + b_jn) * 8 + b_r;
                uint32_t off = swz64(nrow, kb + b_kb);
                ldsm4(bh[jp * 2][0], bh[jp * 2][1], bh[jp * 2 + 1][0],
                      bh[jp * 2 + 1][1], st + MM_BH + off);
                ldsm4(bl[jp * 2][0], bl[jp * 2][1], bl[jp * 2 + 1][0],
                      bl[jp * 2 + 1][1], st + MM_BL + off);
            }
#pragma unroll
            for (int im = 0; im < 4; im++) {
                int row = wm * 64 + im * 16 + a_r;
                uint32_t off = swz64(row, kb + a_kb);
                uint32_t ah[4], al[4];
                ldsm4(ah[0], ah[1], ah[2], ah[3], st + MM_AH + off);
                ldsm4(al[0], al[1], al[2], al[3], st + MM_AL + off);
#pragma unroll
                for (int jn = 0; jn < 4; jn++) {
                    mma_bf16(acc[im][jn], ah, bh[jn]);
                    mma_bf16(acc[im][jn], ah, bl[jn]);
                    mma_bf16(acc[im][jn], al, bh[jn]);
                }
            }
        }
        stg++;
        if (stg == 3) stg = 0;
    }

    int er = lane >> 2, ec = (lane & 3) * 2;
#pragma unroll
    for (int im = 0; im < 4; im++) {
#pragma unroll
        for (int jn = 0; jn < 4; jn++) {
            int row = bm + wm * 64 + im * 16 + er;
            int col = bn + wn * 32 + jn * 8 + ec;
            float v0 = acc[im][jn][0], v1 = acc[im][jn][1];
            float v2 = acc[im][jn][2], v3 = acc[im][jn][3];
            if (MODE == 0) {
                v0 = v0 / (1.f + __expf(-v0));
                v1 = v1 / (1.f + __expf(-v1));
                v2 = v2 / (1.f + __expf(-v2));
                v3 = v3 / (1.f + __expf(-v3));
                uint32_t h01, l01, h23, l23;
                split2(v0, v1, h01, l01);
                split2(v2, v3, h23, l23);
                *(uint32_t*)(Chi + (size_t)row * EE + col) = h01;
                *(uint32_t*)(Clo + (size_t)row * EE + col) = l01;
                *(uint32_t*)(Chi + (size_t)(row + 8) * EE + col) = h23;
                *(uint32_t*)(Clo + (size_t)(row + 8) * EE + col) = l23;
            } else {
                *(float2*)(Cm + (size_t)row * EE + col) = make_float2(v0, v1);
                *(float2*)(Cm + (size_t)(row + 8) * EE + col) = make_float2(v2, v3);
            }
        }
    }
}

// ======================= mm_g1: t16 = x @ Wg1 ============================
#define G1RB 776
__global__ __launch_bounds__(256) void mm_g1() {
    extern __shared__ __nv_bfloat16 sg[];
    __nv_bfloat16* Bh = sg;
    __nv_bfloat16* Bl = sg + 12416;
    __nv_bfloat16* Ah = sg + 24832;
    __nv_bfloat16* Al = sg + 34048;
    uint32_t sbase = smem_u32(sg);

    int tid = threadIdx.x, wid = tid >> 5, lane = tid & 31;
    int bm = blockIdx.x * 128;

    for (int i = tid; i < 16 * 96; i += 256) {
        int r = i / 96, c8 = (i % 96) * 8;
        *(uint4*)(Bh + r * G1RB + c8) = *(const uint4*)(g_g1thi + r * EE + c8);
        *(uint4*)(Bl + r * G1RB + c8) = *(const uint4*)(g_g1tlo + r * EE + c8);
    }

    float acc[2][4];
#pragma unroll
    for (int j = 0; j < 2; j++)
#pragma unroll
        for (int e = 0; e < 4; e++) acc[j][e] = 0.f;

    int a_r = lane & 15, a_k = (lane >> 4) << 3;
    int b_r = lane & 7, b_k = ((lane >> 3) & 1) << 3;

    for (int kt = 0; kt < 12; kt++) {
        __syncthreads();
        for (int i = tid; i < 1024; i += 256) {
            int p = i >> 3, c = i & 7;
            size_t go = (size_t)(bm + p) * EE + kt * 64 + c * 8;
            *(uint4*)(Ah + p * 72 + c * 8) = *(const uint4*)(g_xhi + go);
            *(uint4*)(Al + p * 72 + c * 8) = *(const uint4*)(g_xlo + go);
        }
        __syncthreads();
#pragma unroll
        for (int ks = 0; ks < 4; ks++) {
            int kk = ks * 16;
            uint32_t ah[4], al[4];
            int row = wid * 16 + a_r;
            uint32_t offa = (uint32_t)(24832 + row * 72 + kk + a_k) * 2;
            ldsm4(ah[0], ah[1], ah[2], ah[3], sbase + offa);
            ldsm4(al[0], al[1], al[2], al[3], sbase + offa + 9216 * 2);
#pragma unroll
            for (int jn = 0; jn < 2; jn++) {
                int nrow = jn * 8 + b_r;
                uint32_t offb = (uint32_t)(nrow * G1RB + kt * 64 + kk + b_k) * 2;
                uint32_t bh[2], bl[2];
                ldsm2(bh[0], bh[1], sbase + offb);
                ldsm2(bl[0], bl[1], sbase + offb + 12416 * 2);
                mma_bf16(acc[jn], ah, bh);
                mma_bf16(acc[jn], ah, bl);
                mma_bf16(acc[jn], al, bh);
            }
        }
    }
    int er = lane >> 2, ec = (lane & 3) * 2;
#pragma unroll
    for (int jn = 0; jn < 2; jn++) {
        int row = bm + wid * 16 + er;
        int col = jn * 8 + ec;
        *(float2*)(g_t16 + (size_t)row * GG + col) = make_float2(acc[jn][0], acc[jn][1]);
        *(float2*)(g_t16 + (size_t)(row + 8) * GG + col) = make_float2(acc[jn][2], acc[jn][3]);
    }
}

// ======================= attention pass A (intra-chunk, mma) =============
#define O_QH 0
#define O_QL 9216
#define O_KH 18432
#define O_KL 27648
#define O_VTH 36864
#define O_VTL 45568
#define O_KWH 54272
#define O_KWL 62976
#define O_AH 71680
#define O_AL 89088
#define O_END 106496
#define RQ 72
#define RT 136

__global__ __launch_bounds__(256) void attn_intra_k(const float* __restrict__ lam) {
    extern __shared__ __align__(16) __nv_bfloat16 sb16[];
    float* dtab = (float*)(sb16 + O_END);
    uint32_t sbase = smem_u32(sb16);

    int tid = threadIdx.x, wid = tid >> 5, lane = tid & 31;
    int wm = wid & 1, wn = wid >> 1;
    int chunk = blockIdx.x, bh = blockIdx.y;
    int b = bh / HH, h = bh % HH;
    float lambda = lam[h];
    int n0 = chunk * CC;

    for (int i = tid; i <= CC; i += 256) dtab[i] = __expf(lambda * (float)i);

    for (int i = tid; i < 2048; i += 256) {
        int p = i >> 4, d4 = (i & 15) * 4;
        size_t gb = (size_t)(b * NSEQ + n0 + p) * EE + h * DD + d4;
        *(uint2*)(sb16 + O_QH + p * RQ + d4) = *(const uint2*)(g_qhi + gb);
        *(uint2*)(sb16 + O_QL + p * RQ + d4) = *(const uint2*)(g_qlo + gb);
        *(uint2*)(sb16 + O_KH + p * RQ + d4) = *(const uint2*)(g_khi + gb);
        *(uint2*)(sb16 + O_KL + p * RQ + d4) = *(const uint2*)(g_klo + gb);
    }
    for (int i = tid; i < 8192; i += 256) {
        int d = i & 63, p = i >> 6;
        size_t gb = (size_t)(b * NSEQ + n0 + p) * EE + h * DD + d;
        sb16[O_VTH + d * RT + p] = g_vhi[gb];
        sb16[O_VTL + d * RT + p] = g_vlo[gb];
        float kv = __bfloat162float(g_khi[gb]) + __bfloat162float(g_klo[gb]);
        float w = __expf(lambda * (float)(CC - p));
        __nv_bfloat16 hk, lk;
        split_bf16(kv * w, hk, lk);
        sb16[O_KWH + d * RT + p] = hk;
        sb16[O_KWL + d * RT + p] = lk;
    }
    __syncthreads();

    int a_r = lane & 15, a_k = (lane >> 4) << 3;
    int b_r = lane & 7, b_k = ((lane >> 3) & 1) << 3;
    int er = lane >> 2, ec = (lane & 3) * 2;

    // ---- phase 1: S = Q @ K^T ----
    {
        float accS[4][4][4];
#pragma unroll
        for (int i = 0; i < 4; i++)
#pragma unroll
            for (int j = 0; j < 4; j++)
#pragma unroll
                for (int e = 0; e < 4; e++) accS[i][j][e] = 0.f;

#pragma unroll
        for (int ks = 0; ks < 4; ks++) {
            int kk = ks * 16;
            uint32_t kh[4][2], kl[4][2];
#pragma unroll
            for (int jn = 0; jn < 4; jn++) {
                int nrow = wn * 32 + jn * 8 + b_r;
                uint32_t off = (uint32_t)(nrow * RQ + kk + b_k) * 2;
                ldsm2(kh[jn][0], kh[jn][1], sbase + O_KH * 2 + off);
                ldsm2(kl[jn][0], kl[jn][1], sbase + O_KL * 2 + off);
            }
#pragma unroll
            for (int im = 0; im < 4; im++) {
                int row = wm * 64 + im * 16 + a_r;
                uint32_t off = (uint32_t)(row * RQ + kk + a_k) * 2;
                uint32_t qh[4], ql[4];
                ldsm4(qh[0], qh[1], qh[2], qh[3], sbase + O_QH * 2 + off);
                ldsm4(ql[0], ql[1], ql[2], ql[3], sbase + O_QL * 2 + off);
#pragma unroll
                for (int jn = 0; jn < 4; jn++) {
                    mma_bf16(accS[im][jn], qh, kh[jn]);
                    mma_bf16(accS[im][jn], qh, kl[jn]);
                    mma_bf16(accS[im][jn], ql, kh[jn]);
                }
            }
        }
#pragma unroll
        for (int im = 0; im < 4; im++)
#pragma unroll
            for (int jn = 0; jn < 4; jn++) {
                int p0 = wm * 64 + im * 16 + er;
                int j0 = wn * 32 + jn * 8 + ec;
                int dj = p0 - j0;
                float v0 = (dj >= 0)     ? accS[im][jn][0] * dtab[dj] : 0.f;
                float v1 = (dj - 1 >= 0) ? accS[im][jn][1] * dtab[dj - 1] : 0.f;
                float v2 = (dj + 8 >= 0) ? accS[im][jn][2] * dtab[dj + 8] : 0.f;
                float v3 = (dj + 7 >= 0) ? accS[im][jn][3] * dtab[dj + 7] : 0.f;
                uint32_t h01, l01, h23, l23;
                split2(v0, v1, h01, l01);
                split2(v2, v3, h23, l23);
                *(uint32_t*)(sb16 + O_AH + p0 * RT + j0) = h01;
                *(uint32_t*)(sb16 + O_AL + p0 * RT + j0) = l01;
                *(uint32_t*)(sb16 + O_AH + (p0 + 8) * RT + j0) = h23;
                *(uint32_t*)(sb16 + O_AL + (p0 + 8) * RT + j0) = l23;
            }
    }
    __syncthreads();

    // ---- phase 2: O = A @ V ----
    {
        float accO[4][2][4];
#pragma unroll
        for (int i = 0; i < 4; i++)
#pragma unroll
            for (int j = 0; j < 2; j++)
#pragma unroll
                for (int e = 0; e < 4; e++) accO[i][j][e] = 0.f;

#pragma unroll
        for (int ks = 0; ks < 8; ks++) {
            int kk = ks * 16;
            uint32_t vh[2][2], vl[2][2];
#pragma unroll
            for (int jn = 0; jn < 2; jn++) {
                int nrow = wn * 16 + jn * 8 + b_r;
                uint32_t off = (uint32_t)(nrow * RT + kk + b_k) * 2;
                ldsm2(vh[jn][0], vh[jn][1], sbase + O_VTH * 2 + off);
                ldsm2(vl[jn][0], vl[jn][1], sbase + O_VTL * 2 + off);
            }
#pragma unroll
            for (int im = 0; im < 4; im++) {
                int row = wm * 64 + im * 16 + a_r;
                uint32_t off = (uint32_t)(row * RT + kk + a_k) * 2;
                uint32_t ah[4], al4[4];
                ldsm4(ah[0], ah[1], ah[2], ah[3], sbase + O_AH * 2 + off);
                ldsm4(al4[0], al4[1], al4[2], al4[3], sbase + O_AL * 2 + off);
#pragma unroll
                for (int jn = 0; jn < 2; jn++) {
                    mma_bf16(accO[im][jn], ah, vh[jn]);
                    mma_bf16(accO[im][jn], ah, vl[jn]);
                    mma_bf16(accO[im][jn], al4, vh[jn]);
                }
            }
        }
#pragma unroll
        for (int im = 0; im < 4; im++)
#pragma unroll
            for (int jn = 0; jn < 2; jn++) {
                int p0 = wm * 64 + im * 16 + er;
                int col = wn * 16 + jn * 8 + ec;
                size_t gb = (size_t)(b * NSEQ + n0 + p0) * EE + h * DD + col;
                *(float2*)(g_attn + gb) = make_float2(accO[im][jn][0], accO[im][jn][1]);
                *(float2*)(g_attn + gb + (size_t)8 * EE) =
                    make_float2(accO[im][jn][2], accO[im][jn][3]);
            }
    }

    // ---- phase 3: T = Kw^T @ V ----
    {
        float accT[2][2][4];
#pragma unroll
        for (int i = 0; i < 2; i++)
#pragma unroll
            for (int j = 0; j < 2; j++)
#pragma unroll
                for (int e = 0; e < 4; e++) accT[i][j][e] = 0.f;

#pragma unroll
        for (int ks = 0; ks < 8; ks++) {
            int kk = ks * 16;
            uint32_t vh[2][2], vl[2][2];
#pragma unroll
            for (int jn = 0; jn < 2; jn++) {
                int nrow = wn * 16 + jn * 8 + b_r;
                uint32_t off = (uint32_t)(nrow * RT + kk + b_k) * 2;
                ldsm2(vh[jn][0], vh[jn][1], sbase + O_VTH * 2 + off);
                ldsm2(vl[jn][0], vl[jn][1], sbase + O_VTL * 2 + off);
            }
#pragma unroll
            for (int im = 0; im < 2; im++) {
                int row = wm * 32 + im * 16 + a_r;
                uint32_t off = (uint32_t)(row * RT + kk + a_k) * 2;
                uint32_t kwh[4], kwl[4];
                ldsm4(kwh[0], kwh[1], kwh[2], kwh[3], sbase + O_KWH * 2 + off);
                ldsm4(kwl[0], kwl[1], kwl[2], kwl[3], sbase + O_KWL * 2 + off);
#pragma unroll
                for (int jn = 0; jn < 2; jn++) {
                    mma_bf16(accT[im][jn], kwh, vh[jn]);
                    mma_bf16(accT[im][jn], kwh, vl[jn]);
                    mma_bf16(accT[im][jn], kwl, vh[jn]);
                }
            }
        }
        size_t tb = ((size_t)bh * NCH + chunk) * DD * DD;
#pragma unroll
        for (int im = 0; im < 2; im++)
#pragma unroll
            for (int jn = 0; jn < 2; jn++) {
                int dk = wm * 32 + im * 16 + er;
                int dv = wn * 16 + jn * 8 + ec;
                *(float2*)(g_T + tb + dk * DD + dv) =
                    make_float2(accT[im][jn][0], accT[im][jn][1]);
                *(float2*)(g_T + tb + (dk + 8) * DD + dv) =
                    make_float2(accT[im][jn][2], accT[im][jn][3]);
            }
    }
}

// ======================= pass B: chunk-state scan ========================
__global__ __launch_bounds__(256) void scan_k(const float* __restrict__ lam) {
    int bh = blockIdx.x;
    int h = bh % HH;
    float gamma = __expf(lam[h] * (float)CC);
    size_t base = (size_t)bh * NCH * DD * DD;
    for (int e = threadIdx.x; e < DD * DD; e += blockDim.x) {
        float s = 0.f;
#pragma unroll
        for (int t = 0; t < NCH; t++) {
            g_S[base + t * DD * DD + e] = s;
            s = gamma * s + g_T[base + t * DD * DD + e];
        }
    }
}

// ======================= pass C: inter-chunk + gate fuse + bf16 out ======
__global__ __launch_bounds__(256) void attn_inter_k(const float* __restrict__ lam,
                                                    const float* __restrict__ Wg2) {
    extern __shared__ __align__(16) float sm2[];
    float* Qs = sm2;
    float* Ss = Qs + 128 * 64;
    float* ep = Ss + 64 * 64;
    float* t16s = ep + 128;
    float* wg2s = t16s + 128 * 16;

    int tid = threadIdx.x;
    int chunk = blockIdx.x;
    int bh = blockIdx.y;
    int b = bh / HH, h = bh % HH;
    float lambda = lam[h];
    int n0 = chunk * CC;

    for (int i = tid; i < 128; i += 256) ep[i] = __expf(lambda * (float)i);

    for (int idx = tid; idx < 128 * 16; idx += 256) {
        int p = idx >> 4;
        int d4 = (idx & 15) * 4;
        size_t gb = (size_t)(b * NSEQ + n0 + p) * EE + h * DD + d4;
        uint2 hh = *(const uint2*)(g_qhi + gb);
        uint2 ll = *(const uint2*)(g_qlo + gb);
        __nv_bfloat16* hp = (__nv_bfloat16*)&hh;
        __nv_bfloat16* lp = (__nv_bfloat16*)&ll;
#pragma unroll
        for (int e = 0; e < 4; e++)
            Qs[p * 64 + d4 + e] = __bfloat162float(hp[e]) + __bfloat162float(lp[e]);
    }
    size_t sbo = ((size_t)bh * NCH + chunk) * DD * DD;
    for (int idx = tid; idx < 64 * 16; idx += 256)
        *(float4*)(&Ss[idx * 4]) = *(const float4*)(g_S + sbo + idx * 4);
    for (int i = tid; i < 512; i += 256)
        *(float4*)(t16s + i * 4) =
            *(const float4*)(g_t16 + (size_t)(b * NSEQ + n0) * GG + i * 4);
    for (int i = tid; i < 256; i += 256) {
        int g = i >> 4, c4 = (i & 15) * 4;
        *(float4*)(wg2s + g * 64 + c4) = *(const float4*)(Wg2 + g * EE + h * DD + c4);
    }
    __syncthreads();

    int ty = tid >> 4, tx = tid & 15;
    float o[8][4];
#pragma unroll
    for (int i = 0; i < 8; i++)
#pragma unroll
        for (int j = 0; j < 4; j++) o[i][j] = 0.f;
    for (int kd = 0; kd < 64; kd++) {
        float sv[4];
#pragma unroll
        for (int j = 0; j < 4; j++) sv[j] = Ss[kd * 64 + tx + 16 * j];
#pragma unroll
        for (int i = 0; i < 8; i++) {
            float q = Qs[(ty + 16 * i) * 64 + kd];
#pragma unroll
            for (int j = 0; j < 4; j++) o[i][j] += q * sv[j];
        }
    }
#pragma unroll
    for (int i = 0; i < 8; i++) {
        int p = ty + 16 * i;
        float e = ep[p];
        size_t gb = (size_t)(b * NSEQ + n0 + p) * EE + h * DD;
#pragma unroll
        for (int j = 0; j < 4; j++) {
            int c = tx + 16 * j;
            float s = 0.f;
#pragma unroll
            for (int g = 0; g < 16; g++) s += t16s[p * 16 + g] * wg2s[g * 64 + c];
            float gate = 1.f / (1.f + __expf(-s));
            size_t gi = gb + c;
            float val = (g_attn[gi] + e * o[i][j]) * gate;
            __nv_bfloat16 hv, lv;
            split_bf16(val, hv, lv);
            g_ahi[gi] = hv;
            g_alo[gi] = lv;
        }
    }
}

// ======================= LayerNorm =======================================
__global__ __launch_bounds__(256) void ln_k(const float* __restrict__ w,
                                            const float* __restrict__ bias,
                                            float* __restrict__ out) {
    int row = blockIdx.x;
    int t = threadIdx.x;
    const float* yr = g_y + (size_t)row * EE;
    float v0 = yr[t], v1 = yr[t + 256], v2 = yr[t + 512];

    __shared__ float red[32];
    float s = v0 + v1 + v2;
#pragma unroll
    for (int off = 16; off > 0; off >>= 1) s += __shfl_down_sync(0xffffffffu, s, off);
    if ((t & 31) == 0) red[t >> 5] = s;
    __syncthreads();
    if (t < 32) {
        float x = (t < 8) ? red[t] : 0.f;
#pragma unroll
        for (int off = 4; off > 0; off >>= 1) x += __shfl_down_sync(0xffffffffu, x, off);
        if (t == 0) red[0] = x;
    }
    __syncthreads();
    float mu = red[0] * (1.f / 768.f);
    __syncthreads();

    float d0 = v0 - mu, d1 = v1 - mu, d2 = v2 - mu;
    float s2 = d0 * d0 + d1 * d1 + d2 * d2;
#pragma unroll
    for (int off = 16; off > 0; off >>= 1) s2 += __shfl_down_sync(0xffffffffu, s2, off);
    if ((t & 31) == 0) red[t >> 5] = s2;
    __syncthreads();
    if (t < 32) {
        float x = (t < 8) ? red[t] : 0.f;
#pragma unroll
        for (int off = 4; off > 0; off >>= 1) x += __shfl_down_sync(0xffffffffu, x, off);
        if (t == 0) red[0] = x;
    }
    __syncthreads();
    float var = red[0] * (1.f / 768.f);
    float rs = rsqrtf(var + 1e-5f);

    size_t ob = (size_t)row * EE;
    out[ob + t]       = d0 * rs * w[t]       + bias[t];
    out[ob + t + 256] = d1 * rs * w[t + 256] + bias[t + 256];
    out[ob + t + 512] = d2 * rs * w[t + 512] + bias[t + 512];
}

// =========================================================================
extern "C" void kernel_launch(void* const* d_in, const int* in_sizes, int n_in,
                              void* d_out, int out_size) {
    (void)in_sizes; (void)n_in; (void)out_size;
    const float* x         = (const float*)d_in[0];
    const float* log_slope = (const float*)d_in[1];
    const float* Wq        = (const float*)d_in[2];
    const float* Wk        = (const float*)d_in[3];
    const float* Wv        = (const float*)d_in[4];
    const float* Wo        = (const float*)d_in[5];
    const float* Wg1       = (const float*)d_in[6];
    const float* Wg2       = (const float*)d_in[7];
    const float* ln_w      = (const float*)d_in[8];
    const float* ln_b      = (const float*)d_in[9];
    float* out = (float*)d_out;

    int smMM = 3 * MMSTG;   // 96 KB -> 2 CTAs/SM
    cudaFuncSetAttribute(mm_tc<0>, cudaFuncAttributeMaxDynamicSharedMemorySize, smMM);
    cudaFuncSetAttribute(mm_tc<1>, cudaFuncAttributeMaxDynamicSharedMemorySize, smMM);
    int smA = O_END * 2 + 132 * 4;
    cudaFuncSetAttribute(attn_intra_k, cudaFuncAttributeMaxDynamicSharedMemorySize, smA);
    int smG1 = 43264 * 2;
    cudaFuncSetAttribute(mm_g1, cudaFuncAttributeMaxDynamicSharedMemorySize, smG1);
    int smC = (128 * 64 + 64 * 64 + 128 + 128 * 16 + 16 * 64) * (int)sizeof(float);
    cudaFuncSetAttribute(attn_inter_k, cudaFuncAttributeMaxDynamicSharedMemorySize, smC);

    conv_x_k<<<MTOT * EE / 1024, 256>>>(x);
    conv_w_k<<<dim3(EE / 32, EE / 32, 4), 256>>>(Wq, Wk, Wv, Wo);
    convg1_k<<<GG * EE / 256, 256>>>(Wg1);
    mm_tc<0><<<dim3(EE / 128, MTOT / 128, 3), 256, smMM>>>();
    mm_g1<<<MTOT / 128, 256, smG1>>>();
    attn_intra_k<<<dim3(NCH, BHH), 256, smA>>>(log_slope);
    scan_k<<<BHH, 256>>>(log_slope);
    attn_inter_k<<<dim3(NCH, BHH), 256, smC>>>(log_slope, Wg2);
    mm_tc<1><<<dim3(EE / 128, MTOT / 128, 1), 256, smMM>>>();
    ln_k<<<MTOT, 256>>>(ln_w, ln_b, out);
}

// round 7
// speedup vs baseline: 2.6000x; 1.1387x over previous
#include <cuda_runtime.h>
#include <cuda_bf16.h>
#include <cuda_fp16.h>
#include <cstdint>

// Problem constants
#define BB    2
#define NSEQ  2048
#define EE    768
#define HH    12
#define DD    64
#define GG    16
#define CC    128
#define NCH   (NSEQ / CC)         // 16
#define BHH   (BB * HH)           // 24
#define MTOT  (BB * NSEQ)         // 4096

// ---------------- device scratch ----------------
__device__ float g_attn[MTOT * EE];
__device__ float g_y[MTOT * EE];
__device__ float g_t16[MTOT * GG];
__device__ float g_T[BHH * NCH * DD * DD];
__device__ float g_S[BHH * NCH * DD * DD];

// fp16 operands for projection GEMMs (A single, W split)
__device__ __half g_xh[MTOT * EE];
__device__ __half g_ah[MTOT * EE];
__device__ __half g_wth[4 * EE * EE];   // transposed [n][k]
__device__ __half g_wtl[4 * EE * EE];
__device__ __half g_g1th[GG * EE];
__device__ __half g_g1tl[GG * EE];

// bf16 split operands for attention (unchanged precision path)
__device__ __nv_bfloat16 g_qhi[MTOT * EE];
__device__ __nv_bfloat16 g_qlo[MTOT * EE];
__device__ __nv_bfloat16 g_khi[MTOT * EE];
__device__ __nv_bfloat16 g_klo[MTOT * EE];
__device__ __nv_bfloat16 g_vhi[MTOT * EE];
__device__ __nv_bfloat16 g_vlo[MTOT * EE];

// ======================= helpers ==========================
__device__ __forceinline__ uint32_t smem_u32(const void* p) {
    uint32_t a;
    asm("{ .reg .u64 t; cvta.to.shared.u64 t, %1; cvt.u32.u64 %0, t; }"
        : "=r"(a) : "l"(p));
    return a;
}
__device__ __forceinline__ void cp_async16(uint32_t s, const void* g) {
    asm volatile("cp.async.cg.shared.global [%0], [%1], 16;" :: "r"(s), "l"(g));
}
__device__ __forceinline__ void cp_commit() {
    asm volatile("cp.async.commit_group;");
}
template <int N>
__device__ __forceinline__ void cp_wait() {
    asm volatile("cp.async.wait_group %0;" :: "n"(N));
}
__device__ __forceinline__ void ldsm4(uint32_t& r0, uint32_t& r1, uint32_t& r2,
                                      uint32_t& r3, uint32_t a) {
    asm volatile("ldmatrix.sync.aligned.m8n8.x4.shared.b16 {%0,%1,%2,%3}, [%4];"
                 : "=r"(r0), "=r"(r1), "=r"(r2), "=r"(r3) : "r"(a));
}
__device__ __forceinline__ void ldsm2(uint32_t& r0, uint32_t& r1, uint32_t a) {
    asm volatile("ldmatrix.sync.aligned.m8n8.x2.shared.b16 {%0,%1}, [%2];"
                 : "=r"(r0), "=r"(r1) : "r"(a));
}
__device__ __forceinline__ void mma_bf16(float* c, const uint32_t* a,
                                         const uint32_t* b) {
    asm volatile(
        "mma.sync.aligned.m16n8k16.row.col.f32.bf16.bf16.f32 "
        "{%0,%1,%2,%3}, {%4,%5,%6,%7}, {%8,%9}, {%0,%1,%2,%3};"
        : "+f"(c[0]), "+f"(c[1]), "+f"(c[2]), "+f"(c[3])
        : "r"(a[0]), "r"(a[1]), "r"(a[2]), "r"(a[3]), "r"(b[0]), "r"(b[1]));
}
__device__ __forceinline__ void mma_fp16(float* c, const uint32_t* a,
                                         const uint32_t* b) {
    asm volatile(
        "mma.sync.aligned.m16n8k16.row.col.f32.f16.f16.f32 "
        "{%0,%1,%2,%3}, {%4,%5,%6,%7}, {%8,%9}, {%0,%1,%2,%3};"
        : "+f"(c[0]), "+f"(c[1]), "+f"(c[2]), "+f"(c[3])
        : "r"(a[0]), "r"(a[1]), "r"(a[2]), "r"(a[3]), "r"(b[0]), "r"(b[1]));
}
__device__ __forceinline__ void split_bf16(float v, __nv_bfloat16& h, __nv_bfloat16& l) {
    h = __float2bfloat16(v);
    l = __float2bfloat16(v - __bfloat162float(h));
}
__device__ __forceinline__ void split2(float a, float b, uint32_t& hi, uint32_t& lo) {
    __nv_bfloat16 ha = __float2bfloat16(a), hb = __float2bfloat16(b);
    hi = (uint32_t)*(uint16_t*)&ha | ((uint32_t)*(uint16_t*)&hb << 16);
    float la = a - __bfloat162float(ha), lb = b - __bfloat162float(hb);
    __nv_bfloat16 hla = __float2bfloat16(la), hlb = __float2bfloat16(lb);
    lo = (uint32_t)*(uint16_t*)&hla | ((uint32_t)*(uint16_t*)&hlb << 16);
}
// 64B-row swizzle
__device__ __forceinline__ uint32_t swz64(int r, int cbyte) {
    return (uint32_t)(r * 64 + (cbyte ^ (((r >> 1) & 3) << 4)));
}

// ======================= conversion kernels ==============================
__global__ __launch_bounds__(256) void conv_x_k(const float* __restrict__ x) {
    size_t i = ((size_t)blockIdx.x * 256 + threadIdx.x) * 4;
    float4 v = *(const float4*)(x + i);
    __align__(8) __half h[4];
    h[0] = __float2half(v.x);
    h[1] = __float2half(v.y);
    h[2] = __float2half(v.z);
    h[3] = __float2half(v.w);
    *(uint2*)(g_xh + i) = *(uint2*)h;
}

__global__ __launch_bounds__(256) void conv_w_k(const float* __restrict__ Wq,
                                                const float* __restrict__ Wk,
                                                const float* __restrict__ Wv,
                                                const float* __restrict__ Wo) {
    const float* W = (blockIdx.z == 0) ? Wq : (blockIdx.z == 1) ? Wk
                   : (blockIdx.z == 2) ? Wv : Wo;
    __shared__ float t[32][33];
    int tx = threadIdx.x & 31, ty0 = threadIdx.x >> 5;
    int bn = blockIdx.x * 32, bk = blockIdx.y * 32;
#pragma unroll
    for (int r = 0; r < 4; r++) {
        int ty = ty0 + r * 8;
        t[ty][tx] = W[(size_t)(bk + ty) * EE + bn + tx];
    }
    __syncthreads();
    size_t base = (size_t)blockIdx.z * EE * EE;
#pragma unroll
    for (int r = 0; r < 4; r++) {
        int ty = ty0 + r * 8;
        float v = t[tx][ty];
        __half h = __float2half(v);
        __half l = __float2half(v - __half2float(h));
        size_t o = base + (size_t)(bn + ty) * EE + bk + tx;
        g_wth[o] = h;
        g_wtl[o] = l;
    }
}

__global__ __launch_bounds__(256) void convg1_k(const float* __restrict__ Wg1) {
    int i = blockIdx.x * 256 + threadIdx.x;
    int n = i / EE, k = i % EE;
    float v = Wg1[k * GG + n];
    __half h = __float2half(v);
    g_g1th[i] = h;
    g_g1tl[i] = __float2half(v - __half2float(h));
}

// ======================= fp16 2-term mma.sync GEMM =======================
// C = act(A @ W). A single fp16 (rounding error only on A side); W = wh+wl.
// 3-stage cp.async pipeline, 1 barrier per K-tile, swizzled 64B rows.
// Per-stage layout (bytes): Ah 0 (8K), Bh 8192, Bl 16384; stage 24576.
#define MMSTG 24576
#define MM_AH 0
#define MM_BH 8192
#define MM_BL 16384

template <int MODE>
__global__ __launch_bounds__(256, 2) void mm_tc() {
    extern __shared__ char smem[];
    uint32_t sb = smem_u32(smem);

    int tid = threadIdx.x;
    int wid = tid >> 5, lane = tid & 31;
    int wm = wid & 1, wn = wid >> 1;

    int z = blockIdx.z;
    const __half *Ah, *Wh, *Wl;
    float* Cm = nullptr;
    __nv_bfloat16 *Chi = nullptr, *Clo = nullptr;
    if (MODE == 0) {
        Ah = g_xh;
        Wh = g_wth + (size_t)z * EE * EE;
        Wl = g_wtl + (size_t)z * EE * EE;
        Chi = (z == 0) ? g_qhi : (z == 1) ? g_khi : g_vhi;
        Clo = (z == 0) ? g_qlo : (z == 1) ? g_klo : g_vlo;
    } else {
        Ah = g_ah;
        Wh = g_wth + (size_t)3 * EE * EE;
        Wl = g_wtl + (size_t)3 * EE * EE;
        Cm = g_y;
    }
    int bm = blockIdx.y * 128, bn = blockIdx.x * 128;

    float acc[4][4][4];
#pragma unroll
    for (int i = 0; i < 4; i++)
#pragma unroll
        for (int j = 0; j < 4; j++)
#pragma unroll
            for (int e = 0; e < 4; e++) acc[i][j][e] = 0.f;

    int lr0 = tid >> 2;            // rows lr0, lr0+64
    int lcb = (tid & 3) * 16;      // 16B chunk within 64B row
    int lce = (tid & 3) * 8;       // element col

    auto issue = [&](int kt, int stg) {
        int k0 = kt * 32;
        uint32_t st = sb + (uint32_t)stg * MMSTG;
#pragma unroll
        for (int rr = 0; rr < 2; rr++) {
            int r = lr0 + rr * 64;
            uint32_t so = swz64(r, lcb);
            size_t ga = (size_t)(bm + r) * EE + k0 + lce;
            size_t gb = (size_t)(bn + r) * EE + k0 + lce;
            cp_async16(st + MM_AH + so, Ah + ga);
            cp_async16(st + MM_BH + so, Wh + gb);
            cp_async16(st + MM_BL + so, Wl + gb);
        }
        cp_commit();
    };

    int a_r = lane & 15;
    int a_kb = ((lane >> 4) & 1) << 4;
    int bg = lane >> 3;
    int b_r = lane & 7;
    int b_jn = bg >> 1;
    int b_kb = (bg & 1) << 4;

    issue(0, 0);
    issue(1, 1);
    int stg = 0;
    for (int kt = 0; kt < 24; kt++) {
        if (kt < 23) cp_wait<1>(); else cp_wait<0>();
        __syncthreads();
        if (kt < 22) {
            int ns = stg + 2;
            if (ns >= 3) ns -= 3;
            issue(kt + 2, ns);
        }
        uint32_t st = sb + (uint32_t)stg * MMSTG;
#pragma unroll
        for (int ks = 0; ks < 2; ks++) {
            int kb = ks * 32;
            uint32_t bh[4][2], bl[4][2];
#pragma unroll
            for (int jp = 0; jp < 2; jp++) {
                int nrow = wn * 32 + (jp * 2 + b_jn) * 8 + b_r;
                uint32_t off = swz64(nrow, kb + b_kb);
                ldsm4(bh[jp * 2][0], bh[jp * 2][1], bh[jp * 2 + 1][0],
                      bh[jp * 2 + 1][1], st + MM_BH + off);
                ldsm4(bl[jp * 2][0], bl[jp * 2][1], bl[jp * 2 + 1][0],
                      bl[jp * 2 + 1][1], st + MM_BL + off);
            }
#pragma unroll
            for (int im = 0; im < 4; im++) {
                int row = wm * 64 + im * 16 + a_r;
                uint32_t off = swz64(row, kb + a_kb);
                uint32_t ah[4];
                ldsm4(ah[0], ah[1], ah[2], ah[3], st + MM_AH + off);
#pragma unroll
                for (int jn = 0; jn < 4; jn++) {
                    mma_fp16(acc[im][jn], ah, bh[jn]);
                    mma_fp16(acc[im][jn], ah, bl[jn]);
                }
            }
        }
        stg++;
        if (stg == 3) stg = 0;
    }

    int er = lane >> 2, ec = (lane & 3) * 2;
#pragma unroll
    for (int im = 0; im < 4; im++) {
#pragma unroll
        for (int jn = 0; jn < 4; jn++) {
            int row = bm + wm * 64 + im * 16 + er;
            int col = bn + wn * 32 + jn * 8 + ec;
            float v0 = acc[im][jn][0], v1 = acc[im][jn][1];
            float v2 = acc[im][jn][2], v3 = acc[im][jn][3];
            if (MODE == 0) {
                v0 = v0 / (1.f + __expf(-v0));
                v1 = v1 / (1.f + __expf(-v1));
                v2 = v2 / (1.f + __expf(-v2));
                v3 = v3 / (1.f + __expf(-v3));
                uint32_t h01, l01, h23, l23;
                split2(v0, v1, h01, l01);
                split2(v2, v3, h23, l23);
                *(uint32_t*)(Chi + (size_t)row * EE + col) = h01;
                *(uint32_t*)(Clo + (size_t)row * EE + col) = l01;
                *(uint32_t*)(Chi + (size_t)(row + 8) * EE + col) = h23;
                *(uint32_t*)(Clo + (size_t)(row + 8) * EE + col) = l23;
            } else {
                *(float2*)(Cm + (size_t)row * EE + col) = make_float2(v0, v1);
                *(float2*)(Cm + (size_t)(row + 8) * EE + col) = make_float2(v2, v3);
            }
        }
    }
}

// ======================= mm_g1: t16 = x @ Wg1 (fp16 2-term) ==============
#define G1RB 776
// smem (half elems): Bh 0 (12416), Bl 12416, Ah 24832 (9216); end 34048
__global__ __launch_bounds__(256) void mm_g1() {
    extern __shared__ __half sg[];
    __half* Bh = sg;
    __half* Bl = sg + 12416;
    __half* Ahs = sg + 24832;
    uint32_t sbase = smem_u32(sg);

    int tid = threadIdx.x, wid = tid >> 5, lane = tid & 31;
    int bm = blockIdx.x * 128;

    for (int i = tid; i < 16 * 96; i += 256) {
        int r = i / 96, c8 = (i % 96) * 8;
        *(uint4*)(Bh + r * G1RB + c8) = *(const uint4*)(g_g1th + r * EE + c8);
        *(uint4*)(Bl + r * G1RB + c8) = *(const uint4*)(g_g1tl + r * EE + c8);
    }

    float acc[2][4];
#pragma unroll
    for (int j = 0; j < 2; j++)
#pragma unroll
        for (int e = 0; e < 4; e++) acc[j][e] = 0.f;

    int a_r = lane & 15, a_k = (lane >> 4) << 3;
    int b_r = lane & 7, b_k = ((lane >> 3) & 1) << 3;

    for (int kt = 0; kt < 12; kt++) {
        __syncthreads();
        for (int i = tid; i < 1024; i += 256) {
            int p = i >> 3, c = i & 7;
            size_t go = (size_t)(bm + p) * EE + kt * 64 + c * 8;
            *(uint4*)(Ahs + p * 72 + c * 8) = *(const uint4*)(g_xh + go);
        }
        __syncthreads();
#pragma unroll
        for (int ks = 0; ks < 4; ks++) {
            int kk = ks * 16;
            uint32_t ah[4];
            int row = wid * 16 + a_r;
            uint32_t offa = (uint32_t)(24832 + row * 72 + kk + a_k) * 2;
            ldsm4(ah[0], ah[1], ah[2], ah[3], sbase + offa);
#pragma unroll
            for (int jn = 0; jn < 2; jn++) {
                int nrow = jn * 8 + b_r;
                uint32_t offb = (uint32_t)(nrow * G1RB + kt * 64 + kk + b_k) * 2;
                uint32_t bh[2], bl[2];
                ldsm2(bh[0], bh[1], sbase + offb);
                ldsm2(bl[0], bl[1], sbase + offb + 12416 * 2);
                mma_fp16(acc[jn], ah, bh);
                mma_fp16(acc[jn], ah, bl);
            }
        }
    }
    int er = lane >> 2, ec = (lane & 3) * 2;
#pragma unroll
    for (int jn = 0; jn < 2; jn++) {
        int row = bm + wid * 16 + er;
        int col = jn * 8 + ec;
        *(float2*)(g_t16 + (size_t)row * GG + col) = make_float2(acc[jn][0], acc[jn][1]);
        *(float2*)(g_t16 + (size_t)(row + 8) * GG + col) = make_float2(acc[jn][2], acc[jn][3]);
    }
}

// ======================= attention pass A (intra-chunk, bf16x3 mma) ======
#define O_QH 0
#define O_QL 9216
#define O_KH 18432
#define O_KL 27648
#define O_VTH 36864
#define O_VTL 45568
#define O_KWH 54272
#define O_KWL 62976
#define O_AH 71680
#define O_AL 89088
#define O_END 106496
#define RQ 72
#define RT 136

__global__ __launch_bounds__(256) void attn_intra_k(const float* __restrict__ lam) {
    extern __shared__ __align__(16) __nv_bfloat16 sb16[];
    float* dtab = (float*)(sb16 + O_END);
    uint32_t sbase = smem_u32(sb16);

    int tid = threadIdx.x, wid = tid >> 5, lane = tid & 31;
    int wm = wid & 1, wn = wid >> 1;
    int chunk = blockIdx.x, bh = blockIdx.y;
    int b = bh / HH, h = bh % HH;
    float lambda = lam[h];
    int n0 = chunk * CC;

    for (int i = tid; i <= CC; i += 256) dtab[i] = __expf(lambda * (float)i);

    for (int i = tid; i < 2048; i += 256) {
        int p = i >> 4, d4 = (i & 15) * 4;
        size_t gb = (size_t)(b * NSEQ + n0 + p) * EE + h * DD + d4;
        *(uint2*)(sb16 + O_QH + p * RQ + d4) = *(const uint2*)(g_qhi + gb);
        *(uint2*)(sb16 + O_QL + p * RQ + d4) = *(const uint2*)(g_qlo + gb);
        *(uint2*)(sb16 + O_KH + p * RQ + d4) = *(const uint2*)(g_khi + gb);
        *(uint2*)(sb16 + O_KL + p * RQ + d4) = *(const uint2*)(g_klo + gb);
    }
    for (int i = tid; i < 8192; i += 256) {
        int d = i & 63, p = i >> 6;
        size_t gb = (size_t)(b * NSEQ + n0 + p) * EE + h * DD + d;
        sb16[O_VTH + d * RT + p] = g_vhi[gb];
        sb16[O_VTL + d * RT + p] = g_vlo[gb];
        float kv = __bfloat162float(g_khi[gb]) + __bfloat162float(g_klo[gb]);
        float w = __expf(lambda * (float)(CC - p));
        __nv_bfloat16 hk, lk;
        split_bf16(kv * w, hk, lk);
        sb16[O_KWH + d * RT + p] = hk;
        sb16[O_KWL + d * RT + p] = lk;
    }
    __syncthreads();

    int a_r = lane & 15, a_k = (lane >> 4) << 3;
    int b_r = lane & 7, b_k = ((lane >> 3) & 1) << 3;
    int er = lane >> 2, ec = (lane & 3) * 2;

    // ---- phase 1: S = Q @ K^T ----
    {
        float accS[4][4][4];
#pragma unroll
        for (int i = 0; i < 4; i++)
#pragma unroll
            for (int j = 0; j < 4; j++)
#pragma unroll
                for (int e = 0; e < 4; e++) accS[i][j][e] = 0.f;

#pragma unroll
        for (int ks = 0; ks < 4; ks++) {
            int kk = ks * 16;
            uint32_t kh[4][2], kl[4][2];
#pragma unroll
            for (int jn = 0; jn < 4; jn++) {
                int nrow = wn * 32 + jn * 8 + b_r;
                uint32_t off = (uint32_t)(nrow * RQ + kk + b_k) * 2;
                ldsm2(kh[jn][0], kh[jn][1], sbase + O_KH * 2 + off);
                ldsm2(kl[jn][0], kl[jn][1], sbase + O_KL * 2 + off);
            }
#pragma unroll
            for (int im = 0; im < 4; im++) {
                int row = wm * 64 + im * 16 + a_r;
                uint32_t off = (uint32_t)(row * RQ + kk + a_k) * 2;
                uint32_t qh[4], ql[4];
                ldsm4(qh[0], qh[1], qh[2], qh[3], sbase + O_QH * 2 + off);
                ldsm4(ql[0], ql[1], ql[2], ql[3], sbase + O_QL * 2 + off);
#pragma unroll
                for (int jn = 0; jn < 4; jn++) {
                    mma_bf16(accS[im][jn], qh, kh[jn]);
                    mma_bf16(accS[im][jn], qh, kl[jn]);
                    mma_bf16(accS[im][jn], ql, kh[jn]);
                }
            }
        }
#pragma unroll
        for (int im = 0; im < 4; im++)
#pragma unroll
            for (int jn = 0; jn < 4; jn++) {
                int p0 = wm * 64 + im * 16 + er;
                int j0 = wn * 32 + jn * 8 + ec;
                int dj = p0 - j0;
                float v0 = (dj >= 0)     ? accS[im][jn][0] * dtab[dj] : 0.f;
                float v1 = (dj - 1 >= 0) ? accS[im][jn][1] * dtab[dj - 1] : 0.f;
                float v2 = (dj + 8 >= 0) ? accS[im][jn][2] * dtab[dj + 8] : 0.f;
                float v3 = (dj + 7 >= 0) ? accS[im][jn][3] * dtab[dj + 7] : 0.f;
                uint32_t h01, l01, h23, l23;
                split2(v0, v1, h01, l01);
                split2(v2, v3, h23, l23);
                *(uint32_t*)(sb16 + O_AH + p0 * RT + j0) = h01;
                *(uint32_t*)(sb16 + O_AL + p0 * RT + j0) = l01;
                *(uint32_t*)(sb16 + O_AH + (p0 + 8) * RT + j0) = h23;
                *(uint32_t*)(sb16 + O_AL + (p0 + 8) * RT + j0) = l23;
            }
    }
    __syncthreads();

    // ---- phase 2: O = A @ V ----
    {
        float accO[4][2][4];
#pragma unroll
        for (int i = 0; i < 4; i++)
#pragma unroll
            for (int j = 0; j < 2; j++)
#pragma unroll
                for (int e = 0; e < 4; e++) accO[i][j][e] = 0.f;

#pragma unroll
        for (int ks = 0; ks < 8; ks++) {
            int kk = ks * 16;
            uint32_t vh[2][2], vl[2][2];
#pragma unroll
            for (int jn = 0; jn < 2; jn++) {
                int nrow = wn * 16 + jn * 8 + b_r;
                uint32_t off = (uint32_t)(nrow * RT + kk + b_k) * 2;
                ldsm2(vh[jn][0], vh[jn][1], sbase + O_VTH * 2 + off);
                ldsm2(vl[jn][0], vl[jn][1], sbase + O_VTL * 2 + off);
            }
#pragma unroll
            for (int im = 0; im < 4; im++) {
                int row = wm * 64 + im * 16 + a_r;
                uint32_t off = (uint32_t)(row * RT + kk + a_k) * 2;
                uint32_t ah[4], al4[4];
                ldsm4(ah[0], ah[1], ah[2], ah[3], sbase + O_AH * 2 + off);
                ldsm4(al4[0], al4[1], al4[2], al4[3], sbase + O_AL * 2 + off);
#pragma unroll
                for (int jn = 0; jn < 2; jn++) {
                    mma_bf16(accO[im][jn], ah, vh[jn]);
                    mma_bf16(accO[im][jn], ah, vl[jn]);
                    mma_bf16(accO[im][jn], al4, vh[jn]);
                }
            }
        }
#pragma unroll
        for (int im = 0; im < 4; im++)
#pragma unroll
            for (int jn = 0; jn < 2; jn++) {
                int p0 = wm * 64 + im * 16 + er;
                int col = wn * 16 + jn * 8 + ec;
                size_t gb = (size_t)(b * NSEQ + n0 + p0) * EE + h * DD + col;
                *(float2*)(g_attn + gb) = make_float2(accO[im][jn][0], accO[im][jn][1]);
                *(float2*)(g_attn + gb + (size_t)8 * EE) =
                    make_float2(accO[im][jn][2], accO[im][jn][3]);
            }
    }

    // ---- phase 3: T = Kw^T @ V ----
    {
        float accT[2][2][4];
#pragma unroll
        for (int i = 0; i < 2; i++)
#pragma unroll
            for (int j = 0; j < 2; j++)
#pragma unroll
                for (int e = 0; e < 4; e++) accT[i][j][e] = 0.f;

#pragma unroll
        for (int ks = 0; ks < 8; ks++) {
            int kk = ks * 16;
            uint32_t vh[2][2], vl[2][2];
#pragma unroll
            for (int jn = 0; jn < 2; jn++) {
                int nrow = wn * 16 + jn * 8 + b_r;
                uint32_t off = (uint32_t)(nrow * RT + kk + b_k) * 2;
                ldsm2(vh[jn][0], vh[jn][1], sbase + O_VTH * 2 + off);
                ldsm2(vl[jn][0], vl[jn][1], sbase + O_VTL * 2 + off);
            }
#pragma unroll
            for (int im = 0; im < 2; im++) {
                int row = wm * 32 + im * 16 + a_r;
                uint32_t off = (uint32_t)(row * RT + kk + a_k) * 2;
                uint32_t kwh[4], kwl[4];
                ldsm4(kwh[0], kwh[1], kwh[2], kwh[3], sbase + O_KWH * 2 + off);
                ldsm4(kwl[0], kwl[1], kwl[2], kwl[3], sbase + O_KWL * 2 + off);
#pragma unroll
                for (int jn = 0; jn < 2; jn++) {
                    mma_bf16(accT[im][jn], kwh, vh[jn]);
                    mma_bf16(accT[im][jn], kwh, vl[jn]);
                    mma_bf16(accT[im][jn], kwl, vh[jn]);
                }
            }
        }
        size_t tb = ((size_t)bh * NCH + chunk) * DD * DD;
#pragma unroll
        for (int im = 0; im < 2; im++)
#pragma unroll
            for (int jn = 0; jn < 2; jn++) {
                int dk = wm * 32 + im * 16 + er;
                int dv = wn * 16 + jn * 8 + ec;
                *(float2*)(g_T + tb + dk * DD + dv) =
                    make_float2(accT[im][jn][0], accT[im][jn][1]);
                *(float2*)(g_T + tb + (dk + 8) * DD + dv) =
                    make_float2(accT[im][jn][2], accT[im][jn][3]);
            }
    }
}

// ======================= pass B: chunk-state scan ========================
__global__ __launch_bounds__(256) void scan_k(const float* __restrict__ lam) {
    int bh = blockIdx.x;
    int h = bh % HH;
    float gamma = __expf(lam[h] * (float)CC);
    size_t base = (size_t)bh * NCH * DD * DD;
    for (int e = threadIdx.x; e < DD * DD; e += blockDim.x) {
        float s = 0.f;
#pragma unroll
        for (int t = 0; t < NCH; t++) {
            g_S[base + t * DD * DD + e] = s;
            s = gamma * s + g_T[base + t * DD * DD + e];
        }
    }
}

// ======================= pass C: inter-chunk + gate fuse + fp16 out ======
__global__ __launch_bounds__(256) void attn_inter_k(const float* __restrict__ lam,
                                                    const float* __restrict__ Wg2) {
    extern __shared__ __align__(16) float sm2[];
    float* Qs = sm2;
    float* Ss = Qs + 128 * 64;
    float* ep = Ss + 64 * 64;
    float* t16s = ep + 128;
    float* wg2s = t16s + 128 * 16;

    int tid = threadIdx.x;
    int chunk = blockIdx.x;
    int bh = blockIdx.y;
    int b = bh / HH, h = bh % HH;
    float lambda = lam[h];
    int n0 = chunk * CC;

    for (int i = tid; i < 128; i += 256) ep[i] = __expf(lambda * (float)i);

    for (int idx = tid; idx < 128 * 16; idx += 256) {
        int p = idx >> 4;
        int d4 = (idx & 15) * 4;
        size_t gb = (size_t)(b * NSEQ + n0 + p) * EE + h * DD + d4;
        uint2 hh = *(const uint2*)(g_qhi + gb);
        uint2 ll = *(const uint2*)(g_qlo + gb);
        __nv_bfloat16* hp = (__nv_bfloat16*)&hh;
        __nv_bfloat16* lp = (__nv_bfloat16*)&ll;
#pragma unroll
        for (int e = 0; e < 4; e++)
            Qs[p * 64 + d4 + e] = __bfloat162float(hp[e]) + __bfloat162float(lp[e]);
    }
    size_t sbo = ((size_t)bh * NCH + chunk) * DD * DD;
    for (int idx = tid; idx < 64 * 16; idx += 256)
        *(float4*)(&Ss[idx * 4]) = *(const float4*)(g_S + sbo + idx * 4);
    for (int i = tid; i < 512; i += 256)
        *(float4*)(t16s + i * 4) =
            *(const float4*)(g_t16 + (size_t)(b * NSEQ + n0) * GG + i * 4);
    for (int i = tid; i < 256; i += 256) {
        int g = i >> 4, c4 = (i & 15) * 4;
        *(float4*)(wg2s + g * 64 + c4) = *(const float4*)(Wg2 + g * EE + h * DD + c4);
    }
    __syncthreads();

    int ty = tid >> 4, tx = tid & 15;
    float o[8][4];
#pragma unroll
    for (int i = 0; i < 8; i++)
#pragma unroll
        for (int j = 0; j < 4; j++) o[i][j] = 0.f;
    for (int kd = 0; kd < 64; kd++) {
        float sv[4];
#pragma unroll
        for (int j = 0; j < 4; j++) sv[j] = Ss[kd * 64 + tx + 16 * j];
#pragma unroll
        for (int i = 0; i < 8; i++) {
            float q = Qs[(ty + 16 * i) * 64 + kd];
#pragma unroll
            for (int j = 0; j < 4; j++) o[i][j] += q * sv[j];
        }
    }
#pragma unroll
    for (int i = 0; i < 8; i++) {
        int p = ty + 16 * i;
        float e = ep[p];
        size_t gb = (size_t)(b * NSEQ + n0 + p) * EE + h * DD;
#pragma unroll
        for (int j = 0; j < 4; j++) {
            int c = tx + 16 * j;
            float s = 0.f;
#pragma unroll
            for (int g = 0; g < 16; g++) s += t16s[p * 16 + g] * wg2s[g * 64 + c];
            float gate = 1.f / (1.f + __expf(-s));
            size_t gi = gb + c;
            float val = (g_attn[gi] + e * o[i][j]) * gate;
            g_ah[gi] = __float2half(val);
        }
    }
}

// ======================= LayerNorm =======================================
__global__ __launch_bounds__(256) void ln_k(const float* __restrict__ w,
                                            const float* __restrict__ bias,
                                            float* __restrict__ out) {
    int row = blockIdx.x;
    int t = threadIdx.x;
    const float* yr = g_y + (size_t)row * EE;
    float v0 = yr[t], v1 = yr[t + 256], v2 = yr[t + 512];

    __shared__ float red[32];
    float s = v0 + v1 + v2;
#pragma unroll
    for (int off = 16; off > 0; off >>= 1) s += __shfl_down_sync(0xffffffffu, s, off);
    if ((t & 31) == 0) red[t >> 5] = s;
    __syncthreads();
    if (t < 32) {
        float x = (t < 8) ? red[t] : 0.f;
#pragma unroll
        for (int off = 4; off > 0; off >>= 1) x += __shfl_down_sync(0xffffffffu, x, off);
        if (t == 0) red[0] = x;
    }
    __syncthreads();
    float mu = red[0] * (1.f / 768.f);
    __syncthreads();

    float d0 = v0 - mu, d1 = v1 - mu, d2 = v2 - mu;
    float s2 = d0 * d0 + d1 * d1 + d2 * d2;
#pragma unroll
    for (int off = 16; off > 0; off >>= 1) s2 += __shfl_down_sync(0xffffffffu, s2, off);
    if ((t & 31) == 0) red[t >> 5] = s2;
    __syncthreads();
    if (t < 32) {
        float x = (t < 8) ? red[t] : 0.f;
#pragma unroll
        for (int off = 4; off > 0; off >>= 1) x += __shfl_down_sync(0xffffffffu, x, off);
        if (t == 0) red[0] = x;
    }
    __syncthreads();
    float var = red[0] * (1.f / 768.f);
    float rs = rsqrtf(var + 1e-5f);

    size_t ob = (size_t)row * EE;
    out[ob + t]       = d0 * rs * w[t]       + bias[t];
    out[ob + t + 256] = d1 * rs * w[t + 256] + bias[t + 256];
    out[ob + t + 512] = d2 * rs * w[t + 512] + bias[t + 512];
}

// =========================================================================
extern "C" void kernel_launch(void* const* d_in, const int* in_sizes, int n_in,
                              void* d_out, int out_size) {
    (void)in_sizes; (void)n_in; (void)out_size;
    const float* x         = (const float*)d_in[0];
    const float* log_slope = (const float*)d_in[1];
    const float* Wq        = (const float*)d_in[2];
    const float* Wk        = (const float*)d_in[3];
    const float* Wv        = (const float*)d_in[4];
    const float* Wo        = (const float*)d_in[5];
    const float* Wg1       = (const float*)d_in[6];
    const float* Wg2       = (const float*)d_in[7];
    const float* ln_w      = (const float*)d_in[8];
    const float* ln_b      = (const float*)d_in[9];
    float* out = (float*)d_out;

    int smMM = 3 * MMSTG;   // 72 KB -> 2 CTAs/SM
    cudaFuncSetAttribute(mm_tc<0>, cudaFuncAttributeMaxDynamicSharedMemorySize, smMM);
    cudaFuncSetAttribute(mm_tc<1>, cudaFuncAttributeMaxDynamicSharedMemorySize, smMM);
    int smA = O_END * 2 + 132 * 4;
    cudaFuncSetAttribute(attn_intra_k, cudaFuncAttributeMaxDynamicSharedMemorySize, smA);
    int smG1 = 34048 * 2;
    cudaFuncSetAttribute(mm_g1, cudaFuncAttributeMaxDynamicSharedMemorySize, smG1);
    int smC = (128 * 64 + 64 * 64 + 128 + 128 * 16 + 16 * 64) * (int)sizeof(float);
    cudaFuncSetAttribute(attn_inter_k, cudaFuncAttributeMaxDynamicSharedMemorySize, smC);

    conv_x_k<<<MTOT * EE / 1024, 256>>>(x);
    conv_w_k<<<dim3(EE / 32, EE / 32, 4), 256>>>(Wq, Wk, Wv, Wo);
    convg1_k<<<GG * EE / 256, 256>>>(Wg1);
    mm_tc<0><<<dim3(EE / 128, MTOT / 128, 3), 256, smMM>>>();
    mm_g1<<<MTOT / 128, 256, smG1>>>();
    attn_intra_k<<<dim3(NCH, BHH), 256, smA>>>(log_slope);
    scan_k<<<BHH, 256>>>(log_slope);
    attn_inter_k<<<dim3(NCH, BHH), 256, smC>>>(log_slope, Wg2);
    mm_tc<1><<<dim3(EE / 128, MTOT / 128, 1), 256, smMM>>>();
    ln_k<<<MTOT, 256>>>(ln_w, ln_b, out);
}

// round 8
// speedup vs baseline: 2.7065x; 1.0410x over previous
#include <cuda_runtime.h>
#include <cuda_bf16.h>
#include <cuda_fp16.h>
#include <cstdint>

// Problem constants
#define BB    2
#define NSEQ  2048
#define EE    768
#define HH    12
#define DD    64
#define GG    16
#define CC    128
#define NCH   (NSEQ / CC)         // 16
#define BHH   (BB * HH)           // 24
#define MTOT  (BB * NSEQ)         // 4096

// ---------------- device scratch ----------------
__device__ float g_attn[MTOT * EE];
__device__ float g_y[MTOT * EE];
__device__ float g_t16[MTOT * GG];
__device__ float g_T[BHH * NCH * DD * DD];
__device__ float g_S[BHH * NCH * DD * DD];

// fp16 operands
__device__ __half g_xh[MTOT * EE];
__device__ __half g_ah[MTOT * EE];
__device__ __half g_wth[4 * EE * EE];   // transposed [n][k]
__device__ __half g_wtl[4 * EE * EE];
__device__ __half g_g1th[GG * EE];
__device__ __half g_g1tl[GG * EE];

// attention operands: q,v single fp16; k 2-term fp16
__device__ __half g_q16[MTOT * EE];
__device__ __half g_k16h[MTOT * EE];
__device__ __half g_k16l[MTOT * EE];
__device__ __half g_v16[MTOT * EE];

// ======================= helpers ==========================
__device__ __forceinline__ uint32_t smem_u32(const void* p) {
    uint32_t a;
    asm("{ .reg .u64 t; cvta.to.shared.u64 t, %1; cvt.u32.u64 %0, t; }"
        : "=r"(a) : "l"(p));
    return a;
}
__device__ __forceinline__ void cp_async16(uint32_t s, const void* g) {
    asm volatile("cp.async.cg.shared.global [%0], [%1], 16;" :: "r"(s), "l"(g));
}
__device__ __forceinline__ void cp_commit() {
    asm volatile("cp.async.commit_group;");
}
template <int N>
__device__ __forceinline__ void cp_wait() {
    asm volatile("cp.async.wait_group %0;" :: "n"(N));
}
__device__ __forceinline__ void ldsm4(uint32_t& r0, uint32_t& r1, uint32_t& r2,
                                      uint32_t& r3, uint32_t a) {
    asm volatile("ldmatrix.sync.aligned.m8n8.x4.shared.b16 {%0,%1,%2,%3}, [%4];"
                 : "=r"(r0), "=r"(r1), "=r"(r2), "=r"(r3) : "r"(a));
}
__device__ __forceinline__ void ldsm2(uint32_t& r0, uint32_t& r1, uint32_t a) {
    asm volatile("ldmatrix.sync.aligned.m8n8.x2.shared.b16 {%0,%1}, [%2];"
                 : "=r"(r0), "=r"(r1) : "r"(a));
}
__device__ __forceinline__ void mma_fp16(float* c, const uint32_t* a,
                                         const uint32_t* b) {
    asm volatile(
        "mma.sync.aligned.m16n8k16.row.col.f32.f16.f16.f32 "
        "{%0,%1,%2,%3}, {%4,%5,%6,%7}, {%8,%9}, {%0,%1,%2,%3};"
        : "+f"(c[0]), "+f"(c[1]), "+f"(c[2]), "+f"(c[3])
        : "r"(a[0]), "r"(a[1]), "r"(a[2]), "r"(a[3]), "r"(b[0]), "r"(b[1]));
}
// pack two floats into single-fp16 word
__device__ __forceinline__ uint32_t pack2h(float a, float b) {
    __half ha = __float2half(a), hb = __float2half(b);
    return (uint32_t)*(uint16_t*)&ha | ((uint32_t)*(uint16_t*)&hb << 16);
}
// fp16 2-term split of two floats
__device__ __forceinline__ void split2h(float a, float b, uint32_t& hi, uint32_t& lo) {
    __half ha = __float2half(a), hb = __float2half(b);
    hi = (uint32_t)*(uint16_t*)&ha | ((uint32_t)*(uint16_t*)&hb << 16);
    float la = a - __half2float(ha), lb = b - __half2float(hb);
    __half hla = __float2half(la), hlb = __float2half(lb);
    lo = (uint32_t)*(uint16_t*)&hla | ((uint32_t)*(uint16_t*)&hlb << 16);
}
// 64B-row swizzle
__device__ __forceinline__ uint32_t swz64(int r, int cbyte) {
    return (uint32_t)(r * 64 + (cbyte ^ (((r >> 1) & 3) << 4)));
}

// ======================= conversion kernels ==============================
__global__ __launch_bounds__(256) void conv_x_k(const float* __restrict__ x) {
    size_t i = ((size_t)blockIdx.x * 256 + threadIdx.x) * 4;
    float4 v = *(const float4*)(x + i);
    __align__(8) __half h[4];
    h[0] = __float2half(v.x);
    h[1] = __float2half(v.y);
    h[2] = __float2half(v.z);
    h[3] = __float2half(v.w);
    *(uint2*)(g_xh + i) = *(uint2*)h;
}

__global__ __launch_bounds__(256) void conv_w_k(const float* __restrict__ Wq,
                                                const float* __restrict__ Wk,
                                                const float* __restrict__ Wv,
                                                const float* __restrict__ Wo) {
    const float* W = (blockIdx.z == 0) ? Wq : (blockIdx.z == 1) ? Wk
                   : (blockIdx.z == 2) ? Wv : Wo;
    __shared__ float t[32][33];
    int tx = threadIdx.x & 31, ty0 = threadIdx.x >> 5;
    int bn = blockIdx.x * 32, bk = blockIdx.y * 32;
#pragma unroll
    for (int r = 0; r < 4; r++) {
        int ty = ty0 + r * 8;
        t[ty][tx] = W[(size_t)(bk + ty) * EE + bn + tx];
    }
    __syncthreads();
    size_t base = (size_t)blockIdx.z * EE * EE;
#pragma unroll
    for (int r = 0; r < 4; r++) {
        int ty = ty0 + r * 8;
        float v = t[tx][ty];
        __half h = __float2half(v);
        __half l = __float2half(v - __half2float(h));
        size_t o = base + (size_t)(bn + ty) * EE + bk + tx;
        g_wth[o] = h;
        g_wtl[o] = l;
    }
}

__global__ __launch_bounds__(256) void convg1_k(const float* __restrict__ Wg1) {
    int i = blockIdx.x * 256 + threadIdx.x;
    int n = i / EE, k = i % EE;
    float v = Wg1[k * GG + n];
    __half h = __float2half(v);
    g_g1th[i] = h;
    g_g1tl[i] = __float2half(v - __half2float(h));
}

// ======================= fp16 2-term mma.sync GEMM =======================
#define MMSTG 24576
#define MM_AH 0
#define MM_BH 8192
#define MM_BL 16384

template <int MODE>
__global__ __launch_bounds__(256, 2) void mm_tc() {
    extern __shared__ char smem[];
    uint32_t sb = smem_u32(smem);

    int tid = threadIdx.x;
    int wid = tid >> 5, lane = tid & 31;
    int wm = wid & 1, wn = wid >> 1;

    int z = blockIdx.z;
    const __half *Ah, *Wh, *Wl;
    float* Cm = nullptr;
    __half *C1 = nullptr, *C2 = nullptr;
    if (MODE == 0) {
        Ah = g_xh;
        Wh = g_wth + (size_t)z * EE * EE;
        Wl = g_wtl + (size_t)z * EE * EE;
        C1 = (z == 0) ? g_q16 : (z == 1) ? g_k16h : g_v16;
        C2 = (z == 1) ? g_k16l : nullptr;
    } else {
        Ah = g_ah;
        Wh = g_wth + (size_t)3 * EE * EE;
        Wl = g_wtl + (size_t)3 * EE * EE;
        Cm = g_y;
    }
    int bm = blockIdx.y * 128, bn = blockIdx.x * 128;

    float acc[4][4][4];
#pragma unroll
    for (int i = 0; i < 4; i++)
#pragma unroll
        for (int j = 0; j < 4; j++)
#pragma unroll
            for (int e = 0; e < 4; e++) acc[i][j][e] = 0.f;

    int lr0 = tid >> 2;
    int lcb = (tid & 3) * 16;
    int lce = (tid & 3) * 8;

    auto issue = [&](int kt, int stg) {
        int k0 = kt * 32;
        uint32_t st = sb + (uint32_t)stg * MMSTG;
#pragma unroll
        for (int rr = 0; rr < 2; rr++) {
            int r = lr0 + rr * 64;
            uint32_t so = swz64(r, lcb);
            size_t ga = (size_t)(bm + r) * EE + k0 + lce;
            size_t gb = (size_t)(bn + r) * EE + k0 + lce;
            cp_async16(st + MM_AH + so, Ah + ga);
            cp_async16(st + MM_BH + so, Wh + gb);
            cp_async16(st + MM_BL + so, Wl + gb);
        }
        cp_commit();
    };

    int a_r = lane & 15;
    int a_kb = ((lane >> 4) & 1) << 4;
    int bg = lane >> 3;
    int b_r = lane & 7;
    int b_jn = bg >> 1;
    int b_kb = (bg & 1) << 4;

    issue(0, 0);
    issue(1, 1);
    int stg = 0;
    for (int kt = 0; kt < 24; kt++) {
        if (kt < 23) cp_wait<1>(); else cp_wait<0>();
        __syncthreads();
        if (kt < 22) {
            int ns = stg + 2;
            if (ns >= 3) ns -= 3;
            issue(kt + 2, ns);
        }
        uint32_t st = sb + (uint32_t)stg * MMSTG;
#pragma unroll
        for (int ks = 0; ks < 2; ks++) {
            int kb = ks * 32;
            uint32_t bh[4][2], bl[4][2];
#pragma unroll
            for (int jp = 0; jp < 2; jp++) {
                int nrow = wn * 32 + (jp * 2 + b_jn) * 8 + b_r;
                uint32_t off = swz64(nrow, kb + b_kb);
                ldsm4(bh[jp * 2][0], bh[jp * 2][1], bh[jp * 2 + 1][0],
                      bh[jp * 2 + 1][1], st + MM_BH + off);
                ldsm4(bl[jp * 2][0], bl[jp * 2][1], bl[jp * 2 + 1][0],
                      bl[jp * 2 + 1][1], st + MM_BL + off);
            }
#pragma unroll
            for (int im = 0; im < 4; im++) {
                int row = wm * 64 + im * 16 + a_r;
                uint32_t off = swz64(row, kb + a_kb);
                uint32_t ah[4];
                ldsm4(ah[0], ah[1], ah[2], ah[3], st + MM_AH + off);
#pragma unroll
                for (int jn = 0; jn < 4; jn++) {
                    mma_fp16(acc[im][jn], ah, bh[jn]);
                    mma_fp16(acc[im][jn], ah, bl[jn]);
                }
            }
        }
        stg++;
        if (stg == 3) stg = 0;
    }

    int er = lane >> 2, ec = (lane & 3) * 2;
#pragma unroll
    for (int im = 0; im < 4; im++) {
#pragma unroll
        for (int jn = 0; jn < 4; jn++) {
            int row = bm + wm * 64 + im * 16 + er;
            int col = bn + wn * 32 + jn * 8 + ec;
            float v0 = acc[im][jn][0], v1 = acc[im][jn][1];
            float v2 = acc[im][jn][2], v3 = acc[im][jn][3];
            if (MODE == 0) {
                v0 = v0 / (1.f + __expf(-v0));
                v1 = v1 / (1.f + __expf(-v1));
                v2 = v2 / (1.f + __expf(-v2));
                v3 = v3 / (1.f + __expf(-v3));
                if (z == 1) {
                    uint32_t h01, l01, h23, l23;
                    split2h(v0, v1, h01, l01);
                    split2h(v2, v3, h23, l23);
                    *(uint32_t*)(C1 + (size_t)row * EE + col) = h01;
                    *(uint32_t*)(C2 + (size_t)row * EE + col) = l01;
                    *(uint32_t*)(C1 + (size_t)(row + 8) * EE + col) = h23;
                    *(uint32_t*)(C2 + (size_t)(row + 8) * EE + col) = l23;
                } else {
                    *(uint32_t*)(C1 + (size_t)row * EE + col) = pack2h(v0, v1);
                    *(uint32_t*)(C1 + (size_t)(row + 8) * EE + col) = pack2h(v2, v3);
                }
            } else {
                *(float2*)(Cm + (size_t)row * EE + col) = make_float2(v0, v1);
                *(float2*)(Cm + (size_t)(row + 8) * EE + col) = make_float2(v2, v3);
            }
        }
    }
}

// ======================= mm_g1: t16 = x @ Wg1 (fp16 2-term) ==============
#define G1RB 776
__global__ __launch_bounds__(256) void mm_g1() {
    extern __shared__ __half sg[];
    __half* Bh = sg;
    __half* Bl = sg + 12416;
    __half* Ahs = sg + 24832;
    uint32_t sbase = smem_u32(sg);

    int tid = threadIdx.x, wid = tid >> 5, lane = tid & 31;
    int bm = blockIdx.x * 128;

    for (int i = tid; i < 16 * 96; i += 256) {
        int r = i / 96, c8 = (i % 96) * 8;
        *(uint4*)(Bh + r * G1RB + c8) = *(const uint4*)(g_g1th + r * EE + c8);
        *(uint4*)(Bl + r * G1RB + c8) = *(const uint4*)(g_g1tl + r * EE + c8);
    }

    float acc[2][4];
#pragma unroll
    for (int j = 0; j < 2; j++)
#pragma unroll
        for (int e = 0; e < 4; e++) acc[j][e] = 0.f;

    int a_r = lane & 15, a_k = (lane >> 4) << 3;
    int b_r = lane & 7, b_k = ((lane >> 3) & 1) << 3;

    for (int kt = 0; kt < 12; kt++) {
        __syncthreads();
        for (int i = tid; i < 1024; i += 256) {
            int p = i >> 3, c = i & 7;
            size_t go = (size_t)(bm + p) * EE + kt * 64 + c * 8;
            *(uint4*)(Ahs + p * 72 + c * 8) = *(const uint4*)(g_xh + go);
        }
        __syncthreads();
#pragma unroll
        for (int ks = 0; ks < 4; ks++) {
            int kk = ks * 16;
            uint32_t ah[4];
            int row = wid * 16 + a_r;
            uint32_t offa = (uint32_t)(24832 + row * 72 + kk + a_k) * 2;
            ldsm4(ah[0], ah[1], ah[2], ah[3], sbase + offa);
#pragma unroll
            for (int jn = 0; jn < 2; jn++) {
                int nrow = jn * 8 + b_r;
                uint32_t offb = (uint32_t)(nrow * G1RB + kt * 64 + kk + b_k) * 2;
                uint32_t bh[2], bl[2];
                ldsm2(bh[0], bh[1], sbase + offb);
                ldsm2(bl[0], bl[1], sbase + offb + 12416 * 2);
                mma_fp16(acc[jn], ah, bh);
                mma_fp16(acc[jn], ah, bl);
            }
        }
    }
    int er = lane >> 2, ec = (lane & 3) * 2;
#pragma unroll
    for (int jn = 0; jn < 2; jn++) {
        int row = bm + wid * 16 + er;
        int col = jn * 8 + ec;
        *(float2*)(g_t16 + (size_t)row * GG + col) = make_float2(acc[jn][0], acc[jn][1]);
        *(float2*)(g_t16 + (size_t)(row + 8) * GG + col) = make_float2(acc[jn][2], acc[jn][3]);
    }
}

// ======================= attention pass A (asym fp16 mma) ================
// smem layout (half elems):
//  QH 0 (single), KH 9216, KL 18432            (stride 72, [128][64])
//  VT 27648 (single), KWH 36352, KWL 45056     (stride 136, [64][128])
//  AH 53760, AL 71168                          (stride 136, [128][128])
//  dtab (float) at elem 88576
#define O_QH 0
#define O_KH 9216
#define O_KL 18432
#define O_VT 27648
#define O_KWH 36352
#define O_KWL 45056
#define O_AH 53760
#define O_AL 71168
#define O_END 88576
#define RQ 72
#define RT 136

__global__ __launch_bounds__(256) void attn_intra_k(const float* __restrict__ lam) {
    extern __shared__ __align__(16) __half sh16[];
    float* dtab = (float*)(sh16 + O_END);
    uint32_t sbase = smem_u32(sh16);

    int tid = threadIdx.x, wid = tid >> 5, lane = tid & 31;
    int wm = wid & 1, wn = wid >> 1;
    int chunk = blockIdx.x, bh = blockIdx.y;
    int b = bh / HH, h = bh % HH;
    float lambda = lam[h];
    int n0 = chunk * CC;

    for (int i = tid; i <= CC; i += 256) dtab[i] = __expf(lambda * (float)i);

    for (int i = tid; i < 2048; i += 256) {
        int p = i >> 4, d4 = (i & 15) * 4;
        size_t gb = (size_t)(b * NSEQ + n0 + p) * EE + h * DD + d4;
        *(uint2*)(sh16 + O_QH + p * RQ + d4) = *(const uint2*)(g_q16 + gb);
        *(uint2*)(sh16 + O_KH + p * RQ + d4) = *(const uint2*)(g_k16h + gb);
        *(uint2*)(sh16 + O_KL + p * RQ + d4) = *(const uint2*)(g_k16l + gb);
    }
    for (int i = tid; i < 8192; i += 256) {
        int d = i & 63, p = i >> 6;
        size_t gb = (size_t)(b * NSEQ + n0 + p) * EE + h * DD + d;
        sh16[O_VT + d * RT + p] = g_v16[gb];
        float kv = __half2float(g_k16h[gb]) + __half2float(g_k16l[gb]);
        float w = __expf(lambda * (float)(CC - p));
        float kw = kv * w;
        __half hk = __float2half(kw);
        sh16[O_KWH + d * RT + p] = hk;
        sh16[O_KWL + d * RT + p] = __float2half(kw - __half2float(hk));
    }
    __syncthreads();

    int a_r = lane & 15, a_k = (lane >> 4) << 3;
    int b_r = lane & 7, b_k = ((lane >> 3) & 1) << 3;
    int er = lane >> 2, ec = (lane & 3) * 2;

    // ---- phase 1: S = Q(single) @ (Kh+Kl)^T ----
    {
        float accS[4][4][4];
#pragma unroll
        for (int i = 0; i < 4; i++)
#pragma unroll
            for (int j = 0; j < 4; j++)
#pragma unroll
                for (int e = 0; e < 4; e++) accS[i][j][e] = 0.f;

#pragma unroll
        for (int ks = 0; ks < 4; ks++) {
            int kk = ks * 16;
            uint32_t kh[4][2], kl[4][2];
#pragma unroll
            for (int jn = 0; jn < 4; jn++) {
                int nrow = wn * 32 + jn * 8 + b_r;
                uint32_t off = (uint32_t)(nrow * RQ + kk + b_k) * 2;
                ldsm2(kh[jn][0], kh[jn][1], sbase + O_KH * 2 + off);
                ldsm2(kl[jn][0], kl[jn][1], sbase + O_KL * 2 + off);
            }
#pragma unroll
            for (int im = 0; im < 4; im++) {
                int row = wm * 64 + im * 16 + a_r;
                uint32_t off = (uint32_t)(row * RQ + kk + a_k) * 2;
                uint32_t qh[4];
                ldsm4(qh[0], qh[1], qh[2], qh[3], sbase + O_QH * 2 + off);
#pragma unroll
                for (int jn = 0; jn < 4; jn++) {
                    mma_fp16(accS[im][jn], qh, kh[jn]);
                    mma_fp16(accS[im][jn], qh, kl[jn]);
                }
            }
        }
#pragma unroll
        for (int im = 0; im < 4; im++)
#pragma unroll
            for (int jn = 0; jn < 4; jn++) {
                int p0 = wm * 64 + im * 16 + er;
                int j0 = wn * 32 + jn * 8 + ec;
                int dj = p0 - j0;
                float v0 = (dj >= 0)     ? accS[im][jn][0] * dtab[dj] : 0.f;
                float v1 = (dj - 1 >= 0) ? accS[im][jn][1] * dtab[dj - 1] : 0.f;
                float v2 = (dj + 8 >= 0) ? accS[im][jn][2] * dtab[dj + 8] : 0.f;
                float v3 = (dj + 7 >= 0) ? accS[im][jn][3] * dtab[dj + 7] : 0.f;
                uint32_t h01, l01, h23, l23;
                split2h(v0, v1, h01, l01);
                split2h(v2, v3, h23, l23);
                *(uint32_t*)(sh16 + O_AH + p0 * RT + j0) = h01;
                *(uint32_t*)(sh16 + O_AL + p0 * RT + j0) = l01;
                *(uint32_t*)(sh16 + O_AH + (p0 + 8) * RT + j0) = h23;
                *(uint32_t*)(sh16 + O_AL + (p0 + 8) * RT + j0) = l23;
            }
    }
    __syncthreads();

    // ---- phase 2: O = (Ah+Al) @ V(single) ----
    {
        float accO[4][2][4];
#pragma unroll
        for (int i = 0; i < 4; i++)
#pragma unroll
            for (int j = 0; j < 2; j++)
#pragma unroll
                for (int e = 0; e < 4; e++) accO[i][j][e] = 0.f;

#pragma unroll
        for (int ks = 0; ks < 8; ks++) {
            int kk = ks * 16;
            uint32_t vh[2][2];
#pragma unroll
            for (int jn = 0; jn < 2; jn++) {
                int nrow = wn * 16 + jn * 8 + b_r;
                uint32_t off = (uint32_t)(nrow * RT + kk + b_k) * 2;
                ldsm2(vh[jn][0], vh[jn][1], sbase + O_VT * 2 + off);
            }
#pragma unroll
            for (int im = 0; im < 4; im++) {
                int row = wm * 64 + im * 16 + a_r;
                uint32_t off = (uint32_t)(row * RT + kk + a_k) * 2;
                uint32_t ah[4], al4[4];
                ldsm4(ah[0], ah[1], ah[2], ah[3], sbase + O_AH * 2 + off);
                ldsm4(al4[0], al4[1], al4[2], al4[3], sbase + O_AL * 2 + off);
#pragma unroll
                for (int jn = 0; jn < 2; jn++) {
                    mma_fp16(accO[im][jn], ah, vh[jn]);
                    mma_fp16(accO[im][jn], al4, vh[jn]);
                }
            }
        }
#pragma unroll
        for (int im = 0; im < 4; im++)
#pragma unroll
            for (int jn = 0; jn < 2; jn++) {
                int p0 = wm * 64 + im * 16 + er;
                int col = wn * 16 + jn * 8 + ec;
                size_t gb = (size_t)(b * NSEQ + n0 + p0) * EE + h * DD + col;
                *(float2*)(g_attn + gb) = make_float2(accO[im][jn][0], accO[im][jn][1]);
                *(float2*)(g_attn + gb + (size_t)8 * EE) =
                    make_float2(accO[im][jn][2], accO[im][jn][3]);
            }
    }

    // ---- phase 3: T = (Kwh+Kwl)^T @ V(single) ----
    {
        float accT[2][2][4];
#pragma unroll
        for (int i = 0; i < 2; i++)
#pragma unroll
            for (int j = 0; j < 2; j++)
#pragma unroll
                for (int e = 0; e < 4; e++) accT[i][j][e] = 0.f;

#pragma unroll
        for (int ks = 0; ks < 8; ks++) {
            int kk = ks * 16;
            uint32_t vh[2][2];
#pragma unroll
            for (int jn = 0; jn < 2; jn++) {
                int nrow = wn * 16 + jn * 8 + b_r;
                uint32_t off = (uint32_t)(nrow * RT + kk + b_k) * 2;
                ldsm2(vh[jn][0], vh[jn][1], sbase + O_VT * 2 + off);
            }
#pragma unroll
            for (int im = 0; im < 2; im++) {
                int row = wm * 32 + im * 16 + a_r;
                uint32_t off = (uint32_t)(row * RT + kk + a_k) * 2;
                uint32_t kwh[4], kwl[4];
                ldsm4(kwh[0], kwh[1], kwh[2], kwh[3], sbase + O_KWH * 2 + off);
                ldsm4(kwl[0], kwl[1], kwl[2], kwl[3], sbase + O_KWL * 2 + off);
#pragma unroll
                for (int jn = 0; jn < 2; jn++) {
                    mma_fp16(accT[im][jn], kwh, vh[jn]);
                    mma_fp16(accT[im][jn], kwl, vh[jn]);
                }
            }
        }
        size_t tb = ((size_t)bh * NCH + chunk) * DD * DD;
#pragma unroll
        for (int im = 0; im < 2; im++)
#pragma unroll
            for (int jn = 0; jn < 2; jn++) {
                int dk = wm * 32 + im * 16 + er;
                int dv = wn * 16 + jn * 8 + ec;
                *(float2*)(g_T + tb + dk * DD + dv) =
                    make_float2(accT[im][jn][0], accT[im][jn][1]);
                *(float2*)(g_T + tb + (dk + 8) * DD + dv) =
                    make_float2(accT[im][jn][2], accT[im][jn][3]);
            }
    }
}

// ======================= pass B: chunk-state scan ========================
__global__ __launch_bounds__(256) void scan_k(const float* __restrict__ lam) {
    int bh = blockIdx.x;
    int h = bh % HH;
    float gamma = __expf(lam[h] * (float)CC);
    size_t base = (size_t)bh * NCH * DD * DD;
    for (int e = threadIdx.x; e < DD * DD; e += blockDim.x) {
        float s = 0.f;
#pragma unroll
        for (int t = 0; t < NCH; t++) {
            g_S[base + t * DD * DD + e] = s;
            s = gamma * s + g_T[base + t * DD * DD + e];
        }
    }
}

// ======================= pass C: inter-chunk + gate fuse + fp16 out ======
__global__ __launch_bounds__(256) void attn_inter_k(const float* __restrict__ lam,
                                                    const float* __restrict__ Wg2) {
    extern __shared__ __align__(16) float sm2[];
    float* Qs = sm2;
    float* Ss = Qs + 128 * 64;
    float* ep = Ss + 64 * 64;
    float* t16s = ep + 128;
    float* wg2s = t16s + 128 * 16;

    int tid = threadIdx.x;
    int chunk = blockIdx.x;
    int bh = blockIdx.y;
    int b = bh / HH, h = bh % HH;
    float lambda = lam[h];
    int n0 = chunk * CC;

    for (int i = tid; i < 128; i += 256) ep[i] = __expf(lambda * (float)i);

    for (int idx = tid; idx < 128 * 16; idx += 256) {
        int p = idx >> 4;
        int d4 = (idx & 15) * 4;
        size_t gb = (size_t)(b * NSEQ + n0 + p) * EE + h * DD + d4;
        uint2 hh = *(const uint2*)(g_q16 + gb);
        __half* hp = (__half*)&hh;
#pragma unroll
        for (int e = 0; e < 4; e++)
            Qs[p * 64 + d4 + e] = __half2float(hp[e]);
    }
    size_t sbo = ((size_t)bh * NCH + chunk) * DD * DD;
    for (int idx = tid; idx < 64 * 16; idx += 256)
        *(float4*)(&Ss[idx * 4]) = *(const float4*)(g_S + sbo + idx * 4);
    for (int i = tid; i < 512; i += 256)
        *(float4*)(t16s + i * 4) =
            *(const float4*)(g_t16 + (size_t)(b * NSEQ + n0) * GG + i * 4);
    for (int i = tid; i < 256; i += 256) {
        int g = i >> 4, c4 = (i & 15) * 4;
        *(float4*)(wg2s + g * 64 + c4) = *(const float4*)(Wg2 + g * EE + h * DD + c4);
    }
    __syncthreads();

    int ty = tid >> 4, tx = tid & 15;
    float o[8][4];
#pragma unroll
    for (int i = 0; i < 8; i++)
#pragma unroll
        for (int j = 0; j < 4; j++) o[i][j] = 0.f;
    for (int kd = 0; kd < 64; kd++) {
        float sv[4];
#pragma unroll
        for (int j = 0; j < 4; j++) sv[j] = Ss[kd * 64 + tx + 16 * j];
#pragma unroll
        for (int i = 0; i < 8; i++) {
            float q = Qs[(ty + 16 * i) * 64 + kd];
#pragma unroll
            for (int j = 0; j < 4; j++) o[i][j] += q * sv[j];
        }
    }
#pragma unroll
    for (int i = 0; i < 8; i++) {
        int p = ty + 16 * i;
        float e = ep[p];
        size_t gb = (size_t)(b * NSEQ + n0 + p) * EE + h * DD;
#pragma unroll
        for (int j = 0; j < 4; j++) {
            int c = tx + 16 * j;
            float s = 0.f;
#pragma unroll
            for (int g = 0; g < 16; g++) s += t16s[p * 16 + g] * wg2s[g * 64 + c];
            float gate = 1.f / (1.f + __expf(-s));
            size_t gi = gb + c;
            float val = (g_attn[gi] + e * o[i][j]) * gate;
            g_ah[gi] = __float2half(val);
        }
    }
}

// ======================= LayerNorm =======================================
__global__ __launch_bounds__(256) void ln_k(const float* __restrict__ w,
                                            const float* __restrict__ bias,
                                            float* __restrict__ out) {
    int row = blockIdx.x;
    int t = threadIdx.x;
    const float* yr = g_y + (size_t)row * EE;
    float v0 = yr[t], v1 = yr[t + 256], v2 = yr[t + 512];

    __shared__ float red[32];
    float s = v0 + v1 + v2;
#pragma unroll
    for (int off = 16; off > 0; off >>= 1) s += __shfl_down_sync(0xffffffffu, s, off);
    if ((t & 31) == 0) red[t >> 5] = s;
    __syncthreads();
    if (t < 32) {
        float x = (t < 8) ? red[t] : 0.f;
#pragma unroll
        for (int off = 4; off > 0; off >>= 1) x += __shfl_down_sync(0xffffffffu, x, off);
        if (t == 0) red[0] = x;
    }
    __syncthreads();
    float mu = red[0] * (1.f / 768.f);
    __syncthreads();

    float d0 = v0 - mu, d1 = v1 - mu, d2 = v2 - mu;
    float s2 = d0 * d0 + d1 * d1 + d2 * d2;
#pragma unroll
    for (int off = 16; off > 0; off >>= 1) s2 += __shfl_down_sync(0xffffffffu, s2, off);
    if ((t & 31) == 0) red[t >> 5] = s2;
    __syncthreads();
    if (t < 32) {
        float x = (t < 8) ? red[t] : 0.f;
#pragma unroll
        for (int off = 4; off > 0; off >>= 1) x += __shfl_down_sync(0xffffffffu, x, off);
        if (t == 0) red[0] = x;
    }
    __syncthreads();
    float var = red[0] * (1.f / 768.f);
    float rs = rsqrtf(var + 1e-5f);

    size_t ob = (size_t)row * EE;
    out[ob + t]       = d0 * rs * w[t]       + bias[t];
    out[ob + t + 256] = d1 * rs * w[t + 256] + bias[t + 256];
    out[ob + t + 512] = d2 * rs * w[t + 512] + bias[t + 512];
}

// =========================================================================
extern "C" void kernel_launch(void* const* d_in, const int* in_sizes, int n_in,
                              void* d_out, int out_size) {
    (void)in_sizes; (void)n_in; (void)out_size;
    const float* x         = (const float*)d_in[0];
    const float* log_slope = (const float*)d_in[1];
    const float* Wq        = (const float*)d_in[2];
    const float* Wk        = (const float*)d_in[3];
    const float* Wv        = (const float*)d_in[4];
    const float* Wo        = (const float*)d_in[5];
    const float* Wg1       = (const float*)d_in[6];
    const float* Wg2       = (const float*)d_in[7];
    const float* ln_w      = (const float*)d_in[8];
    const float* ln_b      = (const float*)d_in[9];
    float* out = (float*)d_out;

    int smMM = 3 * MMSTG;   // 72 KB -> 2 CTAs/SM
    cudaFuncSetAttribute(mm_tc<0>, cudaFuncAttributeMaxDynamicSharedMemorySize, smMM);
    cudaFuncSetAttribute(mm_tc<1>, cudaFuncAttributeMaxDynamicSharedMemorySize, smMM);
    int smA = O_END * 2 + 132 * 4;   // ~177.7 KB
    cudaFuncSetAttribute(attn_intra_k, cudaFuncAttributeMaxDynamicSharedMemorySize, smA);
    int smG1 = 34048 * 2;
    cudaFuncSetAttribute(mm_g1, cudaFuncAttributeMaxDynamicSharedMemorySize, smG1);
    int smC = (128 * 64 + 64 * 64 + 128 + 128 * 16 + 16 * 64) * (int)sizeof(float);
    cudaFuncSetAttribute(attn_inter_k, cudaFuncAttributeMaxDynamicSharedMemorySize, smC);

    conv_x_k<<<MTOT * EE / 1024, 256>>>(x);
    conv_w_k<<<dim3(EE / 32, EE / 32, 4), 256>>>(Wq, Wk, Wv, Wo);
    convg1_k<<<GG * EE / 256, 256>>>(Wg1);
    mm_tc<0><<<dim3(EE / 128, MTOT / 128, 3), 256, smMM>>>();
    mm_g1<<<MTOT / 128, 256, smG1>>>();
    attn_intra_k<<<dim3(NCH, BHH), 256, smA>>>(log_slope);
    scan_k<<<BHH, 256>>>(log_slope);
    attn_inter_k<<<dim3(NCH, BHH), 256, smC>>>(log_slope, Wg2);
    mm_tc<1><<<dim3(EE / 128, MTOT / 128, 1), 256, smMM>>>();
    ln_k<<<MTOT, 256>>>(ln_w, ln_b, out);
}

// round 9
// speedup vs baseline: 2.8256x; 1.0440x over previous
#include <cuda_runtime.h>
#include <cuda_bf16.h>
#include <cuda_fp16.h>
#include <cstdint>

// Problem constants
#define BB    2
#define NSEQ  2048
#define EE    768
#define HH    12
#define DD    64
#define GG    16
#define CC    128
#define NCH   (NSEQ / CC)         // 16
#define BHH   (BB * HH)           // 24
#define MTOT  (BB * NSEQ)         // 4096

// ---------------- device scratch ----------------
__device__ float g_attn[MTOT * EE];
__device__ float g_y[MTOT * EE];
__device__ float g_t16[MTOT * GG];
__device__ float g_T[BHH * NCH * DD * DD];
__device__ float g_S[BHH * NCH * DD * DD];

// fp16 operands
__device__ __half g_xh[MTOT * EE];
__device__ __half g_ah[MTOT * EE];
__device__ __half g_wth[4 * EE * EE];   // transposed [n][k]
__device__ __half g_wtl[4 * EE * EE];
__device__ __half g_g1th[GG * EE];
__device__ __half g_g1tl[GG * EE];

// attention operands: q,k,v all single fp16
__device__ __half g_q16[MTOT * EE];
__device__ __half g_k16[MTOT * EE];
__device__ __half g_v16[MTOT * EE];

// ======================= helpers ==========================
__device__ __forceinline__ uint32_t smem_u32(const void* p) {
    uint32_t a;
    asm("{ .reg .u64 t; cvta.to.shared.u64 t, %1; cvt.u32.u64 %0, t; }"
        : "=r"(a) : "l"(p));
    return a;
}
__device__ __forceinline__ void cp_async16(uint32_t s, const void* g) {
    asm volatile("cp.async.cg.shared.global [%0], [%1], 16;" :: "r"(s), "l"(g));
}
__device__ __forceinline__ void cp_commit() {
    asm volatile("cp.async.commit_group;");
}
template <int N>
__device__ __forceinline__ void cp_wait() {
    asm volatile("cp.async.wait_group %0;" :: "n"(N));
}
__device__ __forceinline__ void ldsm4(uint32_t& r0, uint32_t& r1, uint32_t& r2,
                                      uint32_t& r3, uint32_t a) {
    asm volatile("ldmatrix.sync.aligned.m8n8.x4.shared.b16 {%0,%1,%2,%3}, [%4];"
                 : "=r"(r0), "=r"(r1), "=r"(r2), "=r"(r3) : "r"(a));
}
__device__ __forceinline__ void ldsm2(uint32_t& r0, uint32_t& r1, uint32_t a) {
    asm volatile("ldmatrix.sync.aligned.m8n8.x2.shared.b16 {%0,%1}, [%2];"
                 : "=r"(r0), "=r"(r1) : "r"(a));
}
__device__ __forceinline__ void mma_fp16(float* c, const uint32_t* a,
                                         const uint32_t* b) {
    asm volatile(
        "mma.sync.aligned.m16n8k16.row.col.f32.f16.f16.f32 "
        "{%0,%1,%2,%3}, {%4,%5,%6,%7}, {%8,%9}, {%0,%1,%2,%3};"
        : "+f"(c[0]), "+f"(c[1]), "+f"(c[2]), "+f"(c[3])
        : "r"(a[0]), "r"(a[1]), "r"(a[2]), "r"(a[3]), "r"(b[0]), "r"(b[1]));
}
__device__ __forceinline__ uint32_t pack2h(float a, float b) {
    __half ha = __float2half(a), hb = __float2half(b);
    return (uint32_t)*(uint16_t*)&ha | ((uint32_t)*(uint16_t*)&hb << 16);
}
// 64B-row swizzle
__device__ __forceinline__ uint32_t swz64(int r, int cbyte) {
    return (uint32_t)(r * 64 + (cbyte ^ (((r >> 1) & 3) << 4)));
}

// ======================= conversion kernels ==============================
__global__ __launch_bounds__(256) void conv_x_k(const float* __restrict__ x) {
    size_t i = ((size_t)blockIdx.x * 256 + threadIdx.x) * 4;
    float4 v = *(const float4*)(x + i);
    __align__(8) __half h[4];
    h[0] = __float2half(v.x);
    h[1] = __float2half(v.y);
    h[2] = __float2half(v.z);
    h[3] = __float2half(v.w);
    *(uint2*)(g_xh + i) = *(uint2*)h;
}

__global__ __launch_bounds__(256) void conv_w_k(const float* __restrict__ Wq,
                                                const float* __restrict__ Wk,
                                                const float* __restrict__ Wv,
                                                const float* __restrict__ Wo) {
    const float* W = (blockIdx.z == 0) ? Wq : (blockIdx.z == 1) ? Wk
                   : (blockIdx.z == 2) ? Wv : Wo;
    __shared__ float t[32][33];
    int tx = threadIdx.x & 31, ty0 = threadIdx.x >> 5;
    int bn = blockIdx.x * 32, bk = blockIdx.y * 32;
#pragma unroll
    for (int r = 0; r < 4; r++) {
        int ty = ty0 + r * 8;
        t[ty][tx] = W[(size_t)(bk + ty) * EE + bn + tx];
    }
    __syncthreads();
    size_t base = (size_t)blockIdx.z * EE * EE;
#pragma unroll
    for (int r = 0; r < 4; r++) {
        int ty = ty0 + r * 8;
        float v = t[tx][ty];
        __half h = __float2half(v);
        __half l = __float2half(v - __half2float(h));
        size_t o = base + (size_t)(bn + ty) * EE + bk + tx;
        g_wth[o] = h;
        g_wtl[o] = l;
    }
}

__global__ __launch_bounds__(256) void convg1_k(const float* __restrict__ Wg1) {
    int i = blockIdx.x * 256 + threadIdx.x;
    int n = i / EE, k = i % EE;
    float v = Wg1[k * GG + n];
    __half h = __float2half(v);
    g_g1th[i] = h;
    g_g1tl[i] = __float2half(v - __half2float(h));
}

// ======================= fp16 2-term mma.sync GEMM =======================
#define MMSTG 24576
#define MM_AH 0
#define MM_BH 8192
#define MM_BL 16384

template <int MODE>
__global__ __launch_bounds__(256, 2) void mm_tc() {
    extern __shared__ char smem[];
    uint32_t sb = smem_u32(smem);

    int tid = threadIdx.x;
    int wid = tid >> 5, lane = tid & 31;
    int wm = wid & 1, wn = wid >> 1;

    int z = blockIdx.z;
    const __half *Ah, *Wh, *Wl;
    float* Cm = nullptr;
    __half* C1 = nullptr;
    if (MODE == 0) {
        Ah = g_xh;
        Wh = g_wth + (size_t)z * EE * EE;
        Wl = g_wtl + (size_t)z * EE * EE;
        C1 = (z == 0) ? g_q16 : (z == 1) ? g_k16 : g_v16;
    } else {
        Ah = g_ah;
        Wh = g_wth + (size_t)3 * EE * EE;
        Wl = g_wtl + (size_t)3 * EE * EE;
        Cm = g_y;
    }
    int bm = blockIdx.y * 128, bn = blockIdx.x * 128;

    float acc[4][4][4];
#pragma unroll
    for (int i = 0; i < 4; i++)
#pragma unroll
        for (int j = 0; j < 4; j++)
#pragma unroll
            for (int e = 0; e < 4; e++) acc[i][j][e] = 0.f;

    int lr0 = tid >> 2;
    int lcb = (tid & 3) * 16;
    int lce = (tid & 3) * 8;

    auto issue = [&](int kt, int stg) {
        int k0 = kt * 32;
        uint32_t st = sb + (uint32_t)stg * MMSTG;
#pragma unroll
        for (int rr = 0; rr < 2; rr++) {
            int r = lr0 + rr * 64;
            uint32_t so = swz64(r, lcb);
            size_t ga = (size_t)(bm + r) * EE + k0 + lce;
            size_t gb = (size_t)(bn + r) * EE + k0 + lce;
            cp_async16(st + MM_AH + so, Ah + ga);
            cp_async16(st + MM_BH + so, Wh + gb);
            cp_async16(st + MM_BL + so, Wl + gb);
        }
        cp_commit();
    };

    int a_r = lane & 15;
    int a_kb = ((lane >> 4) & 1) << 4;
    int bg = lane >> 3;
    int b_r = lane & 7;
    int b_jn = bg >> 1;
    int b_kb = (bg & 1) << 4;

    issue(0, 0);
    issue(1, 1);
    int stg = 0;
    for (int kt = 0; kt < 24; kt++) {
        if (kt < 23) cp_wait<1>(); else cp_wait<0>();
        __syncthreads();
        if (kt < 22) {
            int ns = stg + 2;
            if (ns >= 3) ns -= 3;
            issue(kt + 2, ns);
        }
        uint32_t st = sb + (uint32_t)stg * MMSTG;
#pragma unroll
        for (int ks = 0; ks < 2; ks++) {
            int kb = ks * 32;
            uint32_t bh[4][2], bl[4][2];
#pragma unroll
            for (int jp = 0; jp < 2; jp++) {
                int nrow = wn * 32 + (jp * 2 + b_jn) * 8 + b_r;
                uint32_t off = swz64(nrow, kb + b_kb);
                ldsm4(bh[jp * 2][0], bh[jp * 2][1], bh[jp * 2 + 1][0],
                      bh[jp * 2 + 1][1], st + MM_BH + off);
                ldsm4(bl[jp * 2][0], bl[jp * 2][1], bl[jp * 2 + 1][0],
                      bl[jp * 2 + 1][1], st + MM_BL + off);
            }
#pragma unroll
            for (int im = 0; im < 4; im++) {
                int row = wm * 64 + im * 16 + a_r;
                uint32_t off = swz64(row, kb + a_kb);
                uint32_t ah[4];
                ldsm4(ah[0], ah[1], ah[2], ah[3], st + MM_AH + off);
#pragma unroll
                for (int jn = 0; jn < 4; jn++) {
                    mma_fp16(acc[im][jn], ah, bh[jn]);
                    mma_fp16(acc[im][jn], ah, bl[jn]);
                }
            }
        }
        stg++;
        if (stg == 3) stg = 0;
    }

    int er = lane >> 2, ec = (lane & 3) * 2;
#pragma unroll
    for (int im = 0; im < 4; im++) {
#pragma unroll
        for (int jn = 0; jn < 4; jn++) {
            int row = bm + wm * 64 + im * 16 + er;
            int col = bn + wn * 32 + jn * 8 + ec;
            float v0 = acc[im][jn][0], v1 = acc[im][jn][1];
            float v2 = acc[im][jn][2], v3 = acc[im][jn][3];
            if (MODE == 0) {
                v0 = v0 / (1.f + __expf(-v0));
                v1 = v1 / (1.f + __expf(-v1));
                v2 = v2 / (1.f + __expf(-v2));
                v3 = v3 / (1.f + __expf(-v3));
                *(uint32_t*)(C1 + (size_t)row * EE + col) = pack2h(v0, v1);
                *(uint32_t*)(C1 + (size_t)(row + 8) * EE + col) = pack2h(v2, v3);
            } else {
                *(float2*)(Cm + (size_t)row * EE + col) = make_float2(v0, v1);
                *(float2*)(Cm + (size_t)(row + 8) * EE + col) = make_float2(v2, v3);
            }
        }
    }
}

// ======================= mm_g1: t16 = x @ Wg1 (fp16 2-term) ==============
#define G1RB 776
__global__ __launch_bounds__(256) void mm_g1() {
    extern __shared__ __half sg[];
    __half* Bh = sg;
    __half* Bl = sg + 12416;
    __half* Ahs = sg + 24832;
    uint32_t sbase = smem_u32(sg);

    int tid = threadIdx.x, wid = tid >> 5, lane = tid & 31;
    int bm = blockIdx.x * 128;

    for (int i = tid; i < 16 * 96; i += 256) {
        int r = i / 96, c8 = (i % 96) * 8;
        *(uint4*)(Bh + r * G1RB + c8) = *(const uint4*)(g_g1th + r * EE + c8);
        *(uint4*)(Bl + r * G1RB + c8) = *(const uint4*)(g_g1tl + r * EE + c8);
    }

    float acc[2][4];
#pragma unroll
    for (int j = 0; j < 2; j++)
#pragma unroll
        for (int e = 0; e < 4; e++) acc[j][e] = 0.f;

    int a_r = lane & 15, a_k = (lane >> 4) << 3;
    int b_r = lane & 7, b_k = ((lane >> 3) & 1) << 3;

    for (int kt = 0; kt < 12; kt++) {
        __syncthreads();
        for (int i = tid; i < 1024; i += 256) {
            int p = i >> 3, c = i & 7;
            size_t go = (size_t)(bm + p) * EE + kt * 64 + c * 8;
            *(uint4*)(Ahs + p * 72 + c * 8) = *(const uint4*)(g_xh + go);
        }
        __syncthreads();
#pragma unroll
        for (int ks = 0; ks < 4; ks++) {
            int kk = ks * 16;
            uint32_t ah[4];
            int row = wid * 16 + a_r;
            uint32_t offa = (uint32_t)(24832 + row * 72 + kk + a_k) * 2;
            ldsm4(ah[0], ah[1], ah[2], ah[3], sbase + offa);
#pragma unroll
            for (int jn = 0; jn < 2; jn++) {
                int nrow = jn * 8 + b_r;
                uint32_t offb = (uint32_t)(nrow * G1RB + kt * 64 + kk + b_k) * 2;
                uint32_t bh[2], bl[2];
                ldsm2(bh[0], bh[1], sbase + offb);
                ldsm2(bl[0], bl[1], sbase + offb + 12416 * 2);
                mma_fp16(acc[jn], ah, bh);
                mma_fp16(acc[jn], ah, bl);
            }
        }
    }
    int er = lane >> 2, ec = (lane & 3) * 2;
#pragma unroll
    for (int jn = 0; jn < 2; jn++) {
        int row = bm + wid * 16 + er;
        int col = jn * 8 + ec;
        *(float2*)(g_t16 + (size_t)row * GG + col) = make_float2(acc[jn][0], acc[jn][1]);
        *(float2*)(g_t16 + (size_t)(row + 8) * GG + col) = make_float2(acc[jn][2], acc[jn][3]);
    }
}

// ======================= attention pass A (all-single fp16 mma) ==========
// smem layout (half elems):
//  QH 0, KH 9216                   (stride 72, [128][64])
//  VT 18432, KWH 27136             (stride 136, [64][128])
//  AH 35840                        (stride 136, [128][128])
//  dtab (float) at elem 53248
#define O_QH 0
#define O_KH 9216
#define O_VT 18432
#define O_KWH 27136
#define O_AH 35840
#define O_END 53248
#define RQ 72
#define RT 136

__global__ __launch_bounds__(256, 2) void attn_intra_k(const float* __restrict__ lam) {
    extern __shared__ __align__(16) __half sh16[];
    float* dtab = (float*)(sh16 + O_END);
    uint32_t sbase = smem_u32(sh16);

    int tid = threadIdx.x, wid = tid >> 5, lane = tid & 31;
    int wm = wid & 1, wn = wid >> 1;
    int chunk = blockIdx.x, bh = blockIdx.y;
    int b = bh / HH, h = bh % HH;
    float lambda = lam[h];
    int n0 = chunk * CC;

    for (int i = tid; i <= CC; i += 256) dtab[i] = __expf(lambda * (float)i);

    for (int i = tid; i < 2048; i += 256) {
        int p = i >> 4, d4 = (i & 15) * 4;
        size_t gb = (size_t)(b * NSEQ + n0 + p) * EE + h * DD + d4;
        *(uint2*)(sh16 + O_QH + p * RQ + d4) = *(const uint2*)(g_q16 + gb);
        *(uint2*)(sh16 + O_KH + p * RQ + d4) = *(const uint2*)(g_k16 + gb);
    }
    for (int i = tid; i < 8192; i += 256) {
        int d = i & 63, p = i >> 6;
        size_t gb = (size_t)(b * NSEQ + n0 + p) * EE + h * DD + d;
        sh16[O_VT + d * RT + p] = g_v16[gb];
        float kv = __half2float(g_k16[gb]);
        float w = __expf(lambda * (float)(CC - p));
        sh16[O_KWH + d * RT + p] = __float2half(kv * w);
    }
    __syncthreads();

    int a_r = lane & 15, a_k = (lane >> 4) << 3;
    int b_r = lane & 7, b_k = ((lane >> 3) & 1) << 3;
    int er = lane >> 2, ec = (lane & 3) * 2;

    // ---- phase 1: S = Q @ K^T ----
    {
        float accS[4][4][4];
#pragma unroll
        for (int i = 0; i < 4; i++)
#pragma unroll
            for (int j = 0; j < 4; j++)
#pragma unroll
                for (int e = 0; e < 4; e++) accS[i][j][e] = 0.f;

#pragma unroll
        for (int ks = 0; ks < 4; ks++) {
            int kk = ks * 16;
            uint32_t kh[4][2];
#pragma unroll
            for (int jn = 0; jn < 4; jn++) {
                int nrow = wn * 32 + jn * 8 + b_r;
                uint32_t off = (uint32_t)(nrow * RQ + kk + b_k) * 2;
                ldsm2(kh[jn][0], kh[jn][1], sbase + O_KH * 2 + off);
            }
#pragma unroll
            for (int im = 0; im < 4; im++) {
                int row = wm * 64 + im * 16 + a_r;
                uint32_t off = (uint32_t)(row * RQ + kk + a_k) * 2;
                uint32_t qh[4];
                ldsm4(qh[0], qh[1], qh[2], qh[3], sbase + O_QH * 2 + off);
#pragma unroll
                for (int jn = 0; jn < 4; jn++)
                    mma_fp16(accS[im][jn], qh, kh[jn]);
            }
        }
#pragma unroll
        for (int im = 0; im < 4; im++)
#pragma unroll
            for (int jn = 0; jn < 4; jn++) {
                int p0 = wm * 64 + im * 16 + er;
                int j0 = wn * 32 + jn * 8 + ec;
                int dj = p0 - j0;
                float v0 = (dj >= 0)     ? accS[im][jn][0] * dtab[dj] : 0.f;
                float v1 = (dj - 1 >= 0) ? accS[im][jn][1] * dtab[dj - 1] : 0.f;
                float v2 = (dj + 8 >= 0) ? accS[im][jn][2] * dtab[dj + 8] : 0.f;
                float v3 = (dj + 7 >= 0) ? accS[im][jn][3] * dtab[dj + 7] : 0.f;
                *(uint32_t*)(sh16 + O_AH + p0 * RT + j0) = pack2h(v0, v1);
                *(uint32_t*)(sh16 + O_AH + (p0 + 8) * RT + j0) = pack2h(v2, v3);
            }
    }
    __syncthreads();

    // ---- phase 2: O = A @ V ----
    {
        float accO[4][2][4];
#pragma unroll
        for (int i = 0; i < 4; i++)
#pragma unroll
            for (int j = 0; j < 2; j++)
#pragma unroll
                for (int e = 0; e < 4; e++) accO[i][j][e] = 0.f;

#pragma unroll
        for (int ks = 0; ks < 8; ks++) {
            int kk = ks * 16;
            uint32_t vh[2][2];
#pragma unroll
            for (int jn = 0; jn < 2; jn++) {
                int nrow = wn * 16 + jn * 8 + b_r;
                uint32_t off = (uint32_t)(nrow * RT + kk + b_k) * 2;
                ldsm2(vh[jn][0], vh[jn][1], sbase + O_VT * 2 + off);
            }
#pragma unroll
            for (int im = 0; im < 4; im++) {
                int row = wm * 64 + im * 16 + a_r;
                uint32_t off = (uint32_t)(row * RT + kk + a_k) * 2;
                uint32_t ah[4];
                ldsm4(ah[0], ah[1], ah[2], ah[3], sbase + O_AH * 2 + off);
#pragma unroll
                for (int jn = 0; jn < 2; jn++)
                    mma_fp16(accO[im][jn], ah, vh[jn]);
            }
        }
#pragma unroll
        for (int im = 0; im < 4; im++)
#pragma unroll
            for (int jn = 0; jn < 2; jn++) {
                int p0 = wm * 64 + im * 16 + er;
                int col = wn * 16 + jn * 8 + ec;
                size_t gb = (size_t)(b * NSEQ + n0 + p0) * EE + h * DD + col;
                *(float2*)(g_attn + gb) = make_float2(accO[im][jn][0], accO[im][jn][1]);
                *(float2*)(g_attn + gb + (size_t)8 * EE) =
                    make_float2(accO[im][jn][2], accO[im][jn][3]);
            }
    }

    // ---- phase 3: T = Kw^T @ V ----
    {
        float accT[2][2][4];
#pragma unroll
        for (int i = 0; i < 2; i++)
#pragma unroll
            for (int j = 0; j < 2; j++)
#pragma unroll
                for (int e = 0; e < 4; e++) accT[i][j][e] = 0.f;

#pragma unroll
        for (int ks = 0; ks < 8; ks++) {
            int kk = ks * 16;
            uint32_t vh[2][2];
#pragma unroll
            for (int jn = 0; jn < 2; jn++) {
                int nrow = wn * 16 + jn * 8 + b_r;
                uint32_t off = (uint32_t)(nrow * RT + kk + b_k) * 2;
                ldsm2(vh[jn][0], vh[jn][1], sbase + O_VT * 2 + off);
            }
#pragma unroll
            for (int im = 0; im < 2; im++) {
                int row = wm * 32 + im * 16 + a_r;
                uint32_t off = (uint32_t)(row * RT + kk + a_k) * 2;
                uint32_t kwh[4];
                ldsm4(kwh[0], kwh[1], kwh[2], kwh[3], sbase + O_KWH * 2 + off);
#pragma unroll
                for (int jn = 0; jn < 2; jn++)
                    mma_fp16(accT[im][jn], kwh, vh[jn]);
            }
        }
        size_t tb = ((size_t)bh * NCH + chunk) * DD * DD;
#pragma unroll
        for (int im = 0; im < 2; im++)
#pragma unroll
            for (int jn = 0; jn < 2; jn++) {
                int dk = wm * 32 + im * 16 + er;
                int dv = wn * 16 + jn * 8 + ec;
                *(float2*)(g_T + tb + dk * DD + dv) =
                    make_float2(accT[im][jn][0], accT[im][jn][1]);
                *(float2*)(g_T + tb + (dk + 8) * DD + dv) =
                    make_float2(accT[im][jn][2], accT[im][jn][3]);
            }
    }
}

// ======================= pass B: chunk-state scan ========================
__global__ __launch_bounds__(256) void scan_k(const float* __restrict__ lam) {
    int bh = blockIdx.x;
    int h = bh % HH;
    float gamma = __expf(lam[h] * (float)CC);
    size_t base = (size_t)bh * NCH * DD * DD;
    for (int e = threadIdx.x; e < DD * DD; e += blockDim.x) {
        float s = 0.f;
#pragma unroll
        for (int t = 0; t < NCH; t++) {
            g_S[base + t * DD * DD + e] = s;
            s = gamma * s + g_T[base + t * DD * DD + e];
        }
    }
}

// ======================= pass C: inter-chunk + gate fuse + fp16 out ======
__global__ __launch_bounds__(256) void attn_inter_k(const float* __restrict__ lam,
                                                    const float* __restrict__ Wg2) {
    extern __shared__ __align__(16) float sm2[];
    float* Qs = sm2;
    float* Ss = Qs + 128 * 64;
    float* ep = Ss + 64 * 64;
    float* t16s = ep + 128;
    float* wg2s = t16s + 128 * 16;

    int tid = threadIdx.x;
    int chunk = blockIdx.x;
    int bh = blockIdx.y;
    int b = bh / HH, h = bh % HH;
    float lambda = lam[h];
    int n0 = chunk * CC;

    for (int i = tid; i < 128; i += 256) ep[i] = __expf(lambda * (float)i);

    for (int idx = tid; idx < 128 * 16; idx += 256) {
        int p = idx >> 4;
        int d4 = (idx & 15) * 4;
        size_t gb = (size_t)(b * NSEQ + n0 + p) * EE + h * DD + d4;
        uint2 hh = *(const uint2*)(g_q16 + gb);
        __half* hp = (__half*)&hh;
#pragma unroll
        for (int e = 0; e < 4; e++)
            Qs[p * 64 + d4 + e] = __half2float(hp[e]);
    }
    size_t sbo = ((size_t)bh * NCH + chunk) * DD * DD;
    for (int idx = tid; idx < 64 * 16; idx += 256)
        *(float4*)(&Ss[idx * 4]) = *(const float4*)(g_S + sbo + idx * 4);
    for (int i = tid; i < 512; i += 256)
        *(float4*)(t16s + i * 4) =
            *(const float4*)(g_t16 + (size_t)(b * NSEQ + n0) * GG + i * 4);
    for (int i = tid; i < 256; i += 256) {
        int g = i >> 4, c4 = (i & 15) * 4;
        *(float4*)(wg2s + g * 64 + c4) = *(const float4*)(Wg2 + g * EE + h * DD + c4);
    }
    __syncthreads();

    int ty = tid >> 4, tx = tid & 15;
    float o[8][4];
#pragma unroll
    for (int i = 0; i < 8; i++)
#pragma unroll
        for (int j = 0; j < 4; j++) o[i][j] = 0.f;
    for (int kd = 0; kd < 64; kd++) {
        float sv[4];
#pragma unroll
        for (int j = 0; j < 4; j++) sv[j] = Ss[kd * 64 + tx + 16 * j];
#pragma unroll
        for (int i = 0; i < 8; i++) {
            float q = Qs[(ty + 16 * i) * 64 + kd];
#pragma unroll
            for (int j = 0; j < 4; j++) o[i][j] += q * sv[j];
        }
    }
#pragma unroll
    for (int i = 0; i < 8; i++) {
        int p = ty + 16 * i;
        float e = ep[p];
        size_t gb = (size_t)(b * NSEQ + n0 + p) * EE + h * DD;
#pragma unroll
        for (int j = 0; j < 4; j++) {
            int c = tx + 16 * j;
            float s = 0.f;
#pragma unroll
            for (int g = 0; g < 16; g++) s += t16s[p * 16 + g] * wg2s[g * 64 + c];
            float gate = 1.f / (1.f + __expf(-s));
            size_t gi = gb + c;
            float val = (g_attn[gi] + e * o[i][j]) * gate;
            g_ah[gi] = __float2half(val);
        }
    }
}

// ======================= LayerNorm =======================================
__global__ __launch_bounds__(256) void ln_k(const float* __restrict__ w,
                                            const float* __restrict__ bias,
                                            float* __restrict__ out) {
    int row = blockIdx.x;
    int t = threadIdx.x;
    const float* yr = g_y + (size_t)row * EE;
    float v0 = yr[t], v1 = yr[t + 256], v2 = yr[t + 512];

    __shared__ float red[32];
    float s = v0 + v1 + v2;
#pragma unroll
    for (int off = 16; off > 0; off >>= 1) s += __shfl_down_sync(0xffffffffu, s, off);
    if ((t & 31) == 0) red[t >> 5] = s;
    __syncthreads();
    if (t < 32) {
        float x = (t < 8) ? red[t] : 0.f;
#pragma unroll
        for (int off = 4; off > 0; off >>= 1) x += __shfl_down_sync(0xffffffffu, x, off);
        if (t == 0) red[0] = x;
    }
    __syncthreads();
    float mu = red[0] * (1.f / 768.f);
    __syncthreads();

    float d0 = v0 - mu, d1 = v1 - mu, d2 = v2 - mu;
    float s2 = d0 * d0 + d1 * d1 + d2 * d2;
#pragma unroll
    for (int off = 16; off > 0; off >>= 1) s2 += __shfl_down_sync(0xffffffffu, s2, off);
    if ((t & 31) == 0) red[t >> 5] = s2;
    __syncthreads();
    if (t < 32) {
        float x = (t < 8) ? red[t] : 0.f;
#pragma unroll
        for (int off = 4; off > 0; off >>= 1) x += __shfl_down_sync(0xffffffffu, x, off);
        if (t == 0) red[0] = x;
    }
    __syncthreads();
    float var = red[0] * (1.f / 768.f);
    float rs = rsqrtf(var + 1e-5f);

    size_t ob = (size_t)row * EE;
    out[ob + t]       = d0 * rs * w[t]       + bias[t];
    out[ob + t + 256] = d1 * rs * w[t + 256] + bias[t + 256];
    out[ob + t + 512] = d2 * rs * w[t + 512] + bias[t + 512];
}

// =========================================================================
extern "C" void kernel_launch(void* const* d_in, const int* in_sizes, int n_in,
                              void* d_out, int out_size) {
    (void)in_sizes; (void)n_in; (void)out_size;
    const float* x         = (const float*)d_in[0];
    const float* log_slope = (const float*)d_in[1];
    const float* Wq        = (const float*)d_in[2];
    const float* Wk        = (const float*)d_in[3];
    const float* Wv        = (const float*)d_in[4];
    const float* Wo        = (const float*)d_in[5];
    const float* Wg1       = (const float*)d_in[6];
    const float* Wg2       = (const float*)d_in[7];
    const float* ln_w      = (const float*)d_in[8];
    const float* ln_b      = (const float*)d_in[9];
    float* out = (float*)d_out;

    int smMM = 3 * MMSTG;   // 72 KB -> 2 CTAs/SM
    cudaFuncSetAttribute(mm_tc<0>, cudaFuncAttributeMaxDynamicSharedMemorySize, smMM);
    cudaFuncSetAttribute(mm_tc<1>, cudaFuncAttributeMaxDynamicSharedMemorySize, smMM);
    int smA = O_END * 2 + 132 * 4;   // ~104.5 KB -> 2 CTAs/SM
    cudaFuncSetAttribute(attn_intra_k, cudaFuncAttributeMaxDynamicSharedMemorySize, smA);
    int smG1 = 34048 * 2;
    cudaFuncSetAttribute(mm_g1, cudaFuncAttributeMaxDynamicSharedMemorySize, smG1);
    int smC = (128 * 64 + 64 * 64 + 128 + 128 * 16 + 16 * 64) * (int)sizeof(float);
    cudaFuncSetAttribute(attn_inter_k, cudaFuncAttributeMaxDynamicSharedMemorySize, smC);

    conv_x_k<<<MTOT * EE / 1024, 256>>>(x);
    conv_w_k<<<dim3(EE / 32, EE / 32, 4), 256>>>(Wq, Wk, Wv, Wo);
    convg1_k<<<GG * EE / 256, 256>>>(Wg1);
    mm_tc<0><<<dim3(EE / 128, MTOT / 128, 3), 256, smMM>>>();
    mm_g1<<<MTOT / 128, 256, smG1>>>();
    attn_intra_k<<<dim3(NCH, BHH), 256, smA>>>(log_slope);
    scan_k<<<BHH, 256>>>(log_slope);
    attn_inter_k<<<dim3(NCH, BHH), 256, smC>>>(log_slope, Wg2);
    mm_tc<1><<<dim3(EE / 128, MTOT / 128, 1), 256, smMM>>>();
    ln_k<<<MTOT, 256>>>(ln_w, ln_b, out);
}

// round 10
// speedup vs baseline: 3.4915x; 1.2357x over previous
#include <cuda_runtime.h>
#include <cuda_bf16.h>
#include <cuda_fp16.h>
#include <cstdint>

// Problem constants
#define BB    2
#define NSEQ  2048
#define EE    768
#define HH    12
#define DD    64
#define GG    16
#define CC    128
#define NCH   (NSEQ / CC)         // 16
#define BHH   (BB * HH)           // 24
#define MTOT  (BB * NSEQ)         // 4096

// ---------------- device scratch ----------------
__device__ float g_attn[MTOT * EE];
__device__ float g_y[MTOT * EE];
__device__ float g_t16[MTOT * GG];
__device__ float g_T[BHH * NCH * DD * DD];
__device__ float g_S[BHH * NCH * DD * DD];

// fp16 operands (all single precision)
__device__ __half g_xh[MTOT * EE];
__device__ __half g_ah[MTOT * EE];
__device__ __half g_wth[4 * EE * EE];   // transposed [n][k]
__device__ __half g_g1th[GG * EE];      // Wg1 transposed [g][k]

// attention operands: q,k,v all single fp16
__device__ __half g_q16[MTOT * EE];
__device__ __half g_k16[MTOT * EE];
__device__ __half g_v16[MTOT * EE];

// ======================= helpers ==========================
__device__ __forceinline__ uint32_t smem_u32(const void* p) {
    uint32_t a;
    asm("{ .reg .u64 t; cvta.to.shared.u64 t, %1; cvt.u32.u64 %0, t; }"
        : "=r"(a) : "l"(p));
    return a;
}
__device__ __forceinline__ void cp_async16(uint32_t s, const void* g) {
    asm volatile("cp.async.cg.shared.global [%0], [%1], 16;" :: "r"(s), "l"(g));
}
__device__ __forceinline__ void cp_commit() {
    asm volatile("cp.async.commit_group;");
}
template <int N>
__device__ __forceinline__ void cp_wait() {
    asm volatile("cp.async.wait_group %0;" :: "n"(N));
}
__device__ __forceinline__ void ldsm4(uint32_t& r0, uint32_t& r1, uint32_t& r2,
                                      uint32_t& r3, uint32_t a) {
    asm volatile("ldmatrix.sync.aligned.m8n8.x4.shared.b16 {%0,%1,%2,%3}, [%4];"
                 : "=r"(r0), "=r"(r1), "=r"(r2), "=r"(r3) : "r"(a));
}
__device__ __forceinline__ void ldsm2(uint32_t& r0, uint32_t& r1, uint32_t a) {
    asm volatile("ldmatrix.sync.aligned.m8n8.x2.shared.b16 {%0,%1}, [%2];"
                 : "=r"(r0), "=r"(r1) : "r"(a));
}
__device__ __forceinline__ void mma_fp16(float* c, const uint32_t* a,
                                         const uint32_t* b) {
    asm volatile(
        "mma.sync.aligned.m16n8k16.row.col.f32.f16.f16.f32 "
        "{%0,%1,%2,%3}, {%4,%5,%6,%7}, {%8,%9}, {%0,%1,%2,%3};"
        : "+f"(c[0]), "+f"(c[1]), "+f"(c[2]), "+f"(c[3])
        : "r"(a[0]), "r"(a[1]), "r"(a[2]), "r"(a[3]), "r"(b[0]), "r"(b[1]));
}
__device__ __forceinline__ uint32_t pack2h(float a, float b) {
    __half ha = __float2half(a), hb = __float2half(b);
    return (uint32_t)*(uint16_t*)&ha | ((uint32_t)*(uint16_t*)&hb << 16);
}
// 64B-row swizzle
__device__ __forceinline__ uint32_t swz64(int r, int cbyte) {
    return (uint32_t)(r * 64 + (cbyte ^ (((r >> 1) & 3) << 4)));
}

// ======================= conversion kernels ==============================
__global__ __launch_bounds__(256) void conv_x_k(const float* __restrict__ x) {
    size_t i = ((size_t)blockIdx.x * 256 + threadIdx.x) * 4;
    float4 v = *(const float4*)(x + i);
    __align__(8) __half h[4];
    h[0] = __float2half(v.x);
    h[1] = __float2half(v.y);
    h[2] = __float2half(v.z);
    h[3] = __float2half(v.w);
    *(uint2*)(g_xh + i) = *(uint2*)h;
}

__global__ __launch_bounds__(256) void conv_w_k(const float* __restrict__ Wq,
                                                const float* __restrict__ Wk,
                                                const float* __restrict__ Wv,
                                                const float* __restrict__ Wo) {
    const float* W = (blockIdx.z == 0) ? Wq : (blockIdx.z == 1) ? Wk
                   : (blockIdx.z == 2) ? Wv : Wo;
    __shared__ float t[32][33];
    int tx = threadIdx.x & 31, ty0 = threadIdx.x >> 5;
    int bn = blockIdx.x * 32, bk = blockIdx.y * 32;
#pragma unroll
    for (int r = 0; r < 4; r++) {
        int ty = ty0 + r * 8;
        t[ty][tx] = W[(size_t)(bk + ty) * EE + bn + tx];
    }
    __syncthreads();
    size_t base = (size_t)blockIdx.z * EE * EE;
#pragma unroll
    for (int r = 0; r < 4; r++) {
        int ty = ty0 + r * 8;
        g_wth[base + (size_t)(bn + ty) * EE + bk + tx] = __float2half(t[tx][ty]);
    }
}

__global__ __launch_bounds__(256) void convg1_k(const float* __restrict__ Wg1) {
    int i = blockIdx.x * 256 + threadIdx.x;
    int n = i / EE, k = i % EE;
    g_g1th[i] = __float2half(Wg1[k * GG + n]);
}

// ======================= single-fp16 mma.sync GEMM =======================
// C = act(A @ W), all operands single fp16, fp32 accum.
// 3-stage cp.async pipeline, 1 barrier per K-tile, swizzled 64B rows.
// Per-stage layout (bytes): A 0 (8K), B 8192 (8K); stage 16384.
#define MMSTG 16384
#define MM_AH 0
#define MM_BH 8192

template <int MODE>
__global__ __launch_bounds__(256, 2) void mm_tc() {
    extern __shared__ char smem[];
    uint32_t sb = smem_u32(smem);

    int tid = threadIdx.x;
    int wid = tid >> 5, lane = tid & 31;
    int wm = wid & 1, wn = wid >> 1;

    int z = blockIdx.z;
    const __half *Ah, *Wh;
    float* Cm = nullptr;
    __half* C1 = nullptr;
    if (MODE == 0) {
        Ah = g_xh;
        Wh = g_wth + (size_t)z * EE * EE;
        C1 = (z == 0) ? g_q16 : (z == 1) ? g_k16 : g_v16;
    } else {
        Ah = g_ah;
        Wh = g_wth + (size_t)3 * EE * EE;
        Cm = g_y;
    }
    int bm = blockIdx.y * 128, bn = blockIdx.x * 128;

    float acc[4][4][4];
#pragma unroll
    for (int i = 0; i < 4; i++)
#pragma unroll
        for (int j = 0; j < 4; j++)
#pragma unroll
            for (int e = 0; e < 4; e++) acc[i][j][e] = 0.f;

    int lr0 = tid >> 2;
    int lcb = (tid & 3) * 16;
    int lce = (tid & 3) * 8;

    auto issue = [&](int kt, int stg) {
        int k0 = kt * 32;
        uint32_t st = sb + (uint32_t)stg * MMSTG;
#pragma unroll
        for (int rr = 0; rr < 2; rr++) {
            int r = lr0 + rr * 64;
            uint32_t so = swz64(r, lcb);
            cp_async16(st + MM_AH + so, Ah + (size_t)(bm + r) * EE + k0 + lce);
            cp_async16(st + MM_BH + so, Wh + (size_t)(bn + r) * EE + k0 + lce);
        }
        cp_commit();
    };

    int a_r = lane & 15;
    int a_kb = ((lane >> 4) & 1) << 4;
    int bg = lane >> 3;
    int b_r = lane & 7;
    int b_jn = bg >> 1;
    int b_kb = (bg & 1) << 4;

    issue(0, 0);
    issue(1, 1);
    int stg = 0;
    for (int kt = 0; kt < 24; kt++) {
        if (kt < 23) cp_wait<1>(); else cp_wait<0>();
        __syncthreads();
        if (kt < 22) {
            int ns = stg + 2;
            if (ns >= 3) ns -= 3;
            issue(kt + 2, ns);
        }
        uint32_t st = sb + (uint32_t)stg * MMSTG;
#pragma unroll
        for (int ks = 0; ks < 2; ks++) {
            int kb = ks * 32;
            uint32_t bh[4][2];
#pragma unroll
            for (int jp = 0; jp < 2; jp++) {
                int nrow = wn * 32 + (jp * 2 + b_jn) * 8 + b_r;
                uint32_t off = swz64(nrow, kb + b_kb);
                ldsm4(bh[jp * 2][0], bh[jp * 2][1], bh[jp * 2 + 1][0],
                      bh[jp * 2 + 1][1], st + MM_BH + off);
            }
#pragma unroll
            for (int im = 0; im < 4; im++) {
                int row = wm * 64 + im * 16 + a_r;
                uint32_t off = swz64(row, kb + a_kb);
                uint32_t ah[4];
                ldsm4(ah[0], ah[1], ah[2], ah[3], st + MM_AH + off);
#pragma unroll
                for (int jn = 0; jn < 4; jn++)
                    mma_fp16(acc[im][jn], ah, bh[jn]);
            }
        }
        stg++;
        if (stg == 3) stg = 0;
    }

    int er = lane >> 2, ec = (lane & 3) * 2;
#pragma unroll
    for (int im = 0; im < 4; im++) {
#pragma unroll
        for (int jn = 0; jn < 4; jn++) {
            int row = bm + wm * 64 + im * 16 + er;
            int col = bn + wn * 32 + jn * 8 + ec;
            float v0 = acc[im][jn][0], v1 = acc[im][jn][1];
            float v2 = acc[im][jn][2], v3 = acc[im][jn][3];
            if (MODE == 0) {
                v0 = v0 / (1.f + __expf(-v0));
                v1 = v1 / (1.f + __expf(-v1));
                v2 = v2 / (1.f + __expf(-v2));
                v3 = v3 / (1.f + __expf(-v3));
                *(uint32_t*)(C1 + (size_t)row * EE + col) = pack2h(v0, v1);
                *(uint32_t*)(C1 + (size_t)(row + 8) * EE + col) = pack2h(v2, v3);
            } else {
                *(float2*)(Cm + (size_t)row * EE + col) = make_float2(v0, v1);
                *(float2*)(Cm + (size_t)(row + 8) * EE + col) = make_float2(v2, v3);
            }
        }
    }
}

// ======================= mm_g1: t16 = x @ Wg1 (single fp16) ==============
#define G1RB 776
// smem (half elems): Bh 0 (12416), Ah 12416 (9216); end 21632
__global__ __launch_bounds__(256) void mm_g1() {
    extern __shared__ __half sg[];
    __half* Bh = sg;
    __half* Ahs = sg + 12416;
    uint32_t sbase = smem_u32(sg);

    int tid = threadIdx.x, wid = tid >> 5, lane = tid & 31;
    int bm = blockIdx.x * 128;

    for (int i = tid; i < 16 * 96; i += 256) {
        int r = i / 96, c8 = (i % 96) * 8;
        *(uint4*)(Bh + r * G1RB + c8) = *(const uint4*)(g_g1th + r * EE + c8);
    }

    float acc[2][4];
#pragma unroll
    for (int j = 0; j < 2; j++)
#pragma unroll
        for (int e = 0; e < 4; e++) acc[j][e] = 0.f;

    int a_r = lane & 15, a_k = (lane >> 4) << 3;
    int b_r = lane & 7, b_k = ((lane >> 3) & 1) << 3;

    for (int kt = 0; kt < 12; kt++) {
        __syncthreads();
        for (int i = tid; i < 1024; i += 256) {
            int p = i >> 3, c = i & 7;
            size_t go = (size_t)(bm + p) * EE + kt * 64 + c * 8;
            *(uint4*)(Ahs + p * 72 + c * 8) = *(const uint4*)(g_xh + go);
        }
        __syncthreads();
#pragma unroll
        for (int ks = 0; ks < 4; ks++) {
            int kk = ks * 16;
            uint32_t ah[4];
            int row = wid * 16 + a_r;
            uint32_t offa = (uint32_t)(12416 + row * 72 + kk + a_k) * 2;
            ldsm4(ah[0], ah[1], ah[2], ah[3], sbase + offa);
#pragma unroll
            for (int jn = 0; jn < 2; jn++) {
                int nrow = jn * 8 + b_r;
                uint32_t offb = (uint32_t)(nrow * G1RB + kt * 64 + kk + b_k) * 2;
                uint32_t bh[2];
                ldsm2(bh[0], bh[1], sbase + offb);
                mma_fp16(acc[jn], ah, bh);
            }
        }
    }
    int er = lane >> 2, ec = (lane & 3) * 2;
#pragma unroll
    for (int jn = 0; jn < 2; jn++) {
        int row = bm + wid * 16 + er;
        int col = jn * 8 + ec;
        *(float2*)(g_t16 + (size_t)row * GG + col) = make_float2(acc[jn][0], acc[jn][1]);
        *(float2*)(g_t16 + (size_t)(row + 8) * GG + col) = make_float2(acc[jn][2], acc[jn][3]);
    }
}

// ======================= attention pass A (all-single fp16 mma) ==========
#define O_QH 0
#define O_KH 9216
#define O_VT 18432
#define O_KWH 27136
#define O_AH 35840
#define O_END 53248
#define RQ 72
#define RT 136

__global__ __launch_bounds__(256, 2) void attn_intra_k(const float* __restrict__ lam) {
    extern __shared__ __align__(16) __half sh16[];
    float* dtab = (float*)(sh16 + O_END);
    uint32_t sbase = smem_u32(sh16);

    int tid = threadIdx.x, wid = tid >> 5, lane = tid & 31;
    int wm = wid & 1, wn = wid >> 1;
    int chunk = blockIdx.x, bh = blockIdx.y;
    int b = bh / HH, h = bh % HH;
    float lambda = lam[h];
    int n0 = chunk * CC;

    for (int i = tid; i <= CC; i += 256) dtab[i] = __expf(lambda * (float)i);

    for (int i = tid; i < 2048; i += 256) {
        int p = i >> 4, d4 = (i & 15) * 4;
        size_t gb = (size_t)(b * NSEQ + n0 + p) * EE + h * DD + d4;
        *(uint2*)(sh16 + O_QH + p * RQ + d4) = *(const uint2*)(g_q16 + gb);
        *(uint2*)(sh16 + O_KH + p * RQ + d4) = *(const uint2*)(g_k16 + gb);
    }
    for (int i = tid; i < 8192; i += 256) {
        int d = i & 63, p = i >> 6;
        size_t gb = (size_t)(b * NSEQ + n0 + p) * EE + h * DD + d;
        sh16[O_VT + d * RT + p] = g_v16[gb];
        float kv = __half2float(g_k16[gb]);
        float w = __expf(lambda * (float)(CC - p));
        sh16[O_KWH + d * RT + p] = __float2half(kv * w);
    }
    __syncthreads();

    int a_r = lane & 15, a_k = (lane >> 4) << 3;
    int b_r = lane & 7, b_k = ((lane >> 3) & 1) << 3;
    int er = lane >> 2, ec = (lane & 3) * 2;

    // ---- phase 1: S = Q @ K^T ----
    {
        float accS[4][4][4];
#pragma unroll
        for (int i = 0; i < 4; i++)
#pragma unroll
            for (int j = 0; j < 4; j++)
#pragma unroll
                for (int e = 0; e < 4; e++) accS[i][j][e] = 0.f;

#pragma unroll
        for (int ks = 0; ks < 4; ks++) {
            int kk = ks * 16;
            uint32_t kh[4][2];
#pragma unroll
            for (int jn = 0; jn < 4; jn++) {
                int nrow = wn * 32 + jn * 8 + b_r;
                uint32_t off = (uint32_t)(nrow * RQ + kk + b_k) * 2;
                ldsm2(kh[jn][0], kh[jn][1], sbase + O_KH * 2 + off);
            }
#pragma unroll
            for (int im = 0; im < 4; im++) {
                int row = wm * 64 + im * 16 + a_r;
                uint32_t off = (uint32_t)(row * RQ + kk + a_k) * 2;
                uint32_t qh[4];
                ldsm4(qh[0], qh[1], qh[2], qh[3], sbase + O_QH * 2 + off);
#pragma unroll
                for (int jn = 0; jn < 4; jn++)
                    mma_fp16(accS[im][jn], qh, kh[jn]);
            }
        }
#pragma unroll
        for (int im = 0; im < 4; im++)
#pragma unroll
            for (int jn = 0; jn < 4; jn++) {
                int p0 = wm * 64 + im * 16 + er;
                int j0 = wn * 32 + jn * 8 + ec;
                int dj = p0 - j0;
                float v0 = (dj >= 0)     ? accS[im][jn][0] * dtab[dj] : 0.f;
                float v1 = (dj - 1 >= 0) ? accS[im][jn][1] * dtab[dj - 1] : 0.f;
                float v2 = (dj + 8 >= 0) ? accS[im][jn][2] * dtab[dj + 8] : 0.f;
                float v3 = (dj + 7 >= 0) ? accS[im][jn][3] * dtab[dj + 7] : 0.f;
                *(uint32_t*)(sh16 + O_AH + p0 * RT + j0) = pack2h(v0, v1);
                *(uint32_t*)(sh16 + O_AH + (p0 + 8) * RT + j0) = pack2h(v2, v3);
            }
    }
    __syncthreads();

    // ---- phase 2: O = A @ V ----
    {
        float accO[4][2][4];
#pragma unroll
        for (int i = 0; i < 4; i++)
#pragma unroll
            for (int j = 0; j < 2; j++)
#pragma unroll
                for (int e = 0; e < 4; e++) accO[i][j][e] = 0.f;

#pragma unroll
        for (int ks = 0; ks < 8; ks++) {
            int kk = ks * 16;
            uint32_t vh[2][2];
#pragma unroll
            for (int jn = 0; jn < 2; jn++) {
                int nrow = wn * 16 + jn * 8 + b_r;
                uint32_t off = (uint32_t)(nrow * RT + kk + b_k) * 2;
                ldsm2(vh[jn][0], vh[jn][1], sbase + O_VT * 2 + off);
            }
#pragma unroll
            for (int im = 0; im < 4; im++) {
                int row = wm * 64 + im * 16 + a_r;
                uint32_t off = (uint32_t)(row * RT + kk + a_k) * 2;
                uint32_t ah[4];
                ldsm4(ah[0], ah[1], ah[2], ah[3], sbase + O_AH * 2 + off);
#pragma unroll
                for (int jn = 0; jn < 2; jn++)
                    mma_fp16(accO[im][jn], ah, vh[jn]);
            }
        }
#pragma unroll
        for (int im = 0; im < 4; im++)
#pragma unroll
            for (int jn = 0; jn < 2; jn++) {
                int p0 = wm * 64 + im * 16 + er;
                int col = wn * 16 + jn * 8 + ec;
                size_t gb = (size_t)(b * NSEQ + n0 + p0) * EE + h * DD + col;
                *(float2*)(g_attn + gb) = make_float2(accO[im][jn][0], accO[im][jn][1]);
                *(float2*)(g_attn + gb + (size_t)8 * EE) =
                    make_float2(accO[im][jn][2], accO[im][jn][3]);
            }
    }

    // ---- phase 3: T = Kw^T @ V ----
    {
        float accT[2][2][4];
#pragma unroll
        for (int i = 0; i < 2; i++)
#pragma unroll
            for (int j = 0; j < 2; j++)
#pragma unroll
                for (int e = 0; e < 4; e++) accT[i][j][e] = 0.f;

#pragma unroll
        for (int ks = 0; ks < 8; ks++) {
            int kk = ks * 16;
            uint32_t vh[2][2];
#pragma unroll
            for (int jn = 0; jn < 2; jn++) {
                int nrow = wn * 16 + jn * 8 + b_r;
                uint32_t off = (uint32_t)(nrow * RT + kk + b_k) * 2;
                ldsm2(vh[jn][0], vh[jn][1], sbase + O_VT * 2 + off);
            }
#pragma unroll
            for (int im = 0; im < 2; im++) {
                int row = wm * 32 + im * 16 + a_r;
                uint32_t off = (uint32_t)(row * RT + kk + a_k) * 2;
                uint32_t kwh[4];
                ldsm4(kwh[0], kwh[1], kwh[2], kwh[3], sbase + O_KWH * 2 + off);
#pragma unroll
                for (int jn = 0; jn < 2; jn++)
                    mma_fp16(accT[im][jn], kwh, vh[jn]);
            }
        }
        size_t tb = ((size_t)bh * NCH + chunk) * DD * DD;
#pragma unroll
        for (int im = 0; im < 2; im++)
#pragma unroll
            for (int jn = 0; jn < 2; jn++) {
                int dk = wm * 32 + im * 16 + er;
                int dv = wn * 16 + jn * 8 + ec;
                *(float2*)(g_T + tb + dk * DD + dv) =
                    make_float2(accT[im][jn][0], accT[im][jn][1]);
                *(float2*)(g_T + tb + (dk + 8) * DD + dv) =
                    make_float2(accT[im][jn][2], accT[im][jn][3]);
            }
    }
}

// ======================= pass B: chunk-state scan ========================
__global__ __launch_bounds__(256) void scan_k(const float* __restrict__ lam) {
    int bh = blockIdx.x;
    int h = bh % HH;
    float gamma = __expf(lam[h] * (float)CC);
    size_t base = (size_t)bh * NCH * DD * DD;
    for (int e = threadIdx.x; e < DD * DD; e += blockDim.x) {
        float s = 0.f;
#pragma unroll
        for (int t = 0; t < NCH; t++) {
            g_S[base + t * DD * DD + e] = s;
            s = gamma * s + g_T[base + t * DD * DD + e];
        }
    }
}

// ======================= pass C: inter-chunk + gate fuse + fp16 out ======
__global__ __launch_bounds__(256) void attn_inter_k(const float* __restrict__ lam,
                                                    const float* __restrict__ Wg2) {
    extern __shared__ __align__(16) float sm2[];
    float* Qs = sm2;
    float* Ss = Qs + 128 * 64;
    float* ep = Ss + 64 * 64;
    float* t16s = ep + 128;
    float* wg2s = t16s + 128 * 16;

    int tid = threadIdx.x;
    int chunk = blockIdx.x;
    int bh = blockIdx.y;
    int b = bh / HH, h = bh % HH;
    float lambda = lam[h];
    int n0 = chunk * CC;

    for (int i = tid; i < 128; i += 256) ep[i] = __expf(lambda * (float)i);

    for (int idx = tid; idx < 128 * 16; idx += 256) {
        int p = idx >> 4;
        int d4 = (idx & 15) * 4;
        size_t gb = (size_t)(b * NSEQ + n0 + p) * EE + h * DD + d4;
        uint2 hh = *(const uint2*)(g_q16 + gb);
        __half* hp = (__half*)&hh;
#pragma unroll
        for (int e = 0; e < 4; e++)
            Qs[p * 64 + d4 + e] = __half2float(hp[e]);
    }
    size_t sbo = ((size_t)bh * NCH + chunk) * DD * DD;
    for (int idx = tid; idx < 64 * 16; idx += 256)
        *(float4*)(&Ss[idx * 4]) = *(const float4*)(g_S + sbo + idx * 4);
    for (int i = tid; i < 512; i += 256)
        *(float4*)(t16s + i * 4) =
            *(const float4*)(g_t16 + (size_t)(b * NSEQ + n0) * GG + i * 4);
    for (int i = tid; i < 256; i += 256) {
        int g = i >> 4, c4 = (i & 15) * 4;
        *(float4*)(wg2s + g * 64 + c4) = *(const float4*)(Wg2 + g * EE + h * DD + c4);
    }
    __syncthreads();

    int ty = tid >> 4, tx = tid & 15;
    float o[8][4];
#pragma unroll
    for (int i = 0; i < 8; i++)
#pragma unroll
        for (int j = 0; j < 4; j++) o[i][j] = 0.f;
    for (int kd = 0; kd < 64; kd++) {
        float sv[4];
#pragma unroll
        for (int j = 0; j < 4; j++) sv[j] = Ss[kd * 64 + tx + 16 * j];
#pragma unroll
        for (int i = 0; i < 8; i++) {
            float q = Qs[(ty + 16 * i) * 64 + kd];
#pragma unroll
            for (int j = 0; j < 4; j++) o[i][j] += q * sv[j];
        }
    }
#pragma unroll
    for (int i = 0; i < 8; i++) {
        int p = ty + 16 * i;
        float e = ep[p];
        size_t gb = (size_t)(b * NSEQ + n0 + p) * EE + h * DD;
#pragma unroll
        for (int j = 0; j < 4; j++) {
            int c = tx + 16 * j;
            float s = 0.f;
#pragma unroll
            for (int g = 0; g < 16; g++) s += t16s[p * 16 + g] * wg2s[g * 64 + c];
            float gate = 1.f / (1.f + __expf(-s));
            size_t gi = gb + c;
            float val = (g_attn[gi] + e * o[i][j]) * gate;
            g_ah[gi] = __float2half(val);
        }
    }
}

// ======================= LayerNorm =======================================
__global__ __launch_bounds__(256) void ln_k(const float* __restrict__ w,
                                            const float* __restrict__ bias,
                                            float* __restrict__ out) {
    int row = blockIdx.x;
    int t = threadIdx.x;
    const float* yr = g_y + (size_t)row * EE;
    float v0 = yr[t], v1 = yr[t + 256], v2 = yr[t + 512];

    __shared__ float red[32];
    float s = v0 + v1 + v2;
#pragma unroll
    for (int off = 16; off > 0; off >>= 1) s += __shfl_down_sync(0xffffffffu, s, off);
    if ((t & 31) == 0) red[t >> 5] = s;
    __syncthreads();
    if (t < 32) {
        float x = (t < 8) ? red[t] : 0.f;
#pragma unroll
        for (int off = 4; off > 0; off >>= 1) x += __shfl_down_sync(0xffffffffu, x, off);
        if (t == 0) red[0] = x;
    }
    __syncthreads();
    float mu = red[0] * (1.f / 768.f);
    __syncthreads();

    float d0 = v0 - mu, d1 = v1 - mu, d2 = v2 - mu;
    float s2 = d0 * d0 + d1 * d1 + d2 * d2;
#pragma unroll
    for (int off = 16; off > 0; off >>= 1) s2 += __shfl_down_sync(0xffffffffu, s2, off);
    if ((t & 31) == 0) red[t >> 5] = s2;
    __syncthreads();
    if (t < 32) {
        float x = (t < 8) ? red[t] : 0.f;
#pragma unroll
        for (int off = 4; off > 0; off >>= 1) x += __shfl_down_sync(0xffffffffu, x, off);
        if (t == 0) red[0] = x;
    }
    __syncthreads();
    float var = red[0] * (1.f / 768.f);
    float rs = rsqrtf(var + 1e-5f);

    size_t ob = (size_t)row * EE;
    out[ob + t]       = d0 * rs * w[t]       + bias[t];
    out[ob + t + 256] = d1 * rs * w[t + 256] + bias[t + 256];
    out[ob + t + 512] = d2 * rs * w[t + 512] + bias[t + 512];
}

// =========================================================================
extern "C" void kernel_launch(void* const* d_in, const int* in_sizes, int n_in,
                              void* d_out, int out_size) {
    (void)in_sizes; (void)n_in; (void)out_size;
    const float* x         = (const float*)d_in[0];
    const float* log_slope = (const float*)d_in[1];
    const float* Wq        = (const float*)d_in[2];
    const float* Wk        = (const float*)d_in[3];
    const float* Wv        = (const float*)d_in[4];
    const float* Wo        = (const float*)d_in[5];
    const float* Wg1       = (const float*)d_in[6];
    const float* Wg2       = (const float*)d_in[7];
    const float* ln_w      = (const float*)d_in[8];
    const float* ln_b      = (const float*)d_in[9];
    float* out = (float*)d_out;

    int smMM = 3 * MMSTG;   // 48 KB -> 2 CTAs/SM (reg-capped)
    cudaFuncSetAttribute(mm_tc<0>, cudaFuncAttributeMaxDynamicSharedMemorySize, smMM);
    cudaFuncSetAttribute(mm_tc<1>, cudaFuncAttributeMaxDynamicSharedMemorySize, smMM);
    int smA = O_END * 2 + 132 * 4;   // ~104.5 KB -> 2 CTAs/SM
    cudaFuncSetAttribute(attn_intra_k, cudaFuncAttributeMaxDynamicSharedMemorySize, smA);
    int smG1 = 21632 * 2;            // ~42 KB
    cudaFuncSetAttribute(mm_g1, cudaFuncAttributeMaxDynamicSharedMemorySize, smG1);
    int smC = (128 * 64 + 64 * 64 + 128 + 128 * 16 + 16 * 64) * (int)sizeof(float);
    cudaFuncSetAttribute(attn_inter_k, cudaFuncAttributeMaxDynamicSharedMemorySize, smC);

    conv_x_k<<<MTOT * EE / 1024, 256>>>(x);
    conv_w_k<<<dim3(EE / 32, EE / 32, 4), 256>>>(Wq, Wk, Wv, Wo);
    convg1_k<<<GG * EE / 256, 256>>>(Wg1);
    mm_tc<0><<<dim3(EE / 128, MTOT / 128, 3), 256, smMM>>>();
    mm_g1<<<MTOT / 128, 256, smG1>>>();
    attn_intra_k<<<dim3(NCH, BHH), 256, smA>>>(log_slope);
    scan_k<<<BHH, 256>>>(log_slope);
    attn_inter_k<<<dim3(NCH, BHH), 256, smC>>>(log_slope, Wg2);
    mm_tc<1><<<dim3(EE / 128, MTOT / 128, 1), 256, smMM>>>();
    ln_k<<<MTOT, 256>>>(ln_w, ln_b, out);
}